// round 1
// baseline (speedup 1.0000x reference)
#include <cuda_runtime.h>

// ---------------- problem constants ----------------
constexpr int Bb   = 4;
constexpr int NTOK = 4096;
constexpr int Cc   = 768;
constexpr int NQ   = 64;
constexpr int HH   = 64, WW = 64;
constexpr int WSZ  = 14;
constexpr int NH   = 12, DH = 64;
constexpr int NWX  = 5;                 // windows per row (70/14)
constexpr int R_   = 25;                // windows per image
constexpr int BW   = Bb * R_;           // 100
constexpr int NWIN = WSZ * WSZ;         // 196
constexpr int LL   = NWIN + NQ;         // 260
constexpr int TOKROWS = BW * LL;        // 26000
constexpr int CTXROWS = Bb * NTOK + Bb * NQ; // 16640

// ---------------- scratch (device globals, no allocation) ----------------
__device__ float g_tok[(size_t)TOKROWS * Cc];
__device__ float g_Q[(size_t)BW * NH * LL * DH];
__device__ float g_K[(size_t)BW * NH * LL * DH];
__device__ float g_V[(size_t)BW * NH * LL * DH];
__device__ float g_S[(size_t)BW * NH * LL * LL];
__device__ float g_O[(size_t)TOKROWS * Cc];
__device__ float g_ctx[(size_t)CTXROWS * Cc];

// ---------------- 1) gather tokens (window partition + query replication) ----
__global__ __launch_bounds__(256) void k_gather_tok(const float* __restrict__ x,
                                                    const float* __restrict__ q) {
    int idx = blockIdx.x * blockDim.x + threadIdx.x;
    if (idx >= TOKROWS * (Cc / 4)) return;
    int t  = idx / (Cc / 4);
    int c4 = idx % (Cc / 4);
    int i = t / LL, l = t % LL;
    float4 val = make_float4(0.f, 0.f, 0.f, 0.f);
    if (l < NWIN) {
        int b = i / R_, w = i % R_;
        int wy = w / NWX, wx = w % NWX;
        int py = wy * WSZ + l / WSZ;
        int px = wx * WSZ + l % WSZ;
        if (py < HH && px < WW)
            val = ((const float4*)(x + ((size_t)b * NTOK + py * WW + px) * Cc))[c4];
    } else {
        int bq = i % Bb;
        int lq = l - NWIN;
        val = ((const float4*)(q + ((size_t)bq * NQ + lq) * Cc))[c4];
    }
    ((float4*)(g_tok + (size_t)t * Cc))[c4] = val;
}

// ---------------- 2) big SGEMM (NT): C = A @ Bmat^T  ------------------------
// mode 0: A = g_tok, scatter to g_Q/g_K/g_V (head-split)
// mode 1: A = g_ctx, out = d_out with bias
__global__ __launch_bounds__(256) void k_gemm_big(const float* __restrict__ Bmat,
                                                  const float* __restrict__ bias,
                                                  float* __restrict__ out,
                                                  int M, int Nn, int K, int mode) {
    __shared__ float As[8][132];
    __shared__ float Bs[8][132];
    const float* A = (mode == 0) ? g_tok : g_ctx;
    int tid = threadIdx.x;
    int bx = blockIdx.x, by = blockIdx.y;
    int trow = tid / 16, tcol = tid % 16;
    float acc[8][8];
#pragma unroll
    for (int i = 0; i < 8; i++)
#pragma unroll
        for (int j = 0; j < 8; j++) acc[i][j] = 0.f;

    int lrow = tid >> 1;
    int lk   = (tid & 1) * 4;
    int gm = by * 128 + lrow;
    int gn = bx * 128 + lrow;

    for (int k0 = 0; k0 < K; k0 += 8) {
        float4 av = make_float4(0, 0, 0, 0), bv = make_float4(0, 0, 0, 0);
        if (gm < M)  av = *(const float4*)(A    + (size_t)gm * K + k0 + lk);
        if (gn < Nn) bv = *(const float4*)(Bmat + (size_t)gn * K + k0 + lk);
        As[lk + 0][lrow] = av.x; As[lk + 1][lrow] = av.y;
        As[lk + 2][lrow] = av.z; As[lk + 3][lrow] = av.w;
        Bs[lk + 0][lrow] = bv.x; Bs[lk + 1][lrow] = bv.y;
        Bs[lk + 2][lrow] = bv.z; Bs[lk + 3][lrow] = bv.w;
        __syncthreads();
#pragma unroll
        for (int kk = 0; kk < 8; kk++) {
            float ar[8], br[8];
#pragma unroll
            for (int i = 0; i < 8; i++) ar[i] = As[kk][trow * 8 + i];
#pragma unroll
            for (int j = 0; j < 8; j++) br[j] = Bs[kk][tcol * 8 + j];
#pragma unroll
            for (int i = 0; i < 8; i++)
#pragma unroll
                for (int j = 0; j < 8; j++)
                    acc[i][j] = fmaf(ar[i], br[j], acc[i][j]);
        }
        __syncthreads();
    }

    if (mode == 0) {
#pragma unroll
        for (int i = 0; i < 8; i++) {
            int m = by * 128 + trow * 8 + i;
            if (m >= M) continue;
            int ti = m / LL, l = m % LL;
#pragma unroll
            for (int j = 0; j < 8; j++) {
                int n = bx * 128 + tcol * 8 + j;
                if (n >= Nn) continue;
                int which = n / Cc;
                int hd = (n % Cc) / DH;
                int dd = n % DH;
                float* dst = (which == 0) ? g_Q : (which == 1) ? g_K : g_V;
                dst[(((size_t)ti * NH + hd) * LL + l) * DH + dd] = acc[i][j];
            }
        }
    } else {
#pragma unroll
        for (int i = 0; i < 8; i++) {
            int m = by * 128 + trow * 8 + i;
            if (m >= M) continue;
#pragma unroll
            for (int j = 0; j < 8; j++) {
                int n = bx * 128 + tcol * 8 + j;
                if (n >= Nn) continue;
                out[(size_t)m * Nn + n] = acc[i][j] + bias[n];
            }
        }
    }
}

// ---------------- 3) S = scale * Q @ K^T + mask (batched, 64x64 tiles) ------
__global__ __launch_bounds__(256) void k_attn_S(const int* __restrict__ q_mask) {
    __shared__ float As[16][68];
    __shared__ float Bs[16][68];
    int z = blockIdx.z;             // i*NH + head
    int iB = z / NH;
    const float* Aq = g_Q + (size_t)z * LL * DH;
    const float* Bk = g_K + (size_t)z * LL * DH;
    int tid = threadIdx.x;
    int trow = tid / 16, tcol = tid % 16;
    float acc[4][4];
#pragma unroll
    for (int i = 0; i < 4; i++)
#pragma unroll
        for (int j = 0; j < 4; j++) acc[i][j] = 0.f;

    int lrow = tid >> 2;
    int lk   = (tid & 3) * 4;
    int gm = blockIdx.y * 64 + lrow;
    int gn = blockIdx.x * 64 + lrow;

    for (int k0 = 0; k0 < DH; k0 += 16) {
        float4 av = make_float4(0, 0, 0, 0), bv = make_float4(0, 0, 0, 0);
        if (gm < LL) av = *(const float4*)(Aq + (size_t)gm * DH + k0 + lk);
        if (gn < LL) bv = *(const float4*)(Bk + (size_t)gn * DH + k0 + lk);
        As[lk + 0][lrow] = av.x; As[lk + 1][lrow] = av.y;
        As[lk + 2][lrow] = av.z; As[lk + 3][lrow] = av.w;
        Bs[lk + 0][lrow] = bv.x; Bs[lk + 1][lrow] = bv.y;
        Bs[lk + 2][lrow] = bv.z; Bs[lk + 3][lrow] = bv.w;
        __syncthreads();
#pragma unroll
        for (int kk = 0; kk < 16; kk++) {
            float ar[4], br[4];
#pragma unroll
            for (int i = 0; i < 4; i++) ar[i] = As[kk][trow * 4 + i];
#pragma unroll
            for (int j = 0; j < 4; j++) br[j] = Bs[kk][tcol * 4 + j];
#pragma unroll
            for (int i = 0; i < 4; i++)
#pragma unroll
                for (int j = 0; j < 4; j++)
                    acc[i][j] = fmaf(ar[i], br[j], acc[i][j]);
        }
        __syncthreads();
    }

    float* Srow = g_S + (size_t)z * LL * LL;
    int bq = iB % Bb;
#pragma unroll
    for (int i = 0; i < 4; i++) {
        int m = blockIdx.y * 64 + trow * 4 + i;
        if (m >= LL) continue;
#pragma unroll
        for (int j = 0; j < 4; j++) {
            int n = blockIdx.x * 64 + tcol * 4 + j;
            if (n >= LL) continue;
            float s = acc[i][j] * 0.125f;
            if (n >= NWIN && q_mask[bq * NQ + (n - NWIN)] == 0) s = -1e30f;
            Srow[(size_t)m * LL + n] = s;
        }
    }
}

// ---------------- 4) row softmax over keys (warp per row) -------------------
__global__ __launch_bounds__(256) void k_softmax() {
    int row  = blockIdx.x * 8 + (threadIdx.x >> 5);
    int lane = threadIdx.x & 31;
    if (row >= BW * NH * LL) return;
    float* s = g_S + (size_t)row * LL;
    float v[9];
    float mx = -1e38f;
#pragma unroll
    for (int j = 0; j < 9; j++) {
        int k = lane + j * 32;
        v[j] = (k < LL) ? s[k] : -1e38f;
        mx = fmaxf(mx, v[j]);
    }
#pragma unroll
    for (int o = 16; o > 0; o >>= 1) mx = fmaxf(mx, __shfl_xor_sync(~0u, mx, o));
    float sum = 0.f;
#pragma unroll
    for (int j = 0; j < 9; j++) {
        int k = lane + j * 32;
        v[j] = (k < LL) ? __expf(v[j] - mx) : 0.f;
        sum += v[j];
    }
#pragma unroll
    for (int o = 16; o > 0; o >>= 1) sum += __shfl_xor_sync(~0u, sum, o);
    float inv = 1.f / sum;
#pragma unroll
    for (int j = 0; j < 9; j++) {
        int k = lane + j * 32;
        if (k < LL) s[k] = v[j] * inv;
    }
}

// ---------------- 5) O = P @ V (batched, 64x64 tiles, NN) --------------------
__global__ __launch_bounds__(256) void k_attn_O() {
    __shared__ float As[16][68];
    __shared__ float Bs[16][68];
    int z = blockIdx.z;
    int iB = z / NH, hd = z % NH;
    const float* P = g_S + (size_t)z * LL * LL;
    const float* V = g_V + (size_t)z * LL * DH;
    int tid = threadIdx.x;
    int trow = tid / 16, tcol = tid % 16;
    float acc[4][4];
#pragma unroll
    for (int i = 0; i < 4; i++)
#pragma unroll
        for (int j = 0; j < 4; j++) acc[i][j] = 0.f;

    int a_row = tid >> 2;
    int a_k   = (tid & 3) * 4;
    int b_k   = tid >> 4;          // 0..15
    int b_n   = (tid & 15) * 4;    // 0..60
    int gm = blockIdx.y * 64 + a_row;

    for (int k0 = 0; k0 < LL; k0 += 16) {
        float4 av = make_float4(0, 0, 0, 0);
        if (gm < LL && (k0 + a_k) < LL)
            av = *(const float4*)(P + (size_t)gm * LL + k0 + a_k);
        As[a_k + 0][a_row] = av.x; As[a_k + 1][a_row] = av.y;
        As[a_k + 2][a_row] = av.z; As[a_k + 3][a_row] = av.w;
        float4 bv = make_float4(0, 0, 0, 0);
        if ((k0 + b_k) < LL)
            bv = *(const float4*)(V + (size_t)(k0 + b_k) * DH + b_n);
        Bs[b_k][b_n + 0] = bv.x; Bs[b_k][b_n + 1] = bv.y;
        Bs[b_k][b_n + 2] = bv.z; Bs[b_k][b_n + 3] = bv.w;
        __syncthreads();
#pragma unroll
        for (int kk = 0; kk < 16; kk++) {
            float ar[4], br[4];
#pragma unroll
            for (int i = 0; i < 4; i++) ar[i] = As[kk][trow * 4 + i];
#pragma unroll
            for (int j = 0; j < 4; j++) br[j] = Bs[kk][tcol * 4 + j];
#pragma unroll
            for (int i = 0; i < 4; i++)
#pragma unroll
                for (int j = 0; j < 4; j++)
                    acc[i][j] = fmaf(ar[i], br[j], acc[i][j]);
        }
        __syncthreads();
    }

#pragma unroll
    for (int i = 0; i < 4; i++) {
        int m = blockIdx.y * 64 + trow * 4 + i;
        if (m >= LL) continue;
#pragma unroll
        for (int j = 0; j < 4; j++) {
            int n = tcol * 4 + j;  // < 64 always
            g_O[((size_t)iB * LL + m) * Cc + hd * DH + n] = acc[i][j];
        }
    }
}

// ---------------- 6a) ctx rows for pixels (window reverse + crop) -----------
__global__ __launch_bounds__(256) void k_ctx_pix() {
    int idx = blockIdx.x * blockDim.x + threadIdx.x;
    if (idx >= Bb * NTOK * (Cc / 4)) return;
    int j  = idx / (Cc / 4);
    int c4 = idx % (Cc / 4);
    int b = j / NTOK, p = j % NTOK;
    int py = p / WW, px = p % WW;
    int wy = py / WSZ, iy = py % WSZ;
    int wx = px / WSZ, ix = px % WSZ;
    int i = b * R_ + wy * NWX + wx;
    int l = iy * WSZ + ix;
    float4 v = ((const float4*)(g_O + ((size_t)i * LL + l) * Cc))[c4];
    ((float4*)(g_ctx + (size_t)j * Cc))[c4] = v;
}

// ---------------- 6b) ctx rows for queries (mean over windows) --------------
__global__ __launch_bounds__(256) void k_ctx_q() {
    int idx = blockIdx.x * blockDim.x + threadIdx.x;
    if (idx >= Bb * NQ * (Cc / 4)) return;
    int j  = idx / (Cc / 4);
    int c4 = idx % (Cc / 4);
    int b = j / NQ, lq = j % NQ;
    float4 acc = make_float4(0, 0, 0, 0);
#pragma unroll
    for (int w = 0; w < R_; w++) {
        int i = w * Bb + b;   // repeat-major flattening
        float4 v = ((const float4*)(g_O + ((size_t)i * LL + NWIN + lq) * Cc))[c4];
        acc.x += v.x; acc.y += v.y; acc.z += v.z; acc.w += v.w;
    }
    const float inv = 1.f / (float)R_;
    acc.x *= inv; acc.y *= inv; acc.z *= inv; acc.w *= inv;
    ((float4*)(g_ctx + (size_t)(Bb * NTOK + j) * Cc))[c4] = acc;
}

// ---------------- launch ------------------------------------------------------
extern "C" void kernel_launch(void* const* d_in, const int* in_sizes, int n_in,
                              void* d_out, int out_size) {
    const float* x     = (const float*)d_in[0];
    const float* q     = (const float*)d_in[1];
    const float* W_in  = (const float*)d_in[2];
    const float* W_out = (const float*)d_in[3];
    const float* b_out = (const float*)d_in[4];
    const int*   qmask = (const int*)d_in[5];
    float* out = (float*)d_out;

    k_gather_tok<<<(TOKROWS * (Cc / 4) + 255) / 256, 256>>>(x, q);

    dim3 g_qkv((3 * Cc + 127) / 128, (TOKROWS + 127) / 128);
    k_gemm_big<<<g_qkv, 256>>>(W_in, nullptr, nullptr, TOKROWS, 3 * Cc, Cc, 0);

    dim3 g_s((LL + 63) / 64, (LL + 63) / 64, BW * NH);
    k_attn_S<<<g_s, 256>>>(qmask);

    k_softmax<<<(BW * NH * LL + 7) / 8, 256>>>();

    dim3 g_o(1, (LL + 63) / 64, BW * NH);
    k_attn_O<<<g_o, 256>>>();

    k_ctx_pix<<<(Bb * NTOK * (Cc / 4) + 255) / 256, 256>>>();
    k_ctx_q<<<(Bb * NQ * (Cc / 4) + 255) / 256, 256>>>();

    dim3 g_out((Cc + 127) / 128, (CTXROWS + 127) / 128);
    k_gemm_big<<<g_out, 256>>>(W_out, b_out, out, CTXROWS, Cc, Cc, 1);
}

// round 4
// speedup vs baseline: 1.9122x; 1.9122x over previous
#include <cuda_runtime.h>
#include <cstdint>

// ---------------- problem constants ----------------
constexpr int Bb   = 4;
constexpr int NTOK = 4096;
constexpr int Cc   = 768;
constexpr int NQ   = 64;
constexpr int HH   = 64, WW = 64;
constexpr int WSZ  = 14;
constexpr int NH   = 12, DH = 64;
constexpr int NWX  = 5;
constexpr int R_   = 25;
constexpr int BW   = Bb * R_;           // 100
constexpr int NWIN = WSZ * WSZ;         // 196
constexpr int LL   = NWIN + NQ;         // 260
constexpr int TOKROWS = BW * LL;        // 26000
constexpr int CTXROWS = Bb * NTOK + Bb * NQ; // 16640

// ---------------- scratch ----------------
__device__ float g_tok[(size_t)TOKROWS * Cc];
__device__ float g_Q[(size_t)BW * NH * LL * DH];
__device__ float g_K[(size_t)BW * NH * LL * DH];
__device__ float g_V[(size_t)BW * NH * LL * DH];
__device__ float g_S[(size_t)BW * NH * LL * LL];
__device__ float g_O[(size_t)TOKROWS * Cc];
__device__ float g_ctx[(size_t)CTXROWS * Cc];
__device__ float g_Wt[(size_t)(3 * Cc) * Cc];   // tf32-rounded W_in
__device__ float g_Wot[(size_t)Cc * Cc];        // tf32-rounded W_out

// ---------------- helpers ----------------
__device__ __forceinline__ float tf32r(float x) {
    uint32_t y;
    asm("cvt.rna.tf32.f32 %0, %1;" : "=r"(y) : "f"(x));
    return __uint_as_float(y);
}
__device__ __forceinline__ uint32_t smem_u32(const void* p) {
    uint32_t a;
    asm("{ .reg .u64 t; cvta.to.shared.u64 t, %1; cvt.u32.u64 %0, t; }"
        : "=r"(a) : "l"(p));
    return a;
}
__device__ __forceinline__ void cp16(uint32_t s, const void* g) {
    asm volatile("cp.async.cg.shared.global [%0], [%1], 16;" :: "r"(s), "l"(g) : "memory");
}
__device__ __forceinline__ void mma_tf32(float* c, const uint32_t* a,
                                         uint32_t b0, uint32_t b1) {
    asm volatile("mma.sync.aligned.m16n8k8.row.col.f32.tf32.tf32.f32 "
                 "{%0,%1,%2,%3}, {%4,%5,%6,%7}, {%8,%9}, {%0,%1,%2,%3};"
                 : "+f"(c[0]), "+f"(c[1]), "+f"(c[2]), "+f"(c[3])
                 : "r"(a[0]), "r"(a[1]), "r"(a[2]), "r"(a[3]), "r"(b0), "r"(b1));
}

// ---------------- 0) tf32-round weights ----------------
__global__ __launch_bounds__(256) void k_cvt_w(const float* __restrict__ Win,
                                               const float* __restrict__ Wout) {
    int idx = blockIdx.x * blockDim.x + threadIdx.x;
    const int N1 = 3 * Cc * Cc;
    const int N2 = Cc * Cc;
    if (idx < N1) g_Wt[idx] = tf32r(Win[idx]);
    else if (idx < N1 + N2) g_Wot[idx - N1] = tf32r(Wout[idx - N1]);
}

// ---------------- 1) gather tokens (tf32-rounded) ----------------
__global__ __launch_bounds__(256) void k_gather_tok(const float* __restrict__ x,
                                                    const float* __restrict__ q) {
    int idx = blockIdx.x * blockDim.x + threadIdx.x;
    if (idx >= TOKROWS * (Cc / 4)) return;
    int t  = idx / (Cc / 4);
    int c4 = idx % (Cc / 4);
    int i = t / LL, l = t % LL;
    float4 val = make_float4(0.f, 0.f, 0.f, 0.f);
    if (l < NWIN) {
        int b = i / R_, w = i % R_;
        int wy = w / NWX, wx = w % NWX;
        int py = wy * WSZ + l / WSZ;
        int px = wx * WSZ + l % WSZ;
        if (py < HH && px < WW)
            val = ((const float4*)(x + ((size_t)b * NTOK + py * WW + px) * Cc))[c4];
    } else {
        int bq = i % Bb;
        int lq = l - NWIN;
        val = ((const float4*)(q + ((size_t)bq * NQ + lq) * Cc))[c4];
    }
    val.x = tf32r(val.x); val.y = tf32r(val.y);
    val.z = tf32r(val.z); val.w = tf32r(val.w);
    ((float4*)(g_tok + (size_t)t * Cc))[c4] = val;
}

// ---------------- 2) tf32 mma.sync GEMM (NT): C = A @ Bw^T ----------------
// CTA tile 128x128, K-chunk 32, double-buffered cp.async.
// mode 0: A=g_tok, Bw=g_Wt,  scatter -> g_Q/g_K/g_V
// mode 1: A=g_ctx, Bw=g_Wot, out = d_out + bias
constexpr int ROWSTR = 36;                 // floats per smem row (conflict-free)
constexpr int TILEB  = 128 * ROWSTR * 4;   // 18432 bytes per tile buffer
constexpr int SMEM_GEMM = 4 * TILEB;       // A0 A1 B0 B1

__global__ __launch_bounds__(256) void k_gemm_mma(const float* __restrict__ bias,
                                                  float* __restrict__ out,
                                                  int M, int Nn, int mode) {
    extern __shared__ float smf[];
    uint32_t sb = smem_u32(smf);
    // select operand pointers IN DEVICE CODE (device-global addresses are
    // only valid when taken on the device)
    const float* A  = (mode == 0) ? g_tok : g_ctx;
    const float* Bw = (mode == 0) ? g_Wt  : g_Wot;
    int tid = threadIdx.x, wid = tid >> 5, lane = tid & 31;
    int grp = lane >> 2, tig = lane & 3;
    int wm = wid & 3, wn = wid >> 2;     // warp 32-row slice, 64-col slice
    int mb = blockIdx.y, nb = blockIdx.x;

    float acc[2][8][4];
#pragma unroll
    for (int i = 0; i < 2; i++)
#pragma unroll
        for (int j = 0; j < 8; j++)
#pragma unroll
            for (int k = 0; k < 4; k++) acc[i][j][k] = 0.f;

    auto copy_tile = [&](int kc, int buf) {
        uint32_t sa = sb + buf * TILEB;
        uint32_t sbm = sb + 2 * TILEB + buf * TILEB;
#pragma unroll
        for (int i = 0; i < 4; i++) {
            int idx = tid * 4 + i;
            int r = idx >> 3, c4 = idx & 7;
            int gm = mb * 128 + r;
            if (gm >= M) gm = M - 1;
            cp16(sa + (r * ROWSTR + c4 * 4) * 4, A + (size_t)gm * Cc + kc + c4 * 4);
            int gn = nb * 128 + r;
            cp16(sbm + (r * ROWSTR + c4 * 4) * 4, Bw + (size_t)gn * Cc + kc + c4 * 4);
        }
        asm volatile("cp.async.commit_group;" ::: "memory");
    };

    copy_tile(0, 0);
    const int NCH = Cc / 32;   // 24
    for (int ci = 0; ci < NCH; ci++) {
        asm volatile("cp.async.wait_group 0;" ::: "memory");
        __syncthreads();
        if (ci + 1 < NCH) copy_tile((ci + 1) * 32, (ci + 1) & 1);

        const uint32_t* As = (const uint32_t*)(smf + (ci & 1) * (TILEB / 4));
        const uint32_t* Bs = (const uint32_t*)(smf + 2 * (TILEB / 4) + (ci & 1) * (TILEB / 4));
#pragma unroll
        for (int ks = 0; ks < 4; ks++) {
            int k0 = ks * 8;
            uint32_t a[2][4];
#pragma unroll
            for (int mt = 0; mt < 2; mt++) {
                int r0 = wm * 32 + mt * 16 + grp;
                a[mt][0] = As[r0 * ROWSTR + k0 + tig];
                a[mt][1] = As[(r0 + 8) * ROWSTR + k0 + tig];
                a[mt][2] = As[r0 * ROWSTR + k0 + tig + 4];
                a[mt][3] = As[(r0 + 8) * ROWSTR + k0 + tig + 4];
            }
#pragma unroll
            for (int nt = 0; nt < 8; nt++) {
                int c0 = wn * 64 + nt * 8 + grp;
                uint32_t b0 = Bs[c0 * ROWSTR + k0 + tig];
                uint32_t b1 = Bs[c0 * ROWSTR + k0 + tig + 4];
                mma_tf32(acc[0][nt], a[0], b0, b1);
                mma_tf32(acc[1][nt], a[1], b0, b1);
            }
        }
        __syncthreads();
    }

    // epilogue
#pragma unroll
    for (int mt = 0; mt < 2; mt++) {
        int m0 = mb * 128 + wm * 32 + mt * 16 + grp;
#pragma unroll
        for (int nt = 0; nt < 8; nt++) {
            int n0 = nb * 128 + wn * 64 + nt * 8 + tig * 2;
#pragma unroll
            for (int h = 0; h < 2; h++) {
                int m = m0 + h * 8;
                if (m >= M) continue;
                float v0 = acc[mt][nt][h * 2 + 0];
                float v1 = acc[mt][nt][h * 2 + 1];
                if (mode == 0) {
                    int ti = m / LL, l = m % LL;
                    int which = n0 / Cc;
                    int hd = (n0 % Cc) / DH;
                    int dd = n0 % DH;
                    float* dst = (which == 0) ? g_Q : (which == 1) ? g_K : g_V;
                    *(float2*)(dst + (((size_t)ti * NH + hd) * LL + l) * DH + dd) =
                        make_float2(v0, v1);
                } else {
                    *(float2*)(out + (size_t)m * Nn + n0) =
                        make_float2(v0 + bias[n0], v1 + bias[n0 + 1]);
                }
            }
        }
    }
}

// ---------------- 3) S = scale * Q @ K^T + mask ----------------
__global__ __launch_bounds__(256) void k_attn_S(const int* __restrict__ q_mask) {
    __shared__ float As[16][68];
    __shared__ float Bs[16][68];
    int z = blockIdx.z;
    int iB = z / NH;
    const float* Aq = g_Q + (size_t)z * LL * DH;
    const float* Bk = g_K + (size_t)z * LL * DH;
    int tid = threadIdx.x;
    int trow = tid / 16, tcol = tid % 16;
    float acc[4][4];
#pragma unroll
    for (int i = 0; i < 4; i++)
#pragma unroll
        for (int j = 0; j < 4; j++) acc[i][j] = 0.f;

    int lrow = tid >> 2;
    int lk   = (tid & 3) * 4;
    int gm = blockIdx.y * 64 + lrow;
    int gn = blockIdx.x * 64 + lrow;

    for (int k0 = 0; k0 < DH; k0 += 16) {
        float4 av = make_float4(0, 0, 0, 0), bv = make_float4(0, 0, 0, 0);
        if (gm < LL) av = *(const float4*)(Aq + (size_t)gm * DH + k0 + lk);
        if (gn < LL) bv = *(const float4*)(Bk + (size_t)gn * DH + k0 + lk);
        As[lk + 0][lrow] = av.x; As[lk + 1][lrow] = av.y;
        As[lk + 2][lrow] = av.z; As[lk + 3][lrow] = av.w;
        Bs[lk + 0][lrow] = bv.x; Bs[lk + 1][lrow] = bv.y;
        Bs[lk + 2][lrow] = bv.z; Bs[lk + 3][lrow] = bv.w;
        __syncthreads();
#pragma unroll
        for (int kk = 0; kk < 16; kk++) {
            float ar[4], br[4];
#pragma unroll
            for (int i = 0; i < 4; i++) ar[i] = As[kk][trow * 4 + i];
#pragma unroll
            for (int j = 0; j < 4; j++) br[j] = Bs[kk][tcol * 4 + j];
#pragma unroll
            for (int i = 0; i < 4; i++)
#pragma unroll
                for (int j = 0; j < 4; j++)
                    acc[i][j] = fmaf(ar[i], br[j], acc[i][j]);
        }
        __syncthreads();
    }

    float* Srow = g_S + (size_t)z * LL * LL;
    int bq = iB % Bb;
#pragma unroll
    for (int i = 0; i < 4; i++) {
        int m = blockIdx.y * 64 + trow * 4 + i;
        if (m >= LL) continue;
#pragma unroll
        for (int j = 0; j < 4; j++) {
            int n = blockIdx.x * 64 + tcol * 4 + j;
            if (n >= LL) continue;
            float s = acc[i][j] * 0.125f;
            if (n >= NWIN && q_mask[bq * NQ + (n - NWIN)] == 0) s = -1e30f;
            Srow[(size_t)m * LL + n] = s;
        }
    }
}

// ---------------- 4) row softmax ----------------
__global__ __launch_bounds__(256) void k_softmax() {
    int row  = blockIdx.x * 8 + (threadIdx.x >> 5);
    int lane = threadIdx.x & 31;
    if (row >= BW * NH * LL) return;
    float* s = g_S + (size_t)row * LL;
    float v[9];
    float mx = -1e38f;
#pragma unroll
    for (int j = 0; j < 9; j++) {
        int k = lane + j * 32;
        v[j] = (k < LL) ? s[k] : -1e38f;
        mx = fmaxf(mx, v[j]);
    }
#pragma unroll
    for (int o = 16; o > 0; o >>= 1) mx = fmaxf(mx, __shfl_xor_sync(~0u, mx, o));
    float sum = 0.f;
#pragma unroll
    for (int j = 0; j < 9; j++) {
        int k = lane + j * 32;
        v[j] = (k < LL) ? __expf(v[j] - mx) : 0.f;
        sum += v[j];
    }
#pragma unroll
    for (int o = 16; o > 0; o >>= 1) sum += __shfl_xor_sync(~0u, sum, o);
    float inv = 1.f / sum;
#pragma unroll
    for (int j = 0; j < 9; j++) {
        int k = lane + j * 32;
        if (k < LL) s[k] = v[j] * inv;
    }
}

// ---------------- 5) O = P @ V ----------------
__global__ __launch_bounds__(256) void k_attn_O() {
    __shared__ float As[16][68];
    __shared__ float Bs[16][68];
    int z = blockIdx.z;
    int iB = z / NH, hd = z % NH;
    const float* P = g_S + (size_t)z * LL * LL;
    const float* V = g_V + (size_t)z * LL * DH;
    int tid = threadIdx.x;
    int trow = tid / 16, tcol = tid % 16;
    float acc[4][4];
#pragma unroll
    for (int i = 0; i < 4; i++)
#pragma unroll
        for (int j = 0; j < 4; j++) acc[i][j] = 0.f;

    int a_row = tid >> 2;
    int a_k   = (tid & 3) * 4;
    int b_k   = tid >> 4;
    int b_n   = (tid & 15) * 4;
    int gm = blockIdx.y * 64 + a_row;

    for (int k0 = 0; k0 < LL; k0 += 16) {
        float4 av = make_float4(0, 0, 0, 0);
        if (gm < LL && (k0 + a_k) < LL)
            av = *(const float4*)(P + (size_t)gm * LL + k0 + a_k);
        As[a_k + 0][a_row] = av.x; As[a_k + 1][a_row] = av.y;
        As[a_k + 2][a_row] = av.z; As[a_k + 3][a_row] = av.w;
        float4 bv = make_float4(0, 0, 0, 0);
        if ((k0 + b_k) < LL)
            bv = *(const float4*)(V + (size_t)(k0 + b_k) * DH + b_n);
        Bs[b_k][b_n + 0] = bv.x; Bs[b_k][b_n + 1] = bv.y;
        Bs[b_k][b_n + 2] = bv.z; Bs[b_k][b_n + 3] = bv.w;
        __syncthreads();
#pragma unroll
        for (int kk = 0; kk < 16; kk++) {
            float ar[4], br[4];
#pragma unroll
            for (int i = 0; i < 4; i++) ar[i] = As[kk][trow * 4 + i];
#pragma unroll
            for (int j = 0; j < 4; j++) br[j] = Bs[kk][tcol * 4 + j];
#pragma unroll
            for (int i = 0; i < 4; i++)
#pragma unroll
                for (int j = 0; j < 4; j++)
                    acc[i][j] = fmaf(ar[i], br[j], acc[i][j]);
        }
        __syncthreads();
    }

#pragma unroll
    for (int i = 0; i < 4; i++) {
        int m = blockIdx.y * 64 + trow * 4 + i;
        if (m >= LL) continue;
#pragma unroll
        for (int j = 0; j < 4; j++) {
            int n = tcol * 4 + j;
            g_O[((size_t)iB * LL + m) * Cc + hd * DH + n] = acc[i][j];
        }
    }
}

// ---------------- 6a) ctx rows for pixels ----------------
__global__ __launch_bounds__(256) void k_ctx_pix() {
    int idx = blockIdx.x * blockDim.x + threadIdx.x;
    if (idx >= Bb * NTOK * (Cc / 4)) return;
    int j  = idx / (Cc / 4);
    int c4 = idx % (Cc / 4);
    int b = j / NTOK, p = j % NTOK;
    int py = p / WW, px = p % WW;
    int wy = py / WSZ, iy = py % WSZ;
    int wx = px / WSZ, ix = px % WSZ;
    int i = b * R_ + wy * NWX + wx;
    int l = iy * WSZ + ix;
    float4 v = ((const float4*)(g_O + ((size_t)i * LL + l) * Cc))[c4];
    v.x = tf32r(v.x); v.y = tf32r(v.y); v.z = tf32r(v.z); v.w = tf32r(v.w);
    ((float4*)(g_ctx + (size_t)j * Cc))[c4] = v;
}

// ---------------- 6b) ctx rows for queries (mean over windows) --------------
__global__ __launch_bounds__(256) void k_ctx_q() {
    int idx = blockIdx.x * blockDim.x + threadIdx.x;
    if (idx >= Bb * NQ * (Cc / 4)) return;
    int j  = idx / (Cc / 4);
    int c4 = idx % (Cc / 4);
    int b = j / NQ, lq = j % NQ;
    float4 acc = make_float4(0, 0, 0, 0);
#pragma unroll
    for (int w = 0; w < R_; w++) {
        int i = w * Bb + b;
        float4 v = ((const float4*)(g_O + ((size_t)i * LL + NWIN + lq) * Cc))[c4];
        acc.x += v.x; acc.y += v.y; acc.z += v.z; acc.w += v.w;
    }
    const float inv = 1.f / (float)R_;
    acc.x = tf32r(acc.x * inv); acc.y = tf32r(acc.y * inv);
    acc.z = tf32r(acc.z * inv); acc.w = tf32r(acc.w * inv);
    ((float4*)(g_ctx + (size_t)(Bb * NTOK + j) * Cc))[c4] = acc;
}

// ---------------- launch ----------------
extern "C" void kernel_launch(void* const* d_in, const int* in_sizes, int n_in,
                              void* d_out, int out_size) {
    const float* x     = (const float*)d_in[0];
    const float* q     = (const float*)d_in[1];
    const float* W_in  = (const float*)d_in[2];
    const float* W_out = (const float*)d_in[3];
    const float* b_out = (const float*)d_in[4];
    const int*   qmask = (const int*)d_in[5];
    float* out = (float*)d_out;

    static bool attr_set = false;
    if (!attr_set) {
        cudaFuncSetAttribute(k_gemm_mma, cudaFuncAttributeMaxDynamicSharedMemorySize,
                             SMEM_GEMM);
        attr_set = true;
    }

    k_cvt_w<<<(4 * Cc * Cc + 255) / 256, 256>>>(W_in, W_out);
    k_gather_tok<<<(TOKROWS * (Cc / 4) + 255) / 256, 256>>>(x, q);

    dim3 g_qkv(3 * Cc / 128, (TOKROWS + 127) / 128);   // 18 x 204
    k_gemm_mma<<<g_qkv, 256, SMEM_GEMM>>>(nullptr, nullptr, TOKROWS, 3 * Cc, 0);

    dim3 g_s((LL + 63) / 64, (LL + 63) / 64, BW * NH);
    k_attn_S<<<g_s, 256>>>(qmask);

    k_softmax<<<(BW * NH * LL + 7) / 8, 256>>>();

    dim3 g_o(1, (LL + 63) / 64, BW * NH);
    k_attn_O<<<g_o, 256>>>();

    k_ctx_pix<<<(Bb * NTOK * (Cc / 4) + 255) / 256, 256>>>();
    k_ctx_q<<<(Bb * NQ * (Cc / 4) + 255) / 256, 256>>>();

    dim3 g_out(Cc / 128, CTXROWS / 128);               // 6 x 130
    k_gemm_mma<<<g_out, 256, SMEM_GEMM>>>(b_out, out, CTXROWS, Cc, 1);
}

// round 6
// speedup vs baseline: 2.5619x; 1.3398x over previous
#include <cuda_runtime.h>
#include <cstdint>

// ---------------- problem constants ----------------
constexpr int Bb   = 4;
constexpr int NTOK = 4096;
constexpr int Cc   = 768;
constexpr int NQ   = 64;
constexpr int HH   = 64, WW = 64;
constexpr int WSZ  = 14;
constexpr int NH   = 12, DH = 64;
constexpr int NWX  = 5;
constexpr int R_   = 25;
constexpr int BW   = Bb * R_;           // 100
constexpr int NWIN = WSZ * WSZ;         // 196
constexpr int LL   = NWIN + NQ;         // 260
constexpr int TOKROWS = BW * LL;        // 26000
constexpr int CTXROWS = Bb * NTOK + Bb * NQ; // 16640

// ---------------- scratch ----------------
__device__ float g_tok[(size_t)TOKROWS * Cc];
__device__ float g_Q[(size_t)BW * NH * LL * DH];
__device__ float g_K[(size_t)BW * NH * LL * DH];
__device__ float g_V[(size_t)BW * NH * LL * DH];
__device__ float g_O[(size_t)TOKROWS * Cc];
__device__ float g_ctx[(size_t)CTXROWS * Cc];
__device__ float g_Wt[(size_t)(3 * Cc) * Cc];
__device__ float g_Wot[(size_t)Cc * Cc];

// ---------------- helpers ----------------
__device__ __forceinline__ float tf32r(float x) {
    uint32_t y;
    asm("cvt.rna.tf32.f32 %0, %1;" : "=r"(y) : "f"(x));
    return __uint_as_float(y);
}
__device__ __forceinline__ uint32_t smem_u32(const void* p) {
    uint32_t a;
    asm("{ .reg .u64 t; cvta.to.shared.u64 t, %1; cvt.u32.u64 %0, t; }"
        : "=r"(a) : "l"(p));
    return a;
}
__device__ __forceinline__ void cp16(uint32_t s, const void* g) {
    asm volatile("cp.async.cg.shared.global [%0], [%1], 16;" :: "r"(s), "l"(g) : "memory");
}
__device__ __forceinline__ void mma_tf32(float* c, const uint32_t* a,
                                         uint32_t b0, uint32_t b1) {
    asm volatile("mma.sync.aligned.m16n8k8.row.col.f32.tf32.tf32.f32 "
                 "{%0,%1,%2,%3}, {%4,%5,%6,%7}, {%8,%9}, {%0,%1,%2,%3};"
                 : "+f"(c[0]), "+f"(c[1]), "+f"(c[2]), "+f"(c[3])
                 : "r"(a[0]), "r"(a[1]), "r"(a[2]), "r"(a[3]), "r"(b0), "r"(b1));
}

// ---------------- 0) tf32-round weights ----------------
__global__ __launch_bounds__(256) void k_cvt_w(const float* __restrict__ Win,
                                               const float* __restrict__ Wout) {
    int idx = blockIdx.x * blockDim.x + threadIdx.x;
    const int N1 = 3 * Cc * Cc;
    const int N2 = Cc * Cc;
    if (idx < N1) g_Wt[idx] = tf32r(Win[idx]);
    else if (idx < N1 + N2) g_Wot[idx - N1] = tf32r(Wout[idx - N1]);
}

// ---------------- 1) gather tokens (tf32-rounded) ----------------
__global__ __launch_bounds__(256) void k_gather_tok(const float* __restrict__ x,
                                                    const float* __restrict__ q) {
    int idx = blockIdx.x * blockDim.x + threadIdx.x;
    if (idx >= TOKROWS * (Cc / 4)) return;
    int t  = idx / (Cc / 4);
    int c4 = idx % (Cc / 4);
    int i = t / LL, l = t % LL;
    float4 val = make_float4(0.f, 0.f, 0.f, 0.f);
    if (l < NWIN) {
        int b = i / R_, w = i % R_;
        int wy = w / NWX, wx = w % NWX;
        int py = wy * WSZ + l / WSZ;
        int px = wx * WSZ + l % WSZ;
        if (py < HH && px < WW)
            val = ((const float4*)(x + ((size_t)b * NTOK + py * WW + px) * Cc))[c4];
    } else {
        int bq = i % Bb;
        int lq = l - NWIN;
        val = ((const float4*)(q + ((size_t)bq * NQ + lq) * Cc))[c4];
    }
    val.x = tf32r(val.x); val.y = tf32r(val.y);
    val.z = tf32r(val.z); val.w = tf32r(val.w);
    ((float4*)(g_tok + (size_t)t * Cc))[c4] = val;
}

// ---------------- 2) tf32 mma.sync GEMM (NT) ----------------
constexpr int ROWSTR = 36;
constexpr int TILEB  = 128 * ROWSTR * 4;
constexpr int SMEM_GEMM = 4 * TILEB;

__global__ __launch_bounds__(256) void k_gemm_mma(const float* __restrict__ bias,
                                                  float* __restrict__ out,
                                                  int M, int Nn, int mode) {
    extern __shared__ float smf[];
    uint32_t sb = smem_u32(smf);
    const float* A  = (mode == 0) ? g_tok : g_ctx;
    const float* Bw = (mode == 0) ? g_Wt  : g_Wot;
    int tid = threadIdx.x, wid = tid >> 5, lane = tid & 31;
    int grp = lane >> 2, tig = lane & 3;
    int wm = wid & 3, wn = wid >> 2;
    int mb = blockIdx.y, nb = blockIdx.x;

    float acc[2][8][4];
#pragma unroll
    for (int i = 0; i < 2; i++)
#pragma unroll
        for (int j = 0; j < 8; j++)
#pragma unroll
            for (int k = 0; k < 4; k++) acc[i][j][k] = 0.f;

    auto copy_tile = [&](int kc, int buf) {
        uint32_t sa = sb + buf * TILEB;
        uint32_t sbm = sb + 2 * TILEB + buf * TILEB;
#pragma unroll
        for (int i = 0; i < 4; i++) {
            int idx = tid * 4 + i;
            int r = idx >> 3, c4 = idx & 7;
            int gm = mb * 128 + r;
            if (gm >= M) gm = M - 1;
            cp16(sa + (r * ROWSTR + c4 * 4) * 4, A + (size_t)gm * Cc + kc + c4 * 4);
            int gn = nb * 128 + r;
            cp16(sbm + (r * ROWSTR + c4 * 4) * 4, Bw + (size_t)gn * Cc + kc + c4 * 4);
        }
        asm volatile("cp.async.commit_group;" ::: "memory");
    };

    copy_tile(0, 0);
    const int NCH = Cc / 32;
    for (int ci = 0; ci < NCH; ci++) {
        asm volatile("cp.async.wait_group 0;" ::: "memory");
        __syncthreads();
        if (ci + 1 < NCH) copy_tile((ci + 1) * 32, (ci + 1) & 1);

        const uint32_t* As = (const uint32_t*)(smf + (ci & 1) * (TILEB / 4));
        const uint32_t* Bs = (const uint32_t*)(smf + 2 * (TILEB / 4) + (ci & 1) * (TILEB / 4));
#pragma unroll
        for (int ks = 0; ks < 4; ks++) {
            int k0 = ks * 8;
            uint32_t a[2][4];
#pragma unroll
            for (int mt = 0; mt < 2; mt++) {
                int r0 = wm * 32 + mt * 16 + grp;
                a[mt][0] = As[r0 * ROWSTR + k0 + tig];
                a[mt][1] = As[(r0 + 8) * ROWSTR + k0 + tig];
                a[mt][2] = As[r0 * ROWSTR + k0 + tig + 4];
                a[mt][3] = As[(r0 + 8) * ROWSTR + k0 + tig + 4];
            }
#pragma unroll
            for (int nt = 0; nt < 8; nt++) {
                int c0 = wn * 64 + nt * 8 + grp;
                uint32_t b0 = Bs[c0 * ROWSTR + k0 + tig];
                uint32_t b1 = Bs[c0 * ROWSTR + k0 + tig + 4];
                mma_tf32(acc[0][nt], a[0], b0, b1);
                mma_tf32(acc[1][nt], a[1], b0, b1);
            }
        }
        __syncthreads();
    }

#pragma unroll
    for (int mt = 0; mt < 2; mt++) {
        int m0 = mb * 128 + wm * 32 + mt * 16 + grp;
#pragma unroll
        for (int nt = 0; nt < 8; nt++) {
            int n0 = nb * 128 + wn * 64 + nt * 8 + tig * 2;
#pragma unroll
            for (int h = 0; h < 2; h++) {
                int m = m0 + h * 8;
                if (m >= M) continue;
                float v0 = acc[mt][nt][h * 2 + 0];
                float v1 = acc[mt][nt][h * 2 + 1];
                if (mode == 0) {
                    int ti = m / LL, l = m % LL;
                    int which = n0 / Cc;
                    int hd = (n0 % Cc) / DH;
                    int dd = n0 % DH;
                    float* dst = (which == 0) ? g_Q : (which == 1) ? g_K : g_V;
                    *(float2*)(dst + (((size_t)ti * NH + hd) * LL + l) * DH + dd) =
                        make_float2(v0, v1);
                } else {
                    *(float2*)(out + (size_t)m * Nn + n0) =
                        make_float2(v0 + bias[n0], v1 + bias[n0 + 1]);
                }
            }
        }
    }
}

// ---------------- 3) fused attention: S -> softmax -> O ----------------
constexpr int PADL   = 272;
constexpr int KV_STR = 68;
constexpr int P_STR  = 276;
constexpr int F_VS   = PADL * KV_STR;
constexpr int F_PQ   = 2 * PADL * KV_STR;
constexpr int F_RMAX = F_PQ + 64 * P_STR;
constexpr int F_RSUM = F_RMAX + 128;
constexpr int F_MSK  = F_RSUM + 128;
constexpr int SMEM_ATT = (F_MSK + PADL) * 4;

__global__ __launch_bounds__(256, 1) void k_attn_fused(const int* __restrict__ q_mask) {
    extern __shared__ float sm[];
    float* Ks = sm;
    float* Vs = sm + F_VS;
    float* PQ = sm + F_PQ;
    float* rmax = sm + F_RMAX;
    float* rsum = sm + F_RSUM;
    float* msk  = sm + F_MSK;

    int z  = blockIdx.x;
    int iB = z / NH;
    int hd = z % NH;
    int bq = iB % Bb;
    const float* Qg = g_Q + (size_t)z * LL * DH;
    const float* Kg = g_K + (size_t)z * LL * DH;
    const float* Vg = g_V + (size_t)z * LL * DH;

    int tid = threadIdx.x, wid = tid >> 5, lane = tid & 31;
    int grp = lane >> 2, tig = lane & 3;
    int wm = wid & 3, wn = wid >> 2;
    int lr0 = wm * 16 + grp, lr1 = lr0 + 8;

    // additive mask per key column (FIX: strided loop, PADL > blockDim)
    for (int j = tid; j < PADL; j += 256) {
        float m = 0.f;
        if (j >= NWIN)
            m = (j < LL && q_mask[bq * NQ + j - NWIN] != 0) ? 0.f : -1e30f;
        msk[j] = m;
    }
    // load K,V (tf32-rounded)
    for (int idx = tid; idx < LL * 16; idx += 256) {
        int r = idx >> 4, c = idx & 15;
        float4 kv = *(const float4*)(Kg + r * DH + c * 4);
        float4 vv = *(const float4*)(Vg + r * DH + c * 4);
        float* kd = Ks + r * KV_STR + c * 4;
        kd[0] = tf32r(kv.x); kd[1] = tf32r(kv.y); kd[2] = tf32r(kv.z); kd[3] = tf32r(kv.w);
        float* vd = Vs + r * KV_STR + c * 4;
        vd[0] = tf32r(vv.x); vd[1] = tf32r(vv.y); vd[2] = tf32r(vv.z); vd[3] = tf32r(vv.w);
    }
    // zero pad rows
    for (int idx = tid; idx < (PADL - LL) * 16; idx += 256) {
        int r = LL + (idx >> 4), c = idx & 15;
        *(float4*)(Ks + r * KV_STR + c * 4) = make_float4(0, 0, 0, 0);
        *(float4*)(Vs + r * KV_STR + c * 4) = make_float4(0, 0, 0, 0);
    }

    const uint32_t* Ku = (const uint32_t*)Ks;
    const uint32_t* Vu = (const uint32_t*)Vs;
    const uint32_t* Qu = (const uint32_t*)PQ;
    const uint32_t* Pu = (const uint32_t*)PQ;

    for (int qt = 0; qt < 5; qt++) {
        int qbase = qt * 64;
        __syncthreads();

        for (int idx = tid; idx < 64 * 16; idx += 256) {
            int r = idx >> 4, c = idx & 15;
            int gr = qbase + r; if (gr >= LL) gr = 0;
            float4 qv = *(const float4*)(Qg + gr * DH + c * 4);
            float* qd = PQ + r * KV_STR + c * 4;
            qd[0] = tf32r(qv.x); qd[1] = tf32r(qv.y);
            qd[2] = tf32r(qv.z); qd[3] = tf32r(qv.w);
        }
        __syncthreads();

        // ---- S = Q @ K^T ----
        float sf[17][4];
#pragma unroll
        for (int t = 0; t < 17; t++)
#pragma unroll
            for (int k = 0; k < 4; k++) sf[t][k] = 0.f;
#pragma unroll
        for (int ksx = 0; ksx < 8; ksx++) {
            int k0 = ksx * 8;
            uint32_t a[4];
            a[0] = Qu[lr0 * KV_STR + k0 + tig];
            a[1] = Qu[lr1 * KV_STR + k0 + tig];
            a[2] = Qu[lr0 * KV_STR + k0 + tig + 4];
            a[3] = Qu[lr1 * KV_STR + k0 + tig + 4];
#pragma unroll
            for (int t = 0; t < 17; t++) {
                int n0 = wn * 136 + t * 8 + grp;
                mma_tf32(sf[t], a, Ku[n0 * KV_STR + k0 + tig],
                                  Ku[n0 * KV_STR + k0 + tig + 4]);
            }
        }

        // ---- scale + mask + rowmax ----
        float mx0 = -3e38f, mx1 = -3e38f;
#pragma unroll
        for (int t = 0; t < 17; t++) {
            int jb = wn * 136 + t * 8 + 2 * tig;
            float m0 = msk[jb], m1 = msk[jb + 1];
            sf[t][0] = sf[t][0] * 0.125f + m0;
            sf[t][1] = sf[t][1] * 0.125f + m1;
            sf[t][2] = sf[t][2] * 0.125f + m0;
            sf[t][3] = sf[t][3] * 0.125f + m1;
            mx0 = fmaxf(mx0, fmaxf(sf[t][0], sf[t][1]));
            mx1 = fmaxf(mx1, fmaxf(sf[t][2], sf[t][3]));
        }
        mx0 = fmaxf(mx0, __shfl_xor_sync(~0u, mx0, 1));
        mx0 = fmaxf(mx0, __shfl_xor_sync(~0u, mx0, 2));
        mx1 = fmaxf(mx1, __shfl_xor_sync(~0u, mx1, 1));
        mx1 = fmaxf(mx1, __shfl_xor_sync(~0u, mx1, 2));
        if (tig == 0) {
            rmax[lr0 * 2 + wn] = mx0;
            rmax[lr1 * 2 + wn] = mx1;
        }
        __syncthreads();
        float M0 = fmaxf(rmax[lr0 * 2], rmax[lr0 * 2 + 1]);
        float M1 = fmaxf(rmax[lr1 * 2], rmax[lr1 * 2 + 1]);

        // ---- exp, write P, row sums ----
        float s0 = 0.f, s1 = 0.f;
#pragma unroll
        for (int t = 0; t < 17; t++) {
            float e0 = __expf(sf[t][0] - M0), e1 = __expf(sf[t][1] - M0);
            float e2 = __expf(sf[t][2] - M1), e3 = __expf(sf[t][3] - M1);
            s0 += e0 + e1; s1 += e2 + e3;
            int j = wn * 136 + t * 8 + 2 * tig;
            *(float2*)(PQ + lr0 * P_STR + j) = make_float2(tf32r(e0), tf32r(e1));
            *(float2*)(PQ + lr1 * P_STR + j) = make_float2(tf32r(e2), tf32r(e3));
        }
        s0 += __shfl_xor_sync(~0u, s0, 1);
        s0 += __shfl_xor_sync(~0u, s0, 2);
        s1 += __shfl_xor_sync(~0u, s1, 1);
        s1 += __shfl_xor_sync(~0u, s1, 2);
        if (tig == 0) {
            rsum[lr0 * 2 + wn] = s0;
            rsum[lr1 * 2 + wn] = s1;
        }
        __syncthreads();

        // ---- O = P @ V ----
        float of[4][4];
#pragma unroll
        for (int nt = 0; nt < 4; nt++)
#pragma unroll
            for (int k = 0; k < 4; k++) of[nt][k] = 0.f;
#pragma unroll
        for (int kt = 0; kt < 34; kt++) {
            int k0 = kt * 8;
            uint32_t a[4];
            a[0] = Pu[lr0 * P_STR + k0 + tig];
            a[1] = Pu[lr1 * P_STR + k0 + tig];
            a[2] = Pu[lr0 * P_STR + k0 + tig + 4];
            a[3] = Pu[lr1 * P_STR + k0 + tig + 4];
#pragma unroll
            for (int nt = 0; nt < 4; nt++) {
                int n0 = wn * 32 + nt * 8 + grp;
                mma_tf32(of[nt], a, Vu[(k0 + tig) * KV_STR + n0],
                                    Vu[(k0 + tig + 4) * KV_STR + n0]);
            }
        }
        float inv0 = 1.f / (rsum[lr0 * 2] + rsum[lr0 * 2 + 1]);
        float inv1 = 1.f / (rsum[lr1 * 2] + rsum[lr1 * 2 + 1]);
        int grow0 = qbase + lr0, grow1 = qbase + lr1;
#pragma unroll
        for (int nt = 0; nt < 4; nt++) {
            int col = hd * DH + wn * 32 + nt * 8 + 2 * tig;
            if (grow0 < LL)
                *(float2*)(g_O + ((size_t)iB * LL + grow0) * Cc + col) =
                    make_float2(of[nt][0] * inv0, of[nt][1] * inv0);
            if (grow1 < LL)
                *(float2*)(g_O + ((size_t)iB * LL + grow1) * Cc + col) =
                    make_float2(of[nt][2] * inv1, of[nt][3] * inv1);
        }
    }
}

// ---------------- 6a) ctx rows for pixels ----------------
__global__ __launch_bounds__(256) void k_ctx_pix() {
    int idx = blockIdx.x * blockDim.x + threadIdx.x;
    if (idx >= Bb * NTOK * (Cc / 4)) return;
    int j  = idx / (Cc / 4);
    int c4 = idx % (Cc / 4);
    int b = j / NTOK, p = j % NTOK;
    int py = p / WW, px = p % WW;
    int wy = py / WSZ, iy = py % WSZ;
    int wx = px / WSZ, ix = px % WSZ;
    int i = b * R_ + wy * NWX + wx;
    int l = iy * WSZ + ix;
    float4 v = ((const float4*)(g_O + ((size_t)i * LL + l) * Cc))[c4];
    v.x = tf32r(v.x); v.y = tf32r(v.y); v.z = tf32r(v.z); v.w = tf32r(v.w);
    ((float4*)(g_ctx + (size_t)j * Cc))[c4] = v;
}

// ---------------- 6b) ctx rows for queries (mean over windows) --------------
__global__ __launch_bounds__(256) void k_ctx_q() {
    int idx = blockIdx.x * blockDim.x + threadIdx.x;
    if (idx >= Bb * NQ * (Cc / 4)) return;
    int j  = idx / (Cc / 4);
    int c4 = idx % (Cc / 4);
    int b = j / NQ, lq = j % NQ;
    float4 acc = make_float4(0, 0, 0, 0);
#pragma unroll
    for (int w = 0; w < R_; w++) {
        int i = w * Bb + b;
        float4 v = ((const float4*)(g_O + ((size_t)i * LL + NWIN + lq) * Cc))[c4];
        acc.x += v.x; acc.y += v.y; acc.z += v.z; acc.w += v.w;
    }
    const float inv = 1.f / (float)R_;
    acc.x = tf32r(acc.x * inv); acc.y = tf32r(acc.y * inv);
    acc.z = tf32r(acc.z * inv); acc.w = tf32r(acc.w * inv);
    ((float4*)(g_ctx + (size_t)(Bb * NTOK + j) * Cc))[c4] = acc;
}

// ---------------- launch ----------------
extern "C" void kernel_launch(void* const* d_in, const int* in_sizes, int n_in,
                              void* d_out, int out_size) {
    const float* x     = (const float*)d_in[0];
    const float* q     = (const float*)d_in[1];
    const float* W_in  = (const float*)d_in[2];
    const float* W_out = (const float*)d_in[3];
    const float* b_out = (const float*)d_in[4];
    const int*   qmask = (const int*)d_in[5];
    float* out = (float*)d_out;

    static bool attr_set = false;
    if (!attr_set) {
        cudaFuncSetAttribute(k_gemm_mma, cudaFuncAttributeMaxDynamicSharedMemorySize,
                             SMEM_GEMM);
        cudaFuncSetAttribute(k_attn_fused, cudaFuncAttributeMaxDynamicSharedMemorySize,
                             SMEM_ATT);
        attr_set = true;
    }

    k_cvt_w<<<(4 * Cc * Cc + 255) / 256, 256>>>(W_in, W_out);
    k_gather_tok<<<(TOKROWS * (Cc / 4) + 255) / 256, 256>>>(x, q);

    dim3 g_qkv(3 * Cc / 128, (TOKROWS + 127) / 128);
    k_gemm_mma<<<g_qkv, 256, SMEM_GEMM>>>(nullptr, nullptr, TOKROWS, 3 * Cc, 0);

    k_attn_fused<<<BW * NH, 256, SMEM_ATT>>>(qmask);

    k_ctx_pix<<<(Bb * NTOK * (Cc / 4) + 255) / 256, 256>>>();
    k_ctx_q<<<(Bb * NQ * (Cc / 4) + 255) / 256, 256>>>();

    dim3 g_out(Cc / 128, CTXROWS / 128);
    k_gemm_mma<<<g_out, 256, SMEM_GEMM>>>(b_out, out, CTXROWS, Cc, 1);
}

// round 7
// speedup vs baseline: 2.6821x; 1.0469x over previous
#include <cuda_runtime.h>
#include <cstdint>

// ---------------- problem constants ----------------
constexpr int Bb   = 4;
constexpr int NTOK = 4096;
constexpr int Cc   = 768;
constexpr int NQ   = 64;
constexpr int HH   = 64, WW = 64;
constexpr int WSZ  = 14;
constexpr int NH   = 12, DH = 64;
constexpr int NWX  = 5;
constexpr int R_   = 25;
constexpr int BW   = Bb * R_;           // 100
constexpr int NWIN = WSZ * WSZ;         // 196
constexpr int LL   = NWIN + NQ;         // 260
constexpr int TOKROWS = BW * LL;        // 26000
constexpr int CTXROWS = Bb * NTOK + Bb * NQ; // 16640

// ---------------- scratch ----------------
__device__ float g_tok[(size_t)TOKROWS * Cc];
__device__ float g_Q[(size_t)BW * NH * LL * DH];
__device__ float g_K[(size_t)BW * NH * LL * DH];
__device__ float g_V[(size_t)BW * NH * LL * DH];
__device__ float g_O[(size_t)TOKROWS * Cc];
__device__ float g_ctx[(size_t)CTXROWS * Cc];
__device__ float g_Wt[(size_t)(3 * Cc) * Cc];
__device__ float g_Wot[(size_t)Cc * Cc];

// ---------------- helpers ----------------
__device__ __forceinline__ float tf32r(float x) {
    uint32_t y;
    asm("cvt.rna.tf32.f32 %0, %1;" : "=r"(y) : "f"(x));
    return __uint_as_float(y);
}
__device__ __forceinline__ uint32_t smem_u32(const void* p) {
    uint32_t a;
    asm("{ .reg .u64 t; cvta.to.shared.u64 t, %1; cvt.u32.u64 %0, t; }"
        : "=r"(a) : "l"(p));
    return a;
}
__device__ __forceinline__ void cp16(uint32_t s, const void* g) {
    asm volatile("cp.async.cg.shared.global [%0], [%1], 16;" :: "r"(s), "l"(g) : "memory");
}
__device__ __forceinline__ void mma_tf32(float* c, const uint32_t* a,
                                         uint32_t b0, uint32_t b1) {
    asm volatile("mma.sync.aligned.m16n8k8.row.col.f32.tf32.tf32.f32 "
                 "{%0,%1,%2,%3}, {%4,%5,%6,%7}, {%8,%9}, {%0,%1,%2,%3};"
                 : "+f"(c[0]), "+f"(c[1]), "+f"(c[2]), "+f"(c[3])
                 : "r"(a[0]), "r"(a[1]), "r"(a[2]), "r"(a[3]), "r"(b0), "r"(b1));
}

// ---------------- 0) tf32-round weights ----------------
__global__ __launch_bounds__(256) void k_cvt_w(const float* __restrict__ Win,
                                               const float* __restrict__ Wout) {
    int idx = blockIdx.x * blockDim.x + threadIdx.x;
    const int N1 = 3 * Cc * Cc;
    const int N2 = Cc * Cc;
    if (idx < N1) g_Wt[idx] = tf32r(Win[idx]);
    else if (idx < N1 + N2) g_Wot[idx - N1] = tf32r(Wout[idx - N1]);
}

// ---------------- 1) gather tokens (tf32-rounded) ----------------
__global__ __launch_bounds__(256) void k_gather_tok(const float* __restrict__ x,
                                                    const float* __restrict__ q) {
    int idx = blockIdx.x * blockDim.x + threadIdx.x;
    if (idx >= TOKROWS * (Cc / 4)) return;
    int t  = idx / (Cc / 4);
    int c4 = idx % (Cc / 4);
    int i = t / LL, l = t % LL;
    float4 val = make_float4(0.f, 0.f, 0.f, 0.f);
    if (l < NWIN) {
        int b = i / R_, w = i % R_;
        int wy = w / NWX, wx = w % NWX;
        int py = wy * WSZ + l / WSZ;
        int px = wx * WSZ + l % WSZ;
        if (py < HH && px < WW)
            val = ((const float4*)(x + ((size_t)b * NTOK + py * WW + px) * Cc))[c4];
    } else {
        int bq = i % Bb;
        int lq = l - NWIN;
        val = ((const float4*)(q + ((size_t)bq * NQ + lq) * Cc))[c4];
    }
    val.x = tf32r(val.x); val.y = tf32r(val.y);
    val.z = tf32r(val.z); val.w = tf32r(val.w);
    ((float4*)(g_tok + (size_t)t * Cc))[c4] = val;
}

// ---------------- 2) tf32 mma.sync GEMM (NT) ----------------
constexpr int ROWSTR = 36;
constexpr int TILEB  = 128 * ROWSTR * 4;
constexpr int SMEM_GEMM = 4 * TILEB;

__global__ __launch_bounds__(256) void k_gemm_mma(const float* __restrict__ bias,
                                                  float* __restrict__ out,
                                                  int M, int Nn, int mode) {
    extern __shared__ float smf[];
    uint32_t sb = smem_u32(smf);
    const float* A  = (mode == 0) ? g_tok : g_ctx;
    const float* Bw = (mode == 0) ? g_Wt  : g_Wot;
    int tid = threadIdx.x, wid = tid >> 5, lane = tid & 31;
    int grp = lane >> 2, tig = lane & 3;
    int wm = wid & 3, wn = wid >> 2;
    int mb = blockIdx.y, nb = blockIdx.x;

    float acc[2][8][4];
#pragma unroll
    for (int i = 0; i < 2; i++)
#pragma unroll
        for (int j = 0; j < 8; j++)
#pragma unroll
            for (int k = 0; k < 4; k++) acc[i][j][k] = 0.f;

    auto copy_tile = [&](int kc, int buf) {
        uint32_t sa = sb + buf * TILEB;
        uint32_t sbm = sb + 2 * TILEB + buf * TILEB;
#pragma unroll
        for (int i = 0; i < 4; i++) {
            int idx = tid * 4 + i;
            int r = idx >> 3, c4 = idx & 7;
            int gm = mb * 128 + r;
            if (gm >= M) gm = M - 1;
            cp16(sa + (r * ROWSTR + c4 * 4) * 4, A + (size_t)gm * Cc + kc + c4 * 4);
            int gn = nb * 128 + r;
            cp16(sbm + (r * ROWSTR + c4 * 4) * 4, Bw + (size_t)gn * Cc + kc + c4 * 4);
        }
        asm volatile("cp.async.commit_group;" ::: "memory");
    };

    copy_tile(0, 0);
    const int NCH = Cc / 32;
    for (int ci = 0; ci < NCH; ci++) {
        asm volatile("cp.async.wait_group 0;" ::: "memory");
        __syncthreads();
        if (ci + 1 < NCH) copy_tile((ci + 1) * 32, (ci + 1) & 1);

        const uint32_t* As = (const uint32_t*)(smf + (ci & 1) * (TILEB / 4));
        const uint32_t* Bs = (const uint32_t*)(smf + 2 * (TILEB / 4) + (ci & 1) * (TILEB / 4));
#pragma unroll
        for (int ks = 0; ks < 4; ks++) {
            int k0 = ks * 8;
            uint32_t a[2][4];
#pragma unroll
            for (int mt = 0; mt < 2; mt++) {
                int r0 = wm * 32 + mt * 16 + grp;
                a[mt][0] = As[r0 * ROWSTR + k0 + tig];
                a[mt][1] = As[(r0 + 8) * ROWSTR + k0 + tig];
                a[mt][2] = As[r0 * ROWSTR + k0 + tig + 4];
                a[mt][3] = As[(r0 + 8) * ROWSTR + k0 + tig + 4];
            }
#pragma unroll
            for (int nt = 0; nt < 8; nt++) {
                int c0 = wn * 64 + nt * 8 + grp;
                uint32_t b0 = Bs[c0 * ROWSTR + k0 + tig];
                uint32_t b1 = Bs[c0 * ROWSTR + k0 + tig + 4];
                mma_tf32(acc[0][nt], a[0], b0, b1);
                mma_tf32(acc[1][nt], a[1], b0, b1);
            }
        }
        __syncthreads();
    }

#pragma unroll
    for (int mt = 0; mt < 2; mt++) {
        int m0 = mb * 128 + wm * 32 + mt * 16 + grp;
#pragma unroll
        for (int nt = 0; nt < 8; nt++) {
            int n0 = nb * 128 + wn * 64 + nt * 8 + tig * 2;
#pragma unroll
            for (int h = 0; h < 2; h++) {
                int m = m0 + h * 8;
                if (m >= M) continue;
                float v0 = acc[mt][nt][h * 2 + 0];
                float v1 = acc[mt][nt][h * 2 + 1];
                if (mode == 0) {
                    int ti = m / LL, l = m % LL;
                    int which = n0 / Cc;
                    int hd = (n0 % Cc) / DH;
                    int dd = n0 % DH;
                    float* dst = (which == 0) ? g_Q : (which == 1) ? g_K : g_V;
                    *(float2*)(dst + (((size_t)ti * NH + hd) * LL + l) * DH + dd) =
                        make_float2(v0, v1);
                } else {
                    *(float2*)(out + (size_t)m * Nn + n0) =
                        make_float2(v0 + bias[n0], v1 + bias[n0 + 1]);
                }
            }
        }
    }
}

// ---------------- 3) fused attention, 512 threads, register-P ----------------
// 16 warps: wm=wid&3 -> 16 q-rows each (64-row q-tile), wn=wid>>2 -> 72-key slice.
// P kept in registers; C-frag -> A-frag via warp shuffles. Partial O combined in smem.
constexpr int PADL  = 288;     // keys padded to 4*72
constexpr int K_STR = 68;
constexpr int V_STR = 72;
constexpr int O_STR = 68;
constexpr int F_VS   = PADL * K_STR;            // 19584
constexpr int F_QS   = F_VS + PADL * V_STR;     // 40320
constexpr int F_OB0  = F_QS + 64 * K_STR;       // 44672
constexpr int F_OB1  = F_OB0 + 64 * O_STR;      // 49024
constexpr int F_RMAX = F_OB1 + 64 * O_STR;      // 53376
constexpr int F_RSUM = F_RMAX + 256;            // 53632
constexpr int F_MSK  = F_RSUM + 256;            // 53888
constexpr int SMEM_ATT = (F_MSK + PADL) * 4;    // 216704 bytes

__global__ __launch_bounds__(512, 1) void k_attn_fused(const int* __restrict__ q_mask) {
    extern __shared__ float sm[];
    float* Ks = sm;
    float* Vs = sm + F_VS;
    float* Qs = sm + F_QS;
    float* Ob0 = sm + F_OB0;
    float* Ob1 = sm + F_OB1;
    float* rmax = sm + F_RMAX;   // [64][4]
    float* rsum = sm + F_RSUM;   // [64][4]
    float* msk  = sm + F_MSK;    // [288]

    int z  = blockIdx.x;
    int iB = z / NH;
    int hd = z % NH;
    int bq = iB % Bb;
    const float* Qg = g_Q + (size_t)z * LL * DH;
    const float* Kg = g_K + (size_t)z * LL * DH;
    const float* Vg = g_V + (size_t)z * LL * DH;

    int tid = threadIdx.x, wid = tid >> 5, lane = tid & 31;
    int grp = lane >> 2, tig = lane & 3;
    int wm = wid & 3, wn = wid >> 2;       // wm: row group, wn: key slice
    int lr0 = wm * 16 + grp, lr1 = lr0 + 8;

    for (int j = tid; j < PADL; j += 512) {
        float m = 0.f;
        if (j >= NWIN)
            m = (j < LL && q_mask[bq * NQ + j - NWIN] != 0) ? 0.f : -1e30f;
        msk[j] = m;
    }
    for (int idx = tid; idx < LL * 16; idx += 512) {
        int r = idx >> 4, c = idx & 15;
        float4 kv = *(const float4*)(Kg + r * DH + c * 4);
        float4 vv = *(const float4*)(Vg + r * DH + c * 4);
        float* kd = Ks + r * K_STR + c * 4;
        kd[0] = tf32r(kv.x); kd[1] = tf32r(kv.y); kd[2] = tf32r(kv.z); kd[3] = tf32r(kv.w);
        float* vd = Vs + r * V_STR + c * 4;
        vd[0] = tf32r(vv.x); vd[1] = tf32r(vv.y); vd[2] = tf32r(vv.z); vd[3] = tf32r(vv.w);
    }
    for (int idx = tid; idx < (PADL - LL) * 16; idx += 512) {
        int r = LL + (idx >> 4), c = idx & 15;
        *(float4*)(Ks + r * K_STR + c * 4) = make_float4(0, 0, 0, 0);
        *(float4*)(Vs + r * V_STR + c * 4) = make_float4(0, 0, 0, 0);
    }

    const uint32_t* Ku = (const uint32_t*)Ks;
    const uint32_t* Vu = (const uint32_t*)Vs;
    const uint32_t* Qu = (const uint32_t*)Qs;

    for (int qt = 0; qt < 5; qt++) {
        int qbase = qt * 64;
        __syncthreads();   // K/V ready (qt=0); prev tile fully consumed (qt>0)

        for (int idx = tid; idx < 64 * 16; idx += 512) {
            int r = idx >> 4, c = idx & 15;
            int gr = qbase + r; if (gr >= LL) gr = 0;
            float4 qv = *(const float4*)(Qg + gr * DH + c * 4);
            float* qd = Qs + r * K_STR + c * 4;
            qd[0] = tf32r(qv.x); qd[1] = tf32r(qv.y);
            qd[2] = tf32r(qv.z); qd[3] = tf32r(qv.w);
        }
        __syncthreads();

        // ---- S = Q @ K^T : warp covers 16 rows x 72 keys ----
        float sf[9][4];
#pragma unroll
        for (int t = 0; t < 9; t++)
#pragma unroll
            for (int k = 0; k < 4; k++) sf[t][k] = 0.f;
#pragma unroll
        for (int ks = 0; ks < 8; ks++) {
            int k0 = ks * 8;
            uint32_t a[4];
            a[0] = Qu[lr0 * K_STR + k0 + tig];
            a[1] = Qu[lr1 * K_STR + k0 + tig];
            a[2] = Qu[lr0 * K_STR + k0 + tig + 4];
            a[3] = Qu[lr1 * K_STR + k0 + tig + 4];
#pragma unroll
            for (int t = 0; t < 9; t++) {
                int n0 = wn * 72 + t * 8 + grp;
                mma_tf32(sf[t], a, Ku[n0 * K_STR + k0 + tig],
                                  Ku[n0 * K_STR + k0 + tig + 4]);
            }
        }

        // ---- scale + mask + rowmax ----
        float mx0 = -3e38f, mx1 = -3e38f;
#pragma unroll
        for (int t = 0; t < 9; t++) {
            int jb = wn * 72 + t * 8 + 2 * tig;
            float m0 = msk[jb], m1 = msk[jb + 1];
            sf[t][0] = sf[t][0] * 0.125f + m0;
            sf[t][1] = sf[t][1] * 0.125f + m1;
            sf[t][2] = sf[t][2] * 0.125f + m0;
            sf[t][3] = sf[t][3] * 0.125f + m1;
            mx0 = fmaxf(mx0, fmaxf(sf[t][0], sf[t][1]));
            mx1 = fmaxf(mx1, fmaxf(sf[t][2], sf[t][3]));
        }
        mx0 = fmaxf(mx0, __shfl_xor_sync(~0u, mx0, 1));
        mx0 = fmaxf(mx0, __shfl_xor_sync(~0u, mx0, 2));
        mx1 = fmaxf(mx1, __shfl_xor_sync(~0u, mx1, 1));
        mx1 = fmaxf(mx1, __shfl_xor_sync(~0u, mx1, 2));
        if (tig == 0) {
            rmax[lr0 * 4 + wn] = mx0;
            rmax[lr1 * 4 + wn] = mx1;
        }
        __syncthreads();
        float4 r40 = *(float4*)(rmax + lr0 * 4);
        float4 r41 = *(float4*)(rmax + lr1 * 4);
        float M0 = fmaxf(fmaxf(r40.x, r40.y), fmaxf(r40.z, r40.w));
        float M1 = fmaxf(fmaxf(r41.x, r41.y), fmaxf(r41.z, r41.w));

        // ---- exp (P stays in registers, tf32-rounded) + row sums ----
        float s0 = 0.f, s1 = 0.f;
#pragma unroll
        for (int t = 0; t < 9; t++) {
            float e0 = __expf(sf[t][0] - M0), e1 = __expf(sf[t][1] - M0);
            float e2 = __expf(sf[t][2] - M1), e3 = __expf(sf[t][3] - M1);
            s0 += e0 + e1; s1 += e2 + e3;
            sf[t][0] = tf32r(e0); sf[t][1] = tf32r(e1);
            sf[t][2] = tf32r(e2); sf[t][3] = tf32r(e3);
        }
        s0 += __shfl_xor_sync(~0u, s0, 1);
        s0 += __shfl_xor_sync(~0u, s0, 2);
        s1 += __shfl_xor_sync(~0u, s1, 1);
        s1 += __shfl_xor_sync(~0u, s1, 2);
        if (tig == 0) {
            rsum[lr0 * 4 + wn] = s0;
            rsum[lr1 * 4 + wn] = s1;
        }

        // ---- O_partial = P @ V over this warp's 72 keys (A-frag via shuffles) ----
        float of[8][4];
#pragma unroll
        for (int nt = 0; nt < 8; nt++)
#pragma unroll
            for (int k = 0; k < 4; k++) of[nt][k] = 0.f;
        int s0l = (grp << 2) + (tig >> 1);
        int s1l = s0l + 2;
#pragma unroll
        for (int kt = 0; kt < 9; kt++) {
            float v00 = __shfl_sync(~0u, sf[kt][0], s0l);
            float v01 = __shfl_sync(~0u, sf[kt][1], s0l);
            float v10 = __shfl_sync(~0u, sf[kt][0], s1l);
            float v11 = __shfl_sync(~0u, sf[kt][1], s1l);
            float w00 = __shfl_sync(~0u, sf[kt][2], s0l);
            float w01 = __shfl_sync(~0u, sf[kt][3], s0l);
            float w10 = __shfl_sync(~0u, sf[kt][2], s1l);
            float w11 = __shfl_sync(~0u, sf[kt][3], s1l);
            uint32_t a[4];
            a[0] = __float_as_uint((tig & 1) ? v01 : v00);
            a[1] = __float_as_uint((tig & 1) ? w01 : w00);
            a[2] = __float_as_uint((tig & 1) ? v11 : v10);
            a[3] = __float_as_uint((tig & 1) ? w11 : w10);
            int kb = wn * 72 + kt * 8;
#pragma unroll
            for (int nt = 0; nt < 8; nt++) {
                int n0 = nt * 8 + grp;
                mma_tf32(of[nt], a, Vu[(kb + tig) * V_STR + n0],
                                    Vu[(kb + tig + 4) * V_STR + n0]);
            }
        }

        // ---- combine 4 key-slices: wn0/wn1 store, wn2/wn3 add, all merge ----
        if (wn < 2) {
            float* Ob = (wn == 0) ? Ob0 : Ob1;
#pragma unroll
            for (int nt = 0; nt < 8; nt++) {
                int c = nt * 8 + 2 * tig;
                *(float2*)(Ob + lr0 * O_STR + c) = make_float2(of[nt][0], of[nt][1]);
                *(float2*)(Ob + lr1 * O_STR + c) = make_float2(of[nt][2], of[nt][3]);
            }
        }
        __syncthreads();
        if (wn >= 2) {
            float* Ob = (wn == 2) ? Ob0 : Ob1;
#pragma unroll
            for (int nt = 0; nt < 8; nt++) {
                int c = nt * 8 + 2 * tig;
                float2 p0 = *(float2*)(Ob + lr0 * O_STR + c);
                float2 p1 = *(float2*)(Ob + lr1 * O_STR + c);
                *(float2*)(Ob + lr0 * O_STR + c) =
                    make_float2(p0.x + of[nt][0], p0.y + of[nt][1]);
                *(float2*)(Ob + lr1 * O_STR + c) =
                    make_float2(p1.x + of[nt][2], p1.y + of[nt][3]);
            }
        }
        __syncthreads();

        // ---- final merge + normalize + write (all 512 threads) ----
        {
            int r = tid >> 3;
            int c0 = (tid & 7) * 8;
            int grow = qbase + r;
            if (grow < LL) {
                float4 s4 = *(float4*)(rsum + r * 4);
                float inv = 1.f / (s4.x + s4.y + s4.z + s4.w);
                float4 x0 = *(float4*)(Ob0 + r * O_STR + c0);
                float4 x1 = *(float4*)(Ob1 + r * O_STR + c0);
                float4 y0 = *(float4*)(Ob0 + r * O_STR + c0 + 4);
                float4 y1 = *(float4*)(Ob1 + r * O_STR + c0 + 4);
                float* dst = g_O + ((size_t)iB * LL + grow) * Cc + hd * DH + c0;
                *(float4*)dst = make_float4((x0.x + x1.x) * inv, (x0.y + x1.y) * inv,
                                            (x0.z + x1.z) * inv, (x0.w + x1.w) * inv);
                *(float4*)(dst + 4) = make_float4((y0.x + y1.x) * inv, (y0.y + y1.y) * inv,
                                                  (y0.z + y1.z) * inv, (y0.w + y1.w) * inv);
            }
        }
    }
}

// ---------------- 6a) ctx rows for pixels ----------------
__global__ __launch_bounds__(256) void k_ctx_pix() {
    int idx = blockIdx.x * blockDim.x + threadIdx.x;
    if (idx >= Bb * NTOK * (Cc / 4)) return;
    int j  = idx / (Cc / 4);
    int c4 = idx % (Cc / 4);
    int b = j / NTOK, p = j % NTOK;
    int py = p / WW, px = p % WW;
    int wy = py / WSZ, iy = py % WSZ;
    int wx = px / WSZ, ix = px % WSZ;
    int i = b * R_ + wy * NWX + wx;
    int l = iy * WSZ + ix;
    float4 v = ((const float4*)(g_O + ((size_t)i * LL + l) * Cc))[c4];
    v.x = tf32r(v.x); v.y = tf32r(v.y); v.z = tf32r(v.z); v.w = tf32r(v.w);
    ((float4*)(g_ctx + (size_t)j * Cc))[c4] = v;
}

// ---------------- 6b) ctx rows for queries (mean over windows) --------------
__global__ __launch_bounds__(256) void k_ctx_q() {
    int idx = blockIdx.x * blockDim.x + threadIdx.x;
    if (idx >= Bb * NQ * (Cc / 4)) return;
    int j  = idx / (Cc / 4);
    int c4 = idx % (Cc / 4);
    int b = j / NQ, lq = j % NQ;
    float4 acc = make_float4(0, 0, 0, 0);
#pragma unroll
    for (int w = 0; w < R_; w++) {
        int i = w * Bb + b;
        float4 v = ((const float4*)(g_O + ((size_t)i * LL + NWIN + lq) * Cc))[c4];
        acc.x += v.x; acc.y += v.y; acc.z += v.z; acc.w += v.w;
    }
    const float inv = 1.f / (float)R_;
    acc.x = tf32r(acc.x * inv); acc.y = tf32r(acc.y * inv);
    acc.z = tf32r(acc.z * inv); acc.w = tf32r(acc.w * inv);
    ((float4*)(g_ctx + (size_t)(Bb * NTOK + j) * Cc))[c4] = acc;
}

// ---------------- launch ----------------
extern "C" void kernel_launch(void* const* d_in, const int* in_sizes, int n_in,
                              void* d_out, int out_size) {
    const float* x     = (const float*)d_in[0];
    const float* q     = (const float*)d_in[1];
    const float* W_in  = (const float*)d_in[2];
    const float* W_out = (const float*)d_in[3];
    const float* b_out = (const float*)d_in[4];
    const int*   qmask = (const int*)d_in[5];
    float* out = (float*)d_out;

    static bool attr_set = false;
    if (!attr_set) {
        cudaFuncSetAttribute(k_gemm_mma, cudaFuncAttributeMaxDynamicSharedMemorySize,
                             SMEM_GEMM);
        cudaFuncSetAttribute(k_attn_fused, cudaFuncAttributeMaxDynamicSharedMemorySize,
                             SMEM_ATT);
        attr_set = true;
    }

    k_cvt_w<<<(4 * Cc * Cc + 255) / 256, 256>>>(W_in, W_out);
    k_gather_tok<<<(TOKROWS * (Cc / 4) + 255) / 256, 256>>>(x, q);

    dim3 g_qkv(3 * Cc / 128, (TOKROWS + 127) / 128);
    k_gemm_mma<<<g_qkv, 256, SMEM_GEMM>>>(nullptr, nullptr, TOKROWS, 3 * Cc, 0);

    k_attn_fused<<<BW * NH, 512, SMEM_ATT>>>(qmask);

    k_ctx_pix<<<(Bb * NTOK * (Cc / 4) + 255) / 256, 256>>>();
    k_ctx_q<<<(Bb * NQ * (Cc / 4) + 255) / 256, 256>>>();

    dim3 g_out(Cc / 128, CTXROWS / 128);
    k_gemm_mma<<<g_out, 256, SMEM_GEMM>>>(b_out, out, CTXROWS, Cc, 1);
}

// round 8
// speedup vs baseline: 2.6890x; 1.0026x over previous
#include <cuda_runtime.h>
#include <cstdint>

// ---------------- problem constants ----------------
constexpr int Bb   = 4;
constexpr int NTOK = 4096;
constexpr int Cc   = 768;
constexpr int NQ   = 64;
constexpr int HH   = 64, WW = 64;
constexpr int WSZ  = 14;
constexpr int NH   = 12, DH = 64;
constexpr int NWX  = 5;
constexpr int R_   = 25;
constexpr int BW   = Bb * R_;           // 100
constexpr int NWIN = WSZ * WSZ;         // 196
constexpr int LL   = NWIN + NQ;         // 260
constexpr int TOKROWS = BW * LL;        // 26000
constexpr int CTXROWS = Bb * NTOK + Bb * NQ; // 16640

// ---------------- scratch ----------------
__device__ float g_tok[(size_t)TOKROWS * Cc];
__device__ float g_Q[(size_t)BW * NH * LL * DH];
__device__ float g_K[(size_t)BW * NH * LL * DH];
__device__ float g_V[(size_t)BW * NH * LL * DH];
__device__ float g_O[(size_t)TOKROWS * Cc];
__device__ float g_ctx[(size_t)CTXROWS * Cc];
__device__ float g_Wt[(size_t)(3 * Cc) * Cc];
__device__ float g_Wot[(size_t)Cc * Cc];

// ---------------- helpers ----------------
__device__ __forceinline__ float tf32r(float x) {
    uint32_t y;
    asm("cvt.rna.tf32.f32 %0, %1;" : "=r"(y) : "f"(x));
    return __uint_as_float(y);
}
__device__ __forceinline__ uint32_t smem_u32(const void* p) {
    uint32_t a;
    asm("{ .reg .u64 t; cvta.to.shared.u64 t, %1; cvt.u32.u64 %0, t; }"
        : "=r"(a) : "l"(p));
    return a;
}
__device__ __forceinline__ void cp16(uint32_t s, const void* g) {
    asm volatile("cp.async.cg.shared.global [%0], [%1], 16;" :: "r"(s), "l"(g) : "memory");
}
__device__ __forceinline__ void mma_tf32(float* c, const uint32_t* a,
                                         uint32_t b0, uint32_t b1) {
    asm volatile("mma.sync.aligned.m16n8k8.row.col.f32.tf32.tf32.f32 "
                 "{%0,%1,%2,%3}, {%4,%5,%6,%7}, {%8,%9}, {%0,%1,%2,%3};"
                 : "+f"(c[0]), "+f"(c[1]), "+f"(c[2]), "+f"(c[3])
                 : "r"(a[0]), "r"(a[1]), "r"(a[2]), "r"(a[3]), "r"(b0), "r"(b1));
}

// ---------------- 0) tf32-round weights ----------------
__global__ __launch_bounds__(256) void k_cvt_w(const float* __restrict__ Win,
                                               const float* __restrict__ Wout) {
    int idx = blockIdx.x * blockDim.x + threadIdx.x;
    const int N1 = 3 * Cc * Cc;
    const int N2 = Cc * Cc;
    if (idx < N1) g_Wt[idx] = tf32r(Win[idx]);
    else if (idx < N1 + N2) g_Wot[idx - N1] = tf32r(Wout[idx - N1]);
}

// ---------------- 1) gather tokens (tf32-rounded) ----------------
__global__ __launch_bounds__(256) void k_gather_tok(const float* __restrict__ x,
                                                    const float* __restrict__ q) {
    int idx = blockIdx.x * blockDim.x + threadIdx.x;
    if (idx >= TOKROWS * (Cc / 4)) return;
    int t  = idx / (Cc / 4);
    int c4 = idx % (Cc / 4);
    int i = t / LL, l = t % LL;
    float4 val = make_float4(0.f, 0.f, 0.f, 0.f);
    if (l < NWIN) {
        int b = i / R_, w = i % R_;
        int wy = w / NWX, wx = w % NWX;
        int py = wy * WSZ + l / WSZ;
        int px = wx * WSZ + l % WSZ;
        if (py < HH && px < WW)
            val = ((const float4*)(x + ((size_t)b * NTOK + py * WW + px) * Cc))[c4];
    } else {
        int bq = i % Bb;
        int lq = l - NWIN;
        val = ((const float4*)(q + ((size_t)bq * NQ + lq) * Cc))[c4];
    }
    val.x = tf32r(val.x); val.y = tf32r(val.y);
    val.z = tf32r(val.z); val.w = tf32r(val.w);
    ((float4*)(g_tok + (size_t)t * Cc))[c4] = val;
}

// ---------------- 2) tf32 mma.sync GEMM (NT), 3-stage cp.async ----------------
constexpr int ROWSTR = 36;
constexpr int TILEB  = 128 * ROWSTR * 4;   // 18432 bytes
constexpr int NSTAGE = 3;
constexpr int SMEM_GEMM = 2 * NSTAGE * TILEB;  // 110592 bytes -> 2 CTAs/SM

__global__ __launch_bounds__(256, 2) void k_gemm_mma(const float* __restrict__ bias,
                                                     float* __restrict__ out,
                                                     int M, int Nn, int mode) {
    extern __shared__ float smf[];
    uint32_t sb = smem_u32(smf);
    const float* A  = (mode == 0) ? g_tok : g_ctx;
    const float* Bw = (mode == 0) ? g_Wt  : g_Wot;
    int tid = threadIdx.x, wid = tid >> 5, lane = tid & 31;
    int grp = lane >> 2, tig = lane & 3;
    int wm = wid & 3, wn = wid >> 2;
    int mb = blockIdx.y, nb = blockIdx.x;

    float acc[2][8][4];
#pragma unroll
    for (int i = 0; i < 2; i++)
#pragma unroll
        for (int j = 0; j < 8; j++)
#pragma unroll
            for (int k = 0; k < 4; k++) acc[i][j][k] = 0.f;

    auto copy_tile = [&](int kc, int buf) {
        uint32_t sa  = sb + buf * TILEB;
        uint32_t sbm = sb + NSTAGE * TILEB + buf * TILEB;
#pragma unroll
        for (int i = 0; i < 4; i++) {
            int idx = tid * 4 + i;
            int r = idx >> 3, c4 = idx & 7;
            int gm = mb * 128 + r;
            if (gm >= M) gm = M - 1;
            cp16(sa + (r * ROWSTR + c4 * 4) * 4, A + (size_t)gm * Cc + kc + c4 * 4);
            int gn = nb * 128 + r;
            cp16(sbm + (r * ROWSTR + c4 * 4) * 4, Bw + (size_t)gn * Cc + kc + c4 * 4);
        }
        asm volatile("cp.async.commit_group;" ::: "memory");
    };

    const int NCH = Cc / 32;   // 24
    copy_tile(0, 0);
    copy_tile(32, 1);

    int buf = 0;
    for (int ci = 0; ci < NCH; ci++) {
        if (ci < NCH - 1)
            asm volatile("cp.async.wait_group 1;" ::: "memory");
        else
            asm volatile("cp.async.wait_group 0;" ::: "memory");
        __syncthreads();
        if (ci + 2 < NCH) {
            int nbuf = buf + 2; if (nbuf >= NSTAGE) nbuf -= NSTAGE;
            copy_tile((ci + 2) * 32, nbuf);
        }

        const uint32_t* As = (const uint32_t*)(smf + buf * (TILEB / 4));
        const uint32_t* Bs = (const uint32_t*)(smf + NSTAGE * (TILEB / 4) + buf * (TILEB / 4));
#pragma unroll
        for (int ks = 0; ks < 4; ks++) {
            int k0 = ks * 8;
            uint32_t a[2][4];
#pragma unroll
            for (int mt = 0; mt < 2; mt++) {
                int r0 = wm * 32 + mt * 16 + grp;
                a[mt][0] = As[r0 * ROWSTR + k0 + tig];
                a[mt][1] = As[(r0 + 8) * ROWSTR + k0 + tig];
                a[mt][2] = As[r0 * ROWSTR + k0 + tig + 4];
                a[mt][3] = As[(r0 + 8) * ROWSTR + k0 + tig + 4];
            }
#pragma unroll
            for (int nt = 0; nt < 8; nt++) {
                int c0 = wn * 64 + nt * 8 + grp;
                uint32_t b0 = Bs[c0 * ROWSTR + k0 + tig];
                uint32_t b1 = Bs[c0 * ROWSTR + k0 + tig + 4];
                mma_tf32(acc[0][nt], a[0], b0, b1);
                mma_tf32(acc[1][nt], a[1], b0, b1);
            }
        }
        buf++; if (buf >= NSTAGE) buf = 0;
        __syncthreads();
    }

#pragma unroll
    for (int mt = 0; mt < 2; mt++) {
        int m0 = mb * 128 + wm * 32 + mt * 16 + grp;
#pragma unroll
        for (int nt = 0; nt < 8; nt++) {
            int n0 = nb * 128 + wn * 64 + nt * 8 + tig * 2;
#pragma unroll
            for (int h = 0; h < 2; h++) {
                int m = m0 + h * 8;
                if (m >= M) continue;
                float v0 = acc[mt][nt][h * 2 + 0];
                float v1 = acc[mt][nt][h * 2 + 1];
                if (mode == 0) {
                    int ti = m / LL, l = m % LL;
                    int which = n0 / Cc;
                    int hd = (n0 % Cc) / DH;
                    int dd = n0 % DH;
                    float* dst = (which == 0) ? g_Q : (which == 1) ? g_K : g_V;
                    *(float2*)(dst + (((size_t)ti * NH + hd) * LL + l) * DH + dd) =
                        make_float2(v0, v1);
                } else {
                    *(float2*)(out + (size_t)m * Nn + n0) =
                        make_float2(v0 + bias[n0], v1 + bias[n0 + 1]);
                }
            }
        }
    }
}

// ---------------- 3) fused attention, 512 threads, register-P ----------------
constexpr int PADL  = 288;
constexpr int K_STR = 68;
constexpr int V_STR = 72;
constexpr int O_STR = 68;
constexpr int F_VS   = PADL * K_STR;
constexpr int F_QS   = F_VS + PADL * V_STR;
constexpr int F_OB0  = F_QS + 64 * K_STR;
constexpr int F_OB1  = F_OB0 + 64 * O_STR;
constexpr int F_RMAX = F_OB1 + 64 * O_STR;
constexpr int F_RSUM = F_RMAX + 256;
constexpr int F_MSK  = F_RSUM + 256;
constexpr int SMEM_ATT = (F_MSK + PADL) * 4;

__global__ __launch_bounds__(512, 1) void k_attn_fused(const int* __restrict__ q_mask) {
    extern __shared__ float sm[];
    float* Ks = sm;
    float* Vs = sm + F_VS;
    float* Qs = sm + F_QS;
    float* Ob0 = sm + F_OB0;
    float* Ob1 = sm + F_OB1;
    float* rmax = sm + F_RMAX;
    float* rsum = sm + F_RSUM;
    float* msk  = sm + F_MSK;

    int z  = blockIdx.x;
    int iB = z / NH;
    int hd = z % NH;
    int bq = iB % Bb;
    const float* Qg = g_Q + (size_t)z * LL * DH;
    const float* Kg = g_K + (size_t)z * LL * DH;
    const float* Vg = g_V + (size_t)z * LL * DH;

    int tid = threadIdx.x, wid = tid >> 5, lane = tid & 31;
    int grp = lane >> 2, tig = lane & 3;
    int wm = wid & 3, wn = wid >> 2;
    int lr0 = wm * 16 + grp, lr1 = lr0 + 8;

    for (int j = tid; j < PADL; j += 512) {
        float m = 0.f;
        if (j >= NWIN)
            m = (j < LL && q_mask[bq * NQ + j - NWIN] != 0) ? 0.f : -1e30f;
        msk[j] = m;
    }
    for (int idx = tid; idx < LL * 16; idx += 512) {
        int r = idx >> 4, c = idx & 15;
        float4 kv = *(const float4*)(Kg + r * DH + c * 4);
        float4 vv = *(const float4*)(Vg + r * DH + c * 4);
        float* kd = Ks + r * K_STR + c * 4;
        kd[0] = tf32r(kv.x); kd[1] = tf32r(kv.y); kd[2] = tf32r(kv.z); kd[3] = tf32r(kv.w);
        float* vd = Vs + r * V_STR + c * 4;
        vd[0] = tf32r(vv.x); vd[1] = tf32r(vv.y); vd[2] = tf32r(vv.z); vd[3] = tf32r(vv.w);
    }
    for (int idx = tid; idx < (PADL - LL) * 16; idx += 512) {
        int r = LL + (idx >> 4), c = idx & 15;
        *(float4*)(Ks + r * K_STR + c * 4) = make_float4(0, 0, 0, 0);
        *(float4*)(Vs + r * V_STR + c * 4) = make_float4(0, 0, 0, 0);
    }

    const uint32_t* Ku = (const uint32_t*)Ks;
    const uint32_t* Vu = (const uint32_t*)Vs;
    const uint32_t* Qu = (const uint32_t*)Qs;

    for (int qt = 0; qt < 5; qt++) {
        int qbase = qt * 64;
        __syncthreads();

        for (int idx = tid; idx < 64 * 16; idx += 512) {
            int r = idx >> 4, c = idx & 15;
            int gr = qbase + r; if (gr >= LL) gr = 0;
            float4 qv = *(const float4*)(Qg + gr * DH + c * 4);
            float* qd = Qs + r * K_STR + c * 4;
            qd[0] = tf32r(qv.x); qd[1] = tf32r(qv.y);
            qd[2] = tf32r(qv.z); qd[3] = tf32r(qv.w);
        }
        __syncthreads();

        float sf[9][4];
#pragma unroll
        for (int t = 0; t < 9; t++)
#pragma unroll
            for (int k = 0; k < 4; k++) sf[t][k] = 0.f;
#pragma unroll
        for (int ks = 0; ks < 8; ks++) {
            int k0 = ks * 8;
            uint32_t a[4];
            a[0] = Qu[lr0 * K_STR + k0 + tig];
            a[1] = Qu[lr1 * K_STR + k0 + tig];
            a[2] = Qu[lr0 * K_STR + k0 + tig + 4];
            a[3] = Qu[lr1 * K_STR + k0 + tig + 4];
#pragma unroll
            for (int t = 0; t < 9; t++) {
                int n0 = wn * 72 + t * 8 + grp;
                mma_tf32(sf[t], a, Ku[n0 * K_STR + k0 + tig],
                                  Ku[n0 * K_STR + k0 + tig + 4]);
            }
        }

        float mx0 = -3e38f, mx1 = -3e38f;
#pragma unroll
        for (int t = 0; t < 9; t++) {
            int jb = wn * 72 + t * 8 + 2 * tig;
            float m0 = msk[jb], m1 = msk[jb + 1];
            sf[t][0] = sf[t][0] * 0.125f + m0;
            sf[t][1] = sf[t][1] * 0.125f + m1;
            sf[t][2] = sf[t][2] * 0.125f + m0;
            sf[t][3] = sf[t][3] * 0.125f + m1;
            mx0 = fmaxf(mx0, fmaxf(sf[t][0], sf[t][1]));
            mx1 = fmaxf(mx1, fmaxf(sf[t][2], sf[t][3]));
        }
        mx0 = fmaxf(mx0, __shfl_xor_sync(~0u, mx0, 1));
        mx0 = fmaxf(mx0, __shfl_xor_sync(~0u, mx0, 2));
        mx1 = fmaxf(mx1, __shfl_xor_sync(~0u, mx1, 1));
        mx1 = fmaxf(mx1, __shfl_xor_sync(~0u, mx1, 2));
        if (tig == 0) {
            rmax[lr0 * 4 + wn] = mx0;
            rmax[lr1 * 4 + wn] = mx1;
        }
        __syncthreads();
        float4 r40 = *(float4*)(rmax + lr0 * 4);
        float4 r41 = *(float4*)(rmax + lr1 * 4);
        float M0 = fmaxf(fmaxf(r40.x, r40.y), fmaxf(r40.z, r40.w));
        float M1 = fmaxf(fmaxf(r41.x, r41.y), fmaxf(r41.z, r41.w));

        float s0 = 0.f, s1 = 0.f;
#pragma unroll
        for (int t = 0; t < 9; t++) {
            float e0 = __expf(sf[t][0] - M0), e1 = __expf(sf[t][1] - M0);
            float e2 = __expf(sf[t][2] - M1), e3 = __expf(sf[t][3] - M1);
            s0 += e0 + e1; s1 += e2 + e3;
            sf[t][0] = tf32r(e0); sf[t][1] = tf32r(e1);
            sf[t][2] = tf32r(e2); sf[t][3] = tf32r(e3);
        }
        s0 += __shfl_xor_sync(~0u, s0, 1);
        s0 += __shfl_xor_sync(~0u, s0, 2);
        s1 += __shfl_xor_sync(~0u, s1, 1);
        s1 += __shfl_xor_sync(~0u, s1, 2);
        if (tig == 0) {
            rsum[lr0 * 4 + wn] = s0;
            rsum[lr1 * 4 + wn] = s1;
        }

        float of[8][4];
#pragma unroll
        for (int nt = 0; nt < 8; nt++)
#pragma unroll
            for (int k = 0; k < 4; k++) of[nt][k] = 0.f;
        int s0l = (grp << 2) + (tig >> 1);
        int s1l = s0l + 2;
#pragma unroll
        for (int kt = 0; kt < 9; kt++) {
            float v00 = __shfl_sync(~0u, sf[kt][0], s0l);
            float v01 = __shfl_sync(~0u, sf[kt][1], s0l);
            float v10 = __shfl_sync(~0u, sf[kt][0], s1l);
            float v11 = __shfl_sync(~0u, sf[kt][1], s1l);
            float w00 = __shfl_sync(~0u, sf[kt][2], s0l);
            float w01 = __shfl_sync(~0u, sf[kt][3], s0l);
            float w10 = __shfl_sync(~0u, sf[kt][2], s1l);
            float w11 = __shfl_sync(~0u, sf[kt][3], s1l);
            uint32_t a[4];
            a[0] = __float_as_uint((tig & 1) ? v01 : v00);
            a[1] = __float_as_uint((tig & 1) ? w01 : w00);
            a[2] = __float_as_uint((tig & 1) ? v11 : v10);
            a[3] = __float_as_uint((tig & 1) ? w11 : w10);
            int kb = wn * 72 + kt * 8;
#pragma unroll
            for (int nt = 0; nt < 8; nt++) {
                int n0 = nt * 8 + grp;
                mma_tf32(of[nt], a, Vu[(kb + tig) * V_STR + n0],
                                    Vu[(kb + tig + 4) * V_STR + n0]);
            }
        }

        if (wn < 2) {
            float* Ob = (wn == 0) ? Ob0 : Ob1;
#pragma unroll
            for (int nt = 0; nt < 8; nt++) {
                int c = nt * 8 + 2 * tig;
                *(float2*)(Ob + lr0 * O_STR + c) = make_float2(of[nt][0], of[nt][1]);
                *(float2*)(Ob + lr1 * O_STR + c) = make_float2(of[nt][2], of[nt][3]);
            }
        }
        __syncthreads();
        if (wn >= 2) {
            float* Ob = (wn == 2) ? Ob0 : Ob1;
#pragma unroll
            for (int nt = 0; nt < 8; nt++) {
                int c = nt * 8 + 2 * tig;
                float2 p0 = *(float2*)(Ob + lr0 * O_STR + c);
                float2 p1 = *(float2*)(Ob + lr1 * O_STR + c);
                *(float2*)(Ob + lr0 * O_STR + c) =
                    make_float2(p0.x + of[nt][0], p0.y + of[nt][1]);
                *(float2*)(Ob + lr1 * O_STR + c) =
                    make_float2(p1.x + of[nt][2], p1.y + of[nt][3]);
            }
        }
        __syncthreads();

        {
            int r = tid >> 3;
            int c0 = (tid & 7) * 8;
            int grow = qbase + r;
            if (grow < LL) {
                float4 s4 = *(float4*)(rsum + r * 4);
                float inv = 1.f / (s4.x + s4.y + s4.z + s4.w);
                float4 x0 = *(float4*)(Ob0 + r * O_STR + c0);
                float4 x1 = *(float4*)(Ob1 + r * O_STR + c0);
                float4 y0 = *(float4*)(Ob0 + r * O_STR + c0 + 4);
                float4 y1 = *(float4*)(Ob1 + r * O_STR + c0 + 4);
                float* dst = g_O + ((size_t)iB * LL + grow) * Cc + hd * DH + c0;
                *(float4*)dst = make_float4((x0.x + x1.x) * inv, (x0.y + x1.y) * inv,
                                            (x0.z + x1.z) * inv, (x0.w + x1.w) * inv);
                *(float4*)(dst + 4) = make_float4((y0.x + y1.x) * inv, (y0.y + y1.y) * inv,
                                                  (y0.z + y1.z) * inv, (y0.w + y1.w) * inv);
            }
        }
    }
}

// ---------------- 6a) ctx rows for pixels ----------------
__global__ __launch_bounds__(256) void k_ctx_pix() {
    int idx = blockIdx.x * blockDim.x + threadIdx.x;
    if (idx >= Bb * NTOK * (Cc / 4)) return;
    int j  = idx / (Cc / 4);
    int c4 = idx % (Cc / 4);
    int b = j / NTOK, p = j % NTOK;
    int py = p / WW, px = p % WW;
    int wy = py / WSZ, iy = py % WSZ;
    int wx = px / WSZ, ix = px % WSZ;
    int i = b * R_ + wy * NWX + wx;
    int l = iy * WSZ + ix;
    float4 v = ((const float4*)(g_O + ((size_t)i * LL + l) * Cc))[c4];
    v.x = tf32r(v.x); v.y = tf32r(v.y); v.z = tf32r(v.z); v.w = tf32r(v.w);
    ((float4*)(g_ctx + (size_t)j * Cc))[c4] = v;
}

// ---------------- 6b) ctx rows for queries (mean over windows) --------------
__global__ __launch_bounds__(256) void k_ctx_q() {
    int idx = blockIdx.x * blockDim.x + threadIdx.x;
    if (idx >= Bb * NQ * (Cc / 4)) return;
    int j  = idx / (Cc / 4);
    int c4 = idx % (Cc / 4);
    int b = j / NQ, lq = j % NQ;
    float4 acc = make_float4(0, 0, 0, 0);
#pragma unroll
    for (int w = 0; w < R_; w++) {
        int i = w * Bb + b;
        float4 v = ((const float4*)(g_O + ((size_t)i * LL + NWIN + lq) * Cc))[c4];
        acc.x += v.x; acc.y += v.y; acc.z += v.z; acc.w += v.w;
    }
    const float inv = 1.f / (float)R_;
    acc.x = tf32r(acc.x * inv); acc.y = tf32r(acc.y * inv);
    acc.z = tf32r(acc.z * inv); acc.w = tf32r(acc.w * inv);
    ((float4*)(g_ctx + (size_t)(Bb * NTOK + j) * Cc))[c4] = acc;
}

// ---------------- launch ----------------
extern "C" void kernel_launch(void* const* d_in, const int* in_sizes, int n_in,
                              void* d_out, int out_size) {
    const float* x     = (const float*)d_in[0];
    const float* q     = (const float*)d_in[1];
    const float* W_in  = (const float*)d_in[2];
    const float* W_out = (const float*)d_in[3];
    const float* b_out = (const float*)d_in[4];
    const int*   qmask = (const int*)d_in[5];
    float* out = (float*)d_out;

    static bool attr_set = false;
    if (!attr_set) {
        cudaFuncSetAttribute(k_gemm_mma, cudaFuncAttributeMaxDynamicSharedMemorySize,
                             SMEM_GEMM);
        cudaFuncSetAttribute(k_attn_fused, cudaFuncAttributeMaxDynamicSharedMemorySize,
                             SMEM_ATT);
        attr_set = true;
    }

    k_cvt_w<<<(4 * Cc * Cc + 255) / 256, 256>>>(W_in, W_out);
    k_gather_tok<<<(TOKROWS * (Cc / 4) + 255) / 256, 256>>>(x, q);

    dim3 g_qkv(3 * Cc / 128, (TOKROWS + 127) / 128);
    k_gemm_mma<<<g_qkv, 256, SMEM_GEMM>>>(nullptr, nullptr, TOKROWS, 3 * Cc, 0);

    k_attn_fused<<<BW * NH, 512, SMEM_ATT>>>(qmask);

    k_ctx_pix<<<(Bb * NTOK * (Cc / 4) + 255) / 256, 256>>>();
    k_ctx_q<<<(Bb * NQ * (Cc / 4) + 255) / 256, 256>>>();

    dim3 g_out(Cc / 128, CTXROWS / 128);
    k_gemm_mma<<<g_out, 256, SMEM_GEMM>>>(b_out, out, CTXROWS, Cc, 1);
}

// round 9
// speedup vs baseline: 2.8329x; 1.0535x over previous
#include <cuda_runtime.h>
#include <cstdint>

// ---------------- problem constants ----------------
constexpr int Bb   = 4;
constexpr int NTOK = 4096;
constexpr int Cc   = 768;
constexpr int NQ   = 64;
constexpr int HH   = 64, WW = 64;
constexpr int WSZ  = 14;
constexpr int NH   = 12, DH = 64;
constexpr int NWX  = 5;
constexpr int R_   = 25;
constexpr int BW   = Bb * R_;           // 100
constexpr int NWIN = WSZ * WSZ;         // 196
constexpr int LL   = NWIN + NQ;         // 260
constexpr int TOKROWS = BW * LL;        // 26000
constexpr int CTXROWS = Bb * NTOK + Bb * NQ; // 16640

// ---------------- scratch ----------------
__device__ float g_tok[(size_t)TOKROWS * Cc];
__device__ float g_Q[(size_t)BW * NH * LL * DH];
__device__ float g_K[(size_t)BW * NH * LL * DH];
__device__ float g_V[(size_t)BW * NH * LL * DH];
__device__ float g_O[(size_t)TOKROWS * Cc];
__device__ float g_ctx[(size_t)CTXROWS * Cc];
__device__ float g_Wt[(size_t)(3 * Cc) * Cc];
__device__ float g_Wot[(size_t)Cc * Cc];

// ---------------- helpers ----------------
__device__ __forceinline__ float tf32r(float x) {
    uint32_t y;
    asm("cvt.rna.tf32.f32 %0, %1;" : "=r"(y) : "f"(x));
    return __uint_as_float(y);
}
__device__ __forceinline__ uint32_t smem_u32(const void* p) {
    uint32_t a;
    asm("{ .reg .u64 t; cvta.to.shared.u64 t, %1; cvt.u32.u64 %0, t; }"
        : "=r"(a) : "l"(p));
    return a;
}
__device__ __forceinline__ void cp16(uint32_t s, const void* g) {
    asm volatile("cp.async.cg.shared.global [%0], [%1], 16;" :: "r"(s), "l"(g) : "memory");
}
__device__ __forceinline__ void mma_tf32(float* c, const uint32_t* a,
                                         uint32_t b0, uint32_t b1) {
    asm volatile("mma.sync.aligned.m16n8k8.row.col.f32.tf32.tf32.f32 "
                 "{%0,%1,%2,%3}, {%4,%5,%6,%7}, {%8,%9}, {%0,%1,%2,%3};"
                 : "+f"(c[0]), "+f"(c[1]), "+f"(c[2]), "+f"(c[3])
                 : "r"(a[0]), "r"(a[1]), "r"(a[2]), "r"(a[3]), "r"(b0), "r"(b1));
}
__device__ __forceinline__ void ldsm_x4(uint32_t* r, uint32_t addr) {
    asm volatile("ldmatrix.sync.aligned.m8n8.x4.shared.b16 {%0,%1,%2,%3}, [%4];"
                 : "=r"(r[0]), "=r"(r[1]), "=r"(r[2]), "=r"(r[3]) : "r"(addr));
}

// ---------------- 0) tf32-round weights ----------------
__global__ __launch_bounds__(256) void k_cvt_w(const float* __restrict__ Win,
                                               const float* __restrict__ Wout) {
    int idx = blockIdx.x * blockDim.x + threadIdx.x;
    const int N1 = 3 * Cc * Cc;
    const int N2 = Cc * Cc;
    if (idx < N1) g_Wt[idx] = tf32r(Win[idx]);
    else if (idx < N1 + N2) g_Wot[idx - N1] = tf32r(Wout[idx - N1]);
}

// ---------------- 1) gather tokens (tf32-rounded) ----------------
__global__ __launch_bounds__(256) void k_gather_tok(const float* __restrict__ x,
                                                    const float* __restrict__ q) {
    int idx = blockIdx.x * blockDim.x + threadIdx.x;
    if (idx >= TOKROWS * (Cc / 4)) return;
    int t  = idx / (Cc / 4);
    int c4 = idx % (Cc / 4);
    int i = t / LL, l = t % LL;
    float4 val = make_float4(0.f, 0.f, 0.f, 0.f);
    if (l < NWIN) {
        int b = i / R_, w = i % R_;
        int wy = w / NWX, wx = w % NWX;
        int py = wy * WSZ + l / WSZ;
        int px = wx * WSZ + l % WSZ;
        if (py < HH && px < WW)
            val = ((const float4*)(x + ((size_t)b * NTOK + py * WW + px) * Cc))[c4];
    } else {
        int bq = i % Bb;
        int lq = l - NWIN;
        val = ((const float4*)(q + ((size_t)bq * NQ + lq) * Cc))[c4];
    }
    val.x = tf32r(val.x); val.y = tf32r(val.y);
    val.z = tf32r(val.z); val.w = tf32r(val.w);
    ((float4*)(g_tok + (size_t)t * Cc))[c4] = val;
}

// ---------------- 2) tf32 mma.sync GEMM (NT), 3-stage + ldmatrix ------------
constexpr int ROWSTR = 36;
constexpr int TILEB  = 128 * ROWSTR * 4;   // 18432 bytes
constexpr int NSTAGE = 3;
constexpr int SMEM_GEMM = 2 * NSTAGE * TILEB;  // 110592 bytes -> 2 CTAs/SM

__global__ __launch_bounds__(256, 2) void k_gemm_mma(const float* __restrict__ bias,
                                                     float* __restrict__ out,
                                                     int M, int Nn, int mode) {
    extern __shared__ float smf[];
    uint32_t sb = smem_u32(smf);
    const float* A  = (mode == 0) ? g_tok : g_ctx;
    const float* Bw = (mode == 0) ? g_Wt  : g_Wot;
    int tid = threadIdx.x, wid = tid >> 5, lane = tid & 31;
    int grp = lane >> 2, tig = lane & 3;
    int wm = wid & 3, wn = wid >> 2;
    int mb = blockIdx.y, nb = blockIdx.x;

    // ldmatrix lane addressing: matrix id m8 = lane>>3, row r8 = lane&7
    int m8 = lane >> 3, r8 = lane & 7;
    // A x4: matrices = {rows +0, rows +8} x {k-half 0, k-half 1}
    uint32_t aoff = (uint32_t)((wm * 32 + (m8 & 1) * 8 + r8) * ROWSTR * 4 + (m8 >> 1) * 16);
    // B x4: matrices = {n-block +0, n-block +8} x {k-half 0, k-half 1}
    uint32_t boff = (uint32_t)((wn * 64 + (m8 >> 1) * 8 + r8) * ROWSTR * 4 + (m8 & 1) * 16);

    float acc[2][8][4];
#pragma unroll
    for (int i = 0; i < 2; i++)
#pragma unroll
        for (int j = 0; j < 8; j++)
#pragma unroll
            for (int k = 0; k < 4; k++) acc[i][j][k] = 0.f;

    auto copy_tile = [&](int kc, int buf) {
        uint32_t sa  = sb + buf * TILEB;
        uint32_t sbm = sb + NSTAGE * TILEB + buf * TILEB;
#pragma unroll
        for (int i = 0; i < 4; i++) {
            int idx = tid * 4 + i;
            int r = idx >> 3, c4 = idx & 7;
            int gm = mb * 128 + r;
            if (gm >= M) gm = M - 1;
            cp16(sa + (r * ROWSTR + c4 * 4) * 4, A + (size_t)gm * Cc + kc + c4 * 4);
            int gn = nb * 128 + r;
            cp16(sbm + (r * ROWSTR + c4 * 4) * 4, Bw + (size_t)gn * Cc + kc + c4 * 4);
        }
        asm volatile("cp.async.commit_group;" ::: "memory");
    };

    const int NCH = Cc / 32;   // 24
    copy_tile(0, 0);
    copy_tile(32, 1);

    int buf = 0;
    for (int ci = 0; ci < NCH; ci++) {
        if (ci < NCH - 1)
            asm volatile("cp.async.wait_group 1;" ::: "memory");
        else
            asm volatile("cp.async.wait_group 0;" ::: "memory");
        __syncthreads();
        if (ci + 2 < NCH) {
            int nbuf = buf + 2; if (nbuf >= NSTAGE) nbuf -= NSTAGE;
            copy_tile((ci + 2) * 32, nbuf);
        }

        uint32_t sa  = sb + buf * TILEB + aoff;
        uint32_t sbm = sb + NSTAGE * TILEB + buf * TILEB + boff;
#pragma unroll
        for (int ks = 0; ks < 4; ks++) {
            uint32_t a[2][4];
            ldsm_x4(a[0], sa + ks * 32);
            ldsm_x4(a[1], sa + ks * 32 + 16 * ROWSTR * 4);
            uint32_t bf[4][4];
#pragma unroll
            for (int p = 0; p < 4; p++)
                ldsm_x4(bf[p], sbm + ks * 32 + p * (16 * ROWSTR * 4));
#pragma unroll
            for (int p = 0; p < 4; p++)
#pragma unroll
                for (int j = 0; j < 2; j++) {
                    int nt = p * 2 + j;
                    mma_tf32(acc[0][nt], a[0], bf[p][2 * j], bf[p][2 * j + 1]);
                    mma_tf32(acc[1][nt], a[1], bf[p][2 * j], bf[p][2 * j + 1]);
                }
        }
        buf++; if (buf >= NSTAGE) buf = 0;
    }

#pragma unroll
    for (int mt = 0; mt < 2; mt++) {
        int m0 = mb * 128 + wm * 32 + mt * 16 + grp;
#pragma unroll
        for (int nt = 0; nt < 8; nt++) {
            int n0 = nb * 128 + wn * 64 + nt * 8 + tig * 2;
#pragma unroll
            for (int h = 0; h < 2; h++) {
                int m = m0 + h * 8;
                if (m >= M) continue;
                float v0 = acc[mt][nt][h * 2 + 0];
                float v1 = acc[mt][nt][h * 2 + 1];
                if (mode == 0) {
                    int ti = m / LL, l = m % LL;
                    int which = n0 / Cc;
                    int hd = (n0 % Cc) / DH;
                    int dd = n0 % DH;
                    float* dst = (which == 0) ? g_Q : (which == 1) ? g_K : g_V;
                    *(float2*)(dst + (((size_t)ti * NH + hd) * LL + l) * DH + dd) =
                        make_float2(v0, v1);
                } else {
                    *(float2*)(out + (size_t)m * Nn + n0) =
                        make_float2(v0 + bias[n0], v1 + bias[n0 + 1]);
                }
            }
        }
    }
}

// ---------------- 3) fused attention, 512 threads, register-P ----------------
constexpr int PADL  = 288;
constexpr int K_STR = 68;
constexpr int V_STR = 72;
constexpr int O_STR = 68;
constexpr int F_VS   = PADL * K_STR;
constexpr int F_QS   = F_VS + PADL * V_STR;
constexpr int F_OB0  = F_QS + 64 * K_STR;
constexpr int F_OB1  = F_OB0 + 64 * O_STR;
constexpr int F_RMAX = F_OB1 + 64 * O_STR;
constexpr int F_RSUM = F_RMAX + 256;
constexpr int F_MSK  = F_RSUM + 256;
constexpr int SMEM_ATT = (F_MSK + PADL) * 4;

__global__ __launch_bounds__(512, 1) void k_attn_fused(const int* __restrict__ q_mask) {
    extern __shared__ float sm[];
    float* Ks = sm;
    float* Vs = sm + F_VS;
    float* Qs = sm + F_QS;
    float* Ob0 = sm + F_OB0;
    float* Ob1 = sm + F_OB1;
    float* rmax = sm + F_RMAX;
    float* rsum = sm + F_RSUM;
    float* msk  = sm + F_MSK;

    int z  = blockIdx.x;
    int iB = z / NH;
    int hd = z % NH;
    int bq = iB % Bb;
    const float* Qg = g_Q + (size_t)z * LL * DH;
    const float* Kg = g_K + (size_t)z * LL * DH;
    const float* Vg = g_V + (size_t)z * LL * DH;

    int tid = threadIdx.x, wid = tid >> 5, lane = tid & 31;
    int grp = lane >> 2, tig = lane & 3;
    int wm = wid & 3, wn = wid >> 2;
    int lr0 = wm * 16 + grp, lr1 = lr0 + 8;

    for (int j = tid; j < PADL; j += 512) {
        float m = 0.f;
        if (j >= NWIN)
            m = (j < LL && q_mask[bq * NQ + j - NWIN] != 0) ? 0.f : -1e30f;
        msk[j] = m;
    }
    for (int idx = tid; idx < LL * 16; idx += 512) {
        int r = idx >> 4, c = idx & 15;
        float4 kv = *(const float4*)(Kg + r * DH + c * 4);
        float4 vv = *(const float4*)(Vg + r * DH + c * 4);
        float* kd = Ks + r * K_STR + c * 4;
        kd[0] = tf32r(kv.x); kd[1] = tf32r(kv.y); kd[2] = tf32r(kv.z); kd[3] = tf32r(kv.w);
        float* vd = Vs + r * V_STR + c * 4;
        vd[0] = tf32r(vv.x); vd[1] = tf32r(vv.y); vd[2] = tf32r(vv.z); vd[3] = tf32r(vv.w);
    }
    for (int idx = tid; idx < (PADL - LL) * 16; idx += 512) {
        int r = LL + (idx >> 4), c = idx & 15;
        *(float4*)(Ks + r * K_STR + c * 4) = make_float4(0, 0, 0, 0);
        *(float4*)(Vs + r * V_STR + c * 4) = make_float4(0, 0, 0, 0);
    }

    const uint32_t* Ku = (const uint32_t*)Ks;
    const uint32_t* Vu = (const uint32_t*)Vs;
    const uint32_t* Qu = (const uint32_t*)Qs;

    for (int qt = 0; qt < 5; qt++) {
        int qbase = qt * 64;
        __syncthreads();

        for (int idx = tid; idx < 64 * 16; idx += 512) {
            int r = idx >> 4, c = idx & 15;
            int gr = qbase + r; if (gr >= LL) gr = 0;
            float4 qv = *(const float4*)(Qg + gr * DH + c * 4);
            float* qd = Qs + r * K_STR + c * 4;
            qd[0] = tf32r(qv.x); qd[1] = tf32r(qv.y);
            qd[2] = tf32r(qv.z); qd[3] = tf32r(qv.w);
        }
        __syncthreads();

        float sf[9][4];
#pragma unroll
        for (int t = 0; t < 9; t++)
#pragma unroll
            for (int k = 0; k < 4; k++) sf[t][k] = 0.f;
#pragma unroll
        for (int ks = 0; ks < 8; ks++) {
            int k0 = ks * 8;
            uint32_t a[4];
            a[0] = Qu[lr0 * K_STR + k0 + tig];
            a[1] = Qu[lr1 * K_STR + k0 + tig];
            a[2] = Qu[lr0 * K_STR + k0 + tig + 4];
            a[3] = Qu[lr1 * K_STR + k0 + tig + 4];
#pragma unroll
            for (int t = 0; t < 9; t++) {
                int n0 = wn * 72 + t * 8 + grp;
                mma_tf32(sf[t], a, Ku[n0 * K_STR + k0 + tig],
                                  Ku[n0 * K_STR + k0 + tig + 4]);
            }
        }

        float mx0 = -3e38f, mx1 = -3e38f;
#pragma unroll
        for (int t = 0; t < 9; t++) {
            int jb = wn * 72 + t * 8 + 2 * tig;
            float m0 = msk[jb], m1 = msk[jb + 1];
            sf[t][0] = sf[t][0] * 0.125f + m0;
            sf[t][1] = sf[t][1] * 0.125f + m1;
            sf[t][2] = sf[t][2] * 0.125f + m0;
            sf[t][3] = sf[t][3] * 0.125f + m1;
            mx0 = fmaxf(mx0, fmaxf(sf[t][0], sf[t][1]));
            mx1 = fmaxf(mx1, fmaxf(sf[t][2], sf[t][3]));
        }
        mx0 = fmaxf(mx0, __shfl_xor_sync(~0u, mx0, 1));
        mx0 = fmaxf(mx0, __shfl_xor_sync(~0u, mx0, 2));
        mx1 = fmaxf(mx1, __shfl_xor_sync(~0u, mx1, 1));
        mx1 = fmaxf(mx1, __shfl_xor_sync(~0u, mx1, 2));
        if (tig == 0) {
            rmax[lr0 * 4 + wn] = mx0;
            rmax[lr1 * 4 + wn] = mx1;
        }
        __syncthreads();
        float4 r40 = *(float4*)(rmax + lr0 * 4);
        float4 r41 = *(float4*)(rmax + lr1 * 4);
        float M0 = fmaxf(fmaxf(r40.x, r40.y), fmaxf(r40.z, r40.w));
        float M1 = fmaxf(fmaxf(r41.x, r41.y), fmaxf(r41.z, r41.w));

        float s0 = 0.f, s1 = 0.f;
#pragma unroll
        for (int t = 0; t < 9; t++) {
            float e0 = __expf(sf[t][0] - M0), e1 = __expf(sf[t][1] - M0);
            float e2 = __expf(sf[t][2] - M1), e3 = __expf(sf[t][3] - M1);
            s0 += e0 + e1; s1 += e2 + e3;
            sf[t][0] = tf32r(e0); sf[t][1] = tf32r(e1);
            sf[t][2] = tf32r(e2); sf[t][3] = tf32r(e3);
        }
        s0 += __shfl_xor_sync(~0u, s0, 1);
        s0 += __shfl_xor_sync(~0u, s0, 2);
        s1 += __shfl_xor_sync(~0u, s1, 1);
        s1 += __shfl_xor_sync(~0u, s1, 2);
        if (tig == 0) {
            rsum[lr0 * 4 + wn] = s0;
            rsum[lr1 * 4 + wn] = s1;
        }

        float of[8][4];
#pragma unroll
        for (int nt = 0; nt < 8; nt++)
#pragma unroll
            for (int k = 0; k < 4; k++) of[nt][k] = 0.f;
        int s0l = (grp << 2) + (tig >> 1);
        int s1l = s0l + 2;
#pragma unroll
        for (int kt = 0; kt < 9; kt++) {
            float v00 = __shfl_sync(~0u, sf[kt][0], s0l);
            float v01 = __shfl_sync(~0u, sf[kt][1], s0l);
            float v10 = __shfl_sync(~0u, sf[kt][0], s1l);
            float v11 = __shfl_sync(~0u, sf[kt][1], s1l);
            float w00 = __shfl_sync(~0u, sf[kt][2], s0l);
            float w01 = __shfl_sync(~0u, sf[kt][3], s0l);
            float w10 = __shfl_sync(~0u, sf[kt][2], s1l);
            float w11 = __shfl_sync(~0u, sf[kt][3], s1l);
            uint32_t a[4];
            a[0] = __float_as_uint((tig & 1) ? v01 : v00);
            a[1] = __float_as_uint((tig & 1) ? w01 : w00);
            a[2] = __float_as_uint((tig & 1) ? v11 : v10);
            a[3] = __float_as_uint((tig & 1) ? w11 : w10);
            int kb = wn * 72 + kt * 8;
#pragma unroll
            for (int nt = 0; nt < 8; nt++) {
                int n0 = nt * 8 + grp;
                mma_tf32(of[nt], a, Vu[(kb + tig) * V_STR + n0],
                                    Vu[(kb + tig + 4) * V_STR + n0]);
            }
        }

        if (wn < 2) {
            float* Ob = (wn == 0) ? Ob0 : Ob1;
#pragma unroll
            for (int nt = 0; nt < 8; nt++) {
                int c = nt * 8 + 2 * tig;
                *(float2*)(Ob + lr0 * O_STR + c) = make_float2(of[nt][0], of[nt][1]);
                *(float2*)(Ob + lr1 * O_STR + c) = make_float2(of[nt][2], of[nt][3]);
            }
        }
        __syncthreads();
        if (wn >= 2) {
            float* Ob = (wn == 2) ? Ob0 : Ob1;
#pragma unroll
            for (int nt = 0; nt < 8; nt++) {
                int c = nt * 8 + 2 * tig;
                float2 p0 = *(float2*)(Ob + lr0 * O_STR + c);
                float2 p1 = *(float2*)(Ob + lr1 * O_STR + c);
                *(float2*)(Ob + lr0 * O_STR + c) =
                    make_float2(p0.x + of[nt][0], p0.y + of[nt][1]);
                *(float2*)(Ob + lr1 * O_STR + c) =
                    make_float2(p1.x + of[nt][2], p1.y + of[nt][3]);
            }
        }
        __syncthreads();

        {
            int r = tid >> 3;
            int c0 = (tid & 7) * 8;
            int grow = qbase + r;
            if (grow < LL) {
                float4 s4 = *(float4*)(rsum + r * 4);
                float inv = 1.f / (s4.x + s4.y + s4.z + s4.w);
                float4 x0 = *(float4*)(Ob0 + r * O_STR + c0);
                float4 x1 = *(float4*)(Ob1 + r * O_STR + c0);
                float4 y0 = *(float4*)(Ob0 + r * O_STR + c0 + 4);
                float4 y1 = *(float4*)(Ob1 + r * O_STR + c0 + 4);
                float* dst = g_O + ((size_t)iB * LL + grow) * Cc + hd * DH + c0;
                *(float4*)dst = make_float4((x0.x + x1.x) * inv, (x0.y + x1.y) * inv,
                                            (x0.z + x1.z) * inv, (x0.w + x1.w) * inv);
                *(float4*)(dst + 4) = make_float4((y0.x + y1.x) * inv, (y0.y + y1.y) * inv,
                                                  (y0.z + y1.z) * inv, (y0.w + y1.w) * inv);
            }
        }
    }
}

// ---------------- 6a) ctx rows for pixels ----------------
__global__ __launch_bounds__(256) void k_ctx_pix() {
    int idx = blockIdx.x * blockDim.x + threadIdx.x;
    if (idx >= Bb * NTOK * (Cc / 4)) return;
    int j  = idx / (Cc / 4);
    int c4 = idx % (Cc / 4);
    int b = j / NTOK, p = j % NTOK;
    int py = p / WW, px = p % WW;
    int wy = py / WSZ, iy = py % WSZ;
    int wx = px / WSZ, ix = px % WSZ;
    int i = b * R_ + wy * NWX + wx;
    int l = iy * WSZ + ix;
    float4 v = ((const float4*)(g_O + ((size_t)i * LL + l) * Cc))[c4];
    v.x = tf32r(v.x); v.y = tf32r(v.y); v.z = tf32r(v.z); v.w = tf32r(v.w);
    ((float4*)(g_ctx + (size_t)j * Cc))[c4] = v;
}

// ---------------- 6b) ctx rows for queries (mean over windows) --------------
__global__ __launch_bounds__(256) void k_ctx_q() {
    int idx = blockIdx.x * blockDim.x + threadIdx.x;
    if (idx >= Bb * NQ * (Cc / 4)) return;
    int j  = idx / (Cc / 4);
    int c4 = idx % (Cc / 4);
    int b = j / NQ, lq = j % NQ;
    float4 acc = make_float4(0, 0, 0, 0);
#pragma unroll
    for (int w = 0; w < R_; w++) {
        int i = w * Bb + b;
        float4 v = ((const float4*)(g_O + ((size_t)i * LL + NWIN + lq) * Cc))[c4];
        acc.x += v.x; acc.y += v.y; acc.z += v.z; acc.w += v.w;
    }
    const float inv = 1.f / (float)R_;
    acc.x = tf32r(acc.x * inv); acc.y = tf32r(acc.y * inv);
    acc.z = tf32r(acc.z * inv); acc.w = tf32r(acc.w * inv);
    ((float4*)(g_ctx + (size_t)(Bb * NTOK + j) * Cc))[c4] = acc;
}

// ---------------- launch ----------------
extern "C" void kernel_launch(void* const* d_in, const int* in_sizes, int n_in,
                              void* d_out, int out_size) {
    const float* x     = (const float*)d_in[0];
    const float* q     = (const float*)d_in[1];
    const float* W_in  = (const float*)d_in[2];
    const float* W_out = (const float*)d_in[3];
    const float* b_out = (const float*)d_in[4];
    const int*   qmask = (const int*)d_in[5];
    float* out = (float*)d_out;

    static bool attr_set = false;
    if (!attr_set) {
        cudaFuncSetAttribute(k_gemm_mma, cudaFuncAttributeMaxDynamicSharedMemorySize,
                             SMEM_GEMM);
        cudaFuncSetAttribute(k_attn_fused, cudaFuncAttributeMaxDynamicSharedMemorySize,
                             SMEM_ATT);
        attr_set = true;
    }

    k_cvt_w<<<(4 * Cc * Cc + 255) / 256, 256>>>(W_in, W_out);
    k_gather_tok<<<(TOKROWS * (Cc / 4) + 255) / 256, 256>>>(x, q);

    dim3 g_qkv(3 * Cc / 128, (TOKROWS + 127) / 128);
    k_gemm_mma<<<g_qkv, 256, SMEM_GEMM>>>(nullptr, nullptr, TOKROWS, 3 * Cc, 0);

    k_attn_fused<<<BW * NH, 512, SMEM_ATT>>>(qmask);

    k_ctx_pix<<<(Bb * NTOK * (Cc / 4) + 255) / 256, 256>>>();
    k_ctx_q<<<(Bb * NQ * (Cc / 4) + 255) / 256, 256>>>();

    dim3 g_out(Cc / 128, CTXROWS / 128);
    k_gemm_mma<<<g_out, 256, SMEM_GEMM>>>(b_out, out, CTXROWS, Cc, 1);
}

// round 10
// speedup vs baseline: 4.6146x; 1.6289x over previous
#include <cuda_runtime.h>
#include <cuda_fp16.h>
#include <cstdint>

// ---------------- problem constants ----------------
constexpr int Bb   = 4;
constexpr int NTOK = 4096;
constexpr int Cc   = 768;
constexpr int NQ   = 64;
constexpr int HH   = 64, WW = 64;
constexpr int WSZ  = 14;
constexpr int NH   = 12, DH = 64;
constexpr int NWX  = 5;
constexpr int R_   = 25;
constexpr int BW   = Bb * R_;           // 100
constexpr int NWIN = WSZ * WSZ;         // 196
constexpr int LL   = NWIN + NQ;         // 260
constexpr int TOKROWS = BW * LL;        // 26000
constexpr int CTXROWS = Bb * NTOK + Bb * NQ; // 16640

// ---------------- scratch (f16 intermediates) ----------------
__device__ __half g_tok[(size_t)TOKROWS * Cc];
__device__ __half g_Q[(size_t)BW * NH * LL * DH];
__device__ __half g_K[(size_t)BW * NH * LL * DH];
__device__ __half g_V[(size_t)BW * NH * LL * DH];
__device__ __half g_O[(size_t)TOKROWS * Cc];
__device__ __half g_ctx[(size_t)CTXROWS * Cc];
__device__ __half g_Wt[(size_t)(3 * Cc) * Cc];
__device__ __half g_Wot[(size_t)Cc * Cc];

// ---------------- helpers ----------------
__device__ __forceinline__ uint32_t smem_u32(const void* p) {
    uint32_t a;
    asm("{ .reg .u64 t; cvta.to.shared.u64 t, %1; cvt.u32.u64 %0, t; }"
        : "=r"(a) : "l"(p));
    return a;
}
__device__ __forceinline__ void cp16(uint32_t s, const void* g) {
    asm volatile("cp.async.cg.shared.global [%0], [%1], 16;" :: "r"(s), "l"(g) : "memory");
}
// f16 mma: m16n8k16, row.col, fp32 accum
__device__ __forceinline__ void mma_f16(float* c, const uint32_t* a,
                                        uint32_t b0, uint32_t b1) {
    asm volatile("mma.sync.aligned.m16n8k16.row.col.f32.f16.f16.f32 "
                 "{%0,%1,%2,%3}, {%4,%5,%6,%7}, {%8,%9}, {%0,%1,%2,%3};"
                 : "+f"(c[0]), "+f"(c[1]), "+f"(c[2]), "+f"(c[3])
                 : "r"(a[0]), "r"(a[1]), "r"(a[2]), "r"(a[3]), "r"(b0), "r"(b1));
}
__device__ __forceinline__ void ldsm_x4(uint32_t* r, uint32_t addr) {
    asm volatile("ldmatrix.sync.aligned.m8n8.x4.shared.b16 {%0,%1,%2,%3}, [%4];"
                 : "=r"(r[0]), "=r"(r[1]), "=r"(r[2]), "=r"(r[3]) : "r"(addr));
}
__device__ __forceinline__ uint32_t pack_h2(float lo, float hi) {
    __half2 h = __floats2half2_rn(lo, hi);
    return *(uint32_t*)&h;
}

// ---------------- 0) convert weights to f16 ----------------
__global__ __launch_bounds__(256) void k_cvt_w(const float* __restrict__ Win,
                                               const float* __restrict__ Wout) {
    int idx = blockIdx.x * blockDim.x + threadIdx.x;
    const int N1 = 3 * Cc * Cc;
    const int N2 = Cc * Cc;
    if (idx < N1) g_Wt[idx] = __float2half_rn(Win[idx]);
    else if (idx < N1 + N2) g_Wot[idx - N1] = __float2half_rn(Wout[idx - N1]);
}

// ---------------- 1) gather tokens -> f16 ----------------
__global__ __launch_bounds__(256) void k_gather_tok(const float* __restrict__ x,
                                                    const float* __restrict__ q) {
    int idx = blockIdx.x * blockDim.x + threadIdx.x;
    if (idx >= TOKROWS * (Cc / 4)) return;
    int t  = idx / (Cc / 4);
    int c4 = idx % (Cc / 4);
    int i = t / LL, l = t % LL;
    float4 val = make_float4(0.f, 0.f, 0.f, 0.f);
    if (l < NWIN) {
        int b = i / R_, w = i % R_;
        int wy = w / NWX, wx = w % NWX;
        int py = wy * WSZ + l / WSZ;
        int px = wx * WSZ + l % WSZ;
        if (py < HH && px < WW)
            val = ((const float4*)(x + ((size_t)b * NTOK + py * WW + px) * Cc))[c4];
    } else {
        int bq = i % Bb;
        int lq = l - NWIN;
        val = ((const float4*)(q + ((size_t)bq * NQ + lq) * Cc))[c4];
    }
    __half2 h0 = __floats2half2_rn(val.x, val.y);
    __half2 h1 = __floats2half2_rn(val.z, val.w);
    __half2* dst = (__half2*)(g_tok + (size_t)t * Cc + c4 * 4);
    dst[0] = h0; dst[1] = h1;
}

// ---------------- 2) f16 mma.sync GEMM (NT), 3-stage + ldmatrix -------------
// K-chunk = 64 halves (128 B/row); row stride 72 halves (144 B) -> conflict-free
constexpr int RSH    = 72;                 // halves per smem row
constexpr int TILEB  = 128 * RSH * 2;      // 18432 bytes
constexpr int NSTAGE = 3;
constexpr int SMEM_GEMM = 2 * NSTAGE * TILEB;  // 110592 -> 2 CTAs/SM

__global__ __launch_bounds__(256, 2) void k_gemm_mma(const float* __restrict__ bias,
                                                     float* __restrict__ out,
                                                     int M, int Nn, int mode) {
    extern __shared__ char smc[];
    uint32_t sb = smem_u32(smc);
    const __half* A  = (mode == 0) ? g_tok : g_ctx;
    const __half* Bw = (mode == 0) ? g_Wt  : g_Wot;
    int tid = threadIdx.x, wid = tid >> 5, lane = tid & 31;
    int grp = lane >> 2, tig = lane & 3;
    int wm = wid & 3, wn = wid >> 2;
    int mb = blockIdx.y, nb = blockIdx.x;

    int m8 = lane >> 3, r8 = lane & 7;
    // A x4: {rows+0, rows+8} x {k-half 0, k-half 1}
    uint32_t aoff = (uint32_t)((wm * 32 + (m8 & 1) * 8 + r8) * (RSH * 2) + (m8 >> 1) * 16);
    // B x4: {n-block, n-block+8} x {k-half 0, k-half 1}
    uint32_t boff = (uint32_t)((wn * 64 + (m8 >> 1) * 8 + r8) * (RSH * 2) + (m8 & 1) * 16);

    float acc[2][8][4];
#pragma unroll
    for (int i = 0; i < 2; i++)
#pragma unroll
        for (int j = 0; j < 8; j++)
#pragma unroll
            for (int k = 0; k < 4; k++) acc[i][j][k] = 0.f;

    auto copy_tile = [&](int kc, int buf) {
        uint32_t sa  = sb + buf * TILEB;
        uint32_t sbm = sb + NSTAGE * TILEB + buf * TILEB;
#pragma unroll
        for (int i = 0; i < 4; i++) {
            int idx = tid * 4 + i;
            int r = idx >> 3, c8 = idx & 7;       // 8 segments of 8 halves
            int gm = mb * 128 + r;
            if (gm >= M) gm = M - 1;
            cp16(sa + r * (RSH * 2) + c8 * 16, A + (size_t)gm * Cc + kc + c8 * 8);
            int gn = nb * 128 + r;
            cp16(sbm + r * (RSH * 2) + c8 * 16, Bw + (size_t)gn * Cc + kc + c8 * 8);
        }
        asm volatile("cp.async.commit_group;" ::: "memory");
    };

    const int NCH = Cc / 64;   // 12
    copy_tile(0, 0);
    copy_tile(64, 1);

    int buf = 0;
    for (int ci = 0; ci < NCH; ci++) {
        if (ci < NCH - 1)
            asm volatile("cp.async.wait_group 1;" ::: "memory");
        else
            asm volatile("cp.async.wait_group 0;" ::: "memory");
        __syncthreads();
        if (ci + 2 < NCH) {
            int nbuf = buf + 2; if (nbuf >= NSTAGE) nbuf -= NSTAGE;
            copy_tile((ci + 2) * 64, nbuf);
        }

        uint32_t sa  = sb + buf * TILEB + aoff;
        uint32_t sbm = sb + NSTAGE * TILEB + buf * TILEB + boff;
#pragma unroll
        for (int ks = 0; ks < 4; ks++) {       // 4 x k16
            uint32_t a[2][4];
            ldsm_x4(a[0], sa + ks * 32);
            ldsm_x4(a[1], sa + ks * 32 + 16 * (RSH * 2));
            uint32_t bf[4][4];
#pragma unroll
            for (int p = 0; p < 4; p++)
                ldsm_x4(bf[p], sbm + ks * 32 + p * (16 * (RSH * 2)));
#pragma unroll
            for (int p = 0; p < 4; p++)
#pragma unroll
                for (int j = 0; j < 2; j++) {
                    int nt = p * 2 + j;
                    mma_f16(acc[0][nt], a[0], bf[p][2 * j], bf[p][2 * j + 1]);
                    mma_f16(acc[1][nt], a[1], bf[p][2 * j], bf[p][2 * j + 1]);
                }
        }
        buf++; if (buf >= NSTAGE) buf = 0;
    }

#pragma unroll
    for (int mt = 0; mt < 2; mt++) {
        int m0 = mb * 128 + wm * 32 + mt * 16 + grp;
#pragma unroll
        for (int nt = 0; nt < 8; nt++) {
            int n0 = nb * 128 + wn * 64 + nt * 8 + tig * 2;
#pragma unroll
            for (int h = 0; h < 2; h++) {
                int m = m0 + h * 8;
                if (m >= M) continue;
                float v0 = acc[mt][nt][h * 2 + 0];
                float v1 = acc[mt][nt][h * 2 + 1];
                if (mode == 0) {
                    int ti = m / LL, l = m % LL;
                    int which = n0 / Cc;
                    int hd = (n0 % Cc) / DH;
                    int dd = n0 % DH;
                    __half* dst = (which == 0) ? g_Q : (which == 1) ? g_K : g_V;
                    *(__half2*)(dst + (((size_t)ti * NH + hd) * LL + l) * DH + dd) =
                        __floats2half2_rn(v0, v1);
                } else {
                    *(float2*)(out + (size_t)m * Nn + n0) =
                        make_float2(v0 + bias[n0], v1 + bias[n0 + 1]);
                }
            }
        }
    }
}

// ---------------- 3) fused attention (f16 mma, register P, no shuffles) -----
constexpr int PADL  = 320;       // keys padded: 4 warps x 80
constexpr int KQ_STR = 72;       // halves per K/Q row (conflict-free)
constexpr int VT_STR = 328;      // halves per transposed-V row
constexpr int O_STR  = 68;       // floats per O-combine row
constexpr int H_KS   = 0;
constexpr int H_VS   = PADL * KQ_STR;             // 23040 halves
constexpr int H_QS   = H_VS + 64 * VT_STR;        // 44032
constexpr int H_END  = H_QS + 64 * KQ_STR;        // 48640 halves = 97280 B
constexpr int F_OB0  = (H_END * 2 + 15) / 16 * 4; // float index, 16B aligned
constexpr int F_OB1  = F_OB0 + 64 * O_STR;
constexpr int F_RMAX = F_OB1 + 64 * O_STR;
constexpr int F_RSUM = F_RMAX + 256;
constexpr int F_MSK  = F_RSUM + 256;
constexpr int SMEM_ATT = (F_MSK + PADL) * 4;

__global__ __launch_bounds__(512, 1) void k_attn_fused(const int* __restrict__ q_mask) {
    extern __shared__ char smc[];
    __half* Ks = (__half*)smc;
    __half* Vs = (__half*)smc + H_VS;     // transposed: [dh][key]
    __half* Qs = (__half*)smc + H_QS;
    float* smf = (float*)smc;
    float* Ob0 = smf + F_OB0;
    float* Ob1 = smf + F_OB1;
    float* rmax = smf + F_RMAX;
    float* rsum = smf + F_RSUM;
    float* msk  = smf + F_MSK;

    int z  = blockIdx.x;
    int iB = z / NH;
    int hd = z % NH;
    int bq = iB % Bb;
    const __half* Qg = g_Q + (size_t)z * LL * DH;
    const __half* Kg = g_K + (size_t)z * LL * DH;
    const __half* Vg = g_V + (size_t)z * LL * DH;

    int tid = threadIdx.x, wid = tid >> 5, lane = tid & 31;
    int grp = lane >> 2, tig = lane & 3;
    int wm = wid & 3, wn = wid >> 2;     // wm: 16-row group, wn: 80-key slice
    int lr0 = wm * 16 + grp, lr1 = lr0 + 8;

    for (int j = tid; j < PADL; j += 512) {
        float m = 0.f;
        if (j >= NWIN)
            m = (j < LL && q_mask[bq * NQ + j - NWIN] != 0) ? 0.f : -1e30f;
        msk[j] = m;
    }
    // K: [key][dh] rows of 64 halves (8 x uint4)
    for (int idx = tid; idx < LL * 8; idx += 512) {
        int r = idx >> 3, c = idx & 7;
        *(uint4*)(Ks + r * KQ_STR + c * 8) = ((const uint4*)(Kg + r * DH))[c];
    }
    for (int idx = tid; idx < (PADL - LL) * 8; idx += 512) {   // zero pad K rows
        int r = LL + (idx >> 3), c = idx & 7;
        *(uint4*)(Ks + r * KQ_STR + c * 8) = make_uint4(0, 0, 0, 0);
    }
    // V transposed: Vs[dh][key]
    for (int idx = tid; idx < LL * 32; idx += 512) {
        int key = idx >> 5, dhp = idx & 31;
        __half2 v = ((const __half2*)(Vg + key * DH))[dhp];
        Vs[(2 * dhp) * VT_STR + key]     = __low2half(v);
        Vs[(2 * dhp + 1) * VT_STR + key] = __high2half(v);
    }
    for (int idx = tid; idx < 64 * (PADL - LL); idx += 512) {  // zero pad V keys
        int dh = idx / (PADL - LL), key = LL + idx % (PADL - LL);
        Vs[dh * VT_STR + key] = __float2half(0.f);
    }

    for (int qt = 0; qt < 5; qt++) {
        int qbase = qt * 64;
        __syncthreads();

        for (int idx = tid; idx < 64 * 8; idx += 512) {
            int r = idx >> 3, c = idx & 7;
            int gr = qbase + r; if (gr >= LL) gr = 0;
            *(uint4*)(Qs + r * KQ_STR + c * 8) = ((const uint4*)(Qg + gr * DH))[c];
        }
        __syncthreads();

        // ---- S = Q @ K^T : warp m16 x n80 (10 tiles), k=64 in 4 k16 steps ----
        float sf[10][4];
#pragma unroll
        for (int t = 0; t < 10; t++)
#pragma unroll
            for (int k = 0; k < 4; k++) sf[t][k] = 0.f;
#pragma unroll
        for (int ks = 0; ks < 4; ks++) {
            int k0 = ks * 16;
            uint32_t a[4];
            a[0] = *(const uint32_t*)(Qs + lr0 * KQ_STR + k0 + 2 * tig);
            a[1] = *(const uint32_t*)(Qs + lr1 * KQ_STR + k0 + 2 * tig);
            a[2] = *(const uint32_t*)(Qs + lr0 * KQ_STR + k0 + 8 + 2 * tig);
            a[3] = *(const uint32_t*)(Qs + lr1 * KQ_STR + k0 + 8 + 2 * tig);
#pragma unroll
            for (int t = 0; t < 10; t++) {
                int n0 = wn * 80 + t * 8;
                uint32_t b0 = *(const uint32_t*)(Ks + (n0 + grp) * KQ_STR + k0 + 2 * tig);
                uint32_t b1 = *(const uint32_t*)(Ks + (n0 + grp) * KQ_STR + k0 + 8 + 2 * tig);
                mma_f16(sf[t], a, b0, b1);
            }
        }

        // ---- scale + mask + rowmax ----
        float mx0 = -3e38f, mx1 = -3e38f;
#pragma unroll
        for (int t = 0; t < 10; t++) {
            int jb = wn * 80 + t * 8 + 2 * tig;
            float m0 = msk[jb], m1 = msk[jb + 1];
            sf[t][0] = sf[t][0] * 0.125f + m0;
            sf[t][1] = sf[t][1] * 0.125f + m1;
            sf[t][2] = sf[t][2] * 0.125f + m0;
            sf[t][3] = sf[t][3] * 0.125f + m1;
            mx0 = fmaxf(mx0, fmaxf(sf[t][0], sf[t][1]));
            mx1 = fmaxf(mx1, fmaxf(sf[t][2], sf[t][3]));
        }
        mx0 = fmaxf(mx0, __shfl_xor_sync(~0u, mx0, 1));
        mx0 = fmaxf(mx0, __shfl_xor_sync(~0u, mx0, 2));
        mx1 = fmaxf(mx1, __shfl_xor_sync(~0u, mx1, 1));
        mx1 = fmaxf(mx1, __shfl_xor_sync(~0u, mx1, 2));
        if (tig == 0) {
            rmax[lr0 * 4 + wn] = mx0;
            rmax[lr1 * 4 + wn] = mx1;
        }
        __syncthreads();
        float4 r40 = *(float4*)(rmax + lr0 * 4);
        float4 r41 = *(float4*)(rmax + lr1 * 4);
        float M0 = fmaxf(fmaxf(r40.x, r40.y), fmaxf(r40.z, r40.w));
        float M1 = fmaxf(fmaxf(r41.x, r41.y), fmaxf(r41.z, r41.w));

        // ---- exp + row sums; pack P into half2 A-fragments ----
        float s0 = 0.f, s1 = 0.f;
        uint32_t pk[10][2];
#pragma unroll
        for (int t = 0; t < 10; t++) {
            float e0 = __expf(sf[t][0] - M0), e1 = __expf(sf[t][1] - M0);
            float e2 = __expf(sf[t][2] - M1), e3 = __expf(sf[t][3] - M1);
            s0 += e0 + e1; s1 += e2 + e3;
            pk[t][0] = pack_h2(e0, e1);   // row grp   : keys 2tig,2tig+1 of tile t
            pk[t][1] = pack_h2(e2, e3);   // row grp+8
        }
        s0 += __shfl_xor_sync(~0u, s0, 1);
        s0 += __shfl_xor_sync(~0u, s0, 2);
        s1 += __shfl_xor_sync(~0u, s1, 1);
        s1 += __shfl_xor_sync(~0u, s1, 2);
        if (tig == 0) {
            rsum[lr0 * 4 + wn] = s0;
            rsum[lr1 * 4 + wn] = s1;
        }

        // ---- O_partial = P @ V over 80 keys: 5 k16 steps, zero shuffles ----
        float of[8][4];
#pragma unroll
        for (int nt = 0; nt < 8; nt++)
#pragma unroll
            for (int k = 0; k < 4; k++) of[nt][k] = 0.f;
#pragma unroll
        for (int kt = 0; kt < 5; kt++) {
            uint32_t a[4];
            a[0] = pk[2 * kt][0];
            a[1] = pk[2 * kt][1];
            a[2] = pk[2 * kt + 1][0];
            a[3] = pk[2 * kt + 1][1];
            int kb = wn * 80 + kt * 16;
#pragma unroll
            for (int nt = 0; nt < 8; nt++) {
                int n0 = nt * 8 + grp;
                uint32_t b0 = *(const uint32_t*)(Vs + n0 * VT_STR + kb + 2 * tig);
                uint32_t b1 = *(const uint32_t*)(Vs + n0 * VT_STR + kb + 8 + 2 * tig);
                mma_f16(of[nt], a, b0, b1);
            }
        }

        // ---- combine 4 key-slices ----
        if (wn < 2) {
            float* Ob = (wn == 0) ? Ob0 : Ob1;
#pragma unroll
            for (int nt = 0; nt < 8; nt++) {
                int c = nt * 8 + 2 * tig;
                *(float2*)(Ob + lr0 * O_STR + c) = make_float2(of[nt][0], of[nt][1]);
                *(float2*)(Ob + lr1 * O_STR + c) = make_float2(of[nt][2], of[nt][3]);
            }
        }
        __syncthreads();
        if (wn >= 2) {
            float* Ob = (wn == 2) ? Ob0 : Ob1;
#pragma unroll
            for (int nt = 0; nt < 8; nt++) {
                int c = nt * 8 + 2 * tig;
                float2 p0 = *(float2*)(Ob + lr0 * O_STR + c);
                float2 p1 = *(float2*)(Ob + lr1 * O_STR + c);
                *(float2*)(Ob + lr0 * O_STR + c) =
                    make_float2(p0.x + of[nt][0], p0.y + of[nt][1]);
                *(float2*)(Ob + lr1 * O_STR + c) =
                    make_float2(p1.x + of[nt][2], p1.y + of[nt][3]);
            }
        }
        __syncthreads();

        // ---- final merge + normalize + write f16 ----
        {
            int r = tid >> 3;
            int c0 = (tid & 7) * 8;
            int grow = qbase + r;
            if (grow < LL) {
                float4 s4 = *(float4*)(rsum + r * 4);
                float inv = 1.f / (s4.x + s4.y + s4.z + s4.w);
                float4 x0 = *(float4*)(Ob0 + r * O_STR + c0);
                float4 x1 = *(float4*)(Ob1 + r * O_STR + c0);
                float4 y0 = *(float4*)(Ob0 + r * O_STR + c0 + 4);
                float4 y1 = *(float4*)(Ob1 + r * O_STR + c0 + 4);
                __half2* dst = (__half2*)(g_O + ((size_t)iB * LL + grow) * Cc + hd * DH + c0);
                dst[0] = __floats2half2_rn((x0.x + x1.x) * inv, (x0.y + x1.y) * inv);
                dst[1] = __floats2half2_rn((x0.z + x1.z) * inv, (x0.w + x1.w) * inv);
                dst[2] = __floats2half2_rn((y0.x + y1.x) * inv, (y0.y + y1.y) * inv);
                dst[3] = __floats2half2_rn((y0.z + y1.z) * inv, (y0.w + y1.w) * inv);
            }
        }
    }
}

// ---------------- 6a) ctx rows for pixels (f16 copy) ----------------
__global__ __launch_bounds__(256) void k_ctx_pix() {
    int idx = blockIdx.x * blockDim.x + threadIdx.x;
    const int SEG = Cc / 8;   // 96 uint4 per row
    if (idx >= Bb * NTOK * SEG) return;
    int j = idx / SEG, c = idx % SEG;
    int b = j / NTOK, p = j % NTOK;
    int py = p / WW, px = p % WW;
    int wy = py / WSZ, iy = py % WSZ;
    int wx = px / WSZ, ix = px % WSZ;
    int i = b * R_ + wy * NWX + wx;
    int l = iy * WSZ + ix;
    ((uint4*)(g_ctx + (size_t)j * Cc))[c] =
        ((const uint4*)(g_O + ((size_t)i * LL + l) * Cc))[c];
}

// ---------------- 6b) ctx rows for queries (mean over windows) --------------
__global__ __launch_bounds__(256) void k_ctx_q() {
    int idx = blockIdx.x * blockDim.x + threadIdx.x;
    const int SEG = Cc / 2;   // 384 half2 per row
    if (idx >= Bb * NQ * SEG) return;
    int j = idx / SEG, c = idx % SEG;
    int b = j / NQ, lq = j % NQ;
    float a0 = 0.f, a1 = 0.f;
#pragma unroll
    for (int w = 0; w < R_; w++) {
        int i = w * Bb + b;
        __half2 v = ((const __half2*)(g_O + ((size_t)i * LL + NWIN + lq) * Cc))[c];
        float2 f = __half22float2(v);
        a0 += f.x; a1 += f.y;
    }
    const float inv = 1.f / (float)R_;
    ((__half2*)(g_ctx + (size_t)(Bb * NTOK + j) * Cc))[c] =
        __floats2half2_rn(a0 * inv, a1 * inv);
}

// ---------------- launch ----------------
extern "C" void kernel_launch(void* const* d_in, const int* in_sizes, int n_in,
                              void* d_out, int out_size) {
    const float* x     = (const float*)d_in[0];
    const float* q     = (const float*)d_in[1];
    const float* W_in  = (const float*)d_in[2];
    const float* W_out = (const float*)d_in[3];
    const float* b_out = (const float*)d_in[4];
    const int*   qmask = (const int*)d_in[5];
    float* out = (float*)d_out;

    static bool attr_set = false;
    if (!attr_set) {
        cudaFuncSetAttribute(k_gemm_mma, cudaFuncAttributeMaxDynamicSharedMemorySize,
                             SMEM_GEMM);
        cudaFuncSetAttribute(k_attn_fused, cudaFuncAttributeMaxDynamicSharedMemorySize,
                             SMEM_ATT);
        attr_set = true;
    }

    k_cvt_w<<<(4 * Cc * Cc + 255) / 256, 256>>>(W_in, W_out);
    k_gather_tok<<<(TOKROWS * (Cc / 4) + 255) / 256, 256>>>(x, q);

    dim3 g_qkv(3 * Cc / 128, (TOKROWS + 127) / 128);
    k_gemm_mma<<<g_qkv, 256, SMEM_GEMM>>>(nullptr, nullptr, TOKROWS, 3 * Cc, 0);

    k_attn_fused<<<BW * NH, 512, SMEM_ATT>>>(qmask);

    k_ctx_pix<<<(Bb * NTOK * (Cc / 8) + 255) / 256, 256>>>();
    k_ctx_q<<<(Bb * NQ * (Cc / 2) + 255) / 256, 256>>>();

    dim3 g_out(Cc / 128, CTXROWS / 128);
    k_gemm_mma<<<g_out, 256, SMEM_GEMM>>>(b_out, out, CTXROWS, Cc, 1);
}

// round 11
// speedup vs baseline: 6.0163x; 1.3038x over previous
#include <cuda_runtime.h>
#include <cuda_fp16.h>
#include <cstdint>

// ---------------- problem constants ----------------
constexpr int Bb   = 4;
constexpr int NTOK = 4096;
constexpr int Cc   = 768;
constexpr int NQ   = 64;
constexpr int HH   = 64, WW = 64;
constexpr int WSZ  = 14;
constexpr int NH   = 12, DH = 64;
constexpr int NWX  = 5;
constexpr int R_   = 25;
constexpr int BW   = Bb * R_;           // 100
constexpr int NWIN = WSZ * WSZ;         // 196
constexpr int LL   = NWIN + NQ;         // 260
constexpr int CTXROWS = Bb * NTOK + Bb * NQ; // 16640 (= unique token rows)
constexpr int PROW = NTOK + NQ;         // 4160 rows per (b,head) in QKV store

// ---------------- scratch (f16 intermediates) ----------------
__device__ __half g_tok[(size_t)CTXROWS * Cc];                  // unique tokens
__device__ __half g_Q[(size_t)Bb * NH * PROW * DH];
__device__ __half g_K[(size_t)Bb * NH * PROW * DH];
__device__ __half g_V[(size_t)Bb * NH * PROW * DH];
__device__ __half g_Oq[(size_t)BW * NQ * Cc];                   // per-window query out
__device__ __half g_ctx[(size_t)CTXROWS * Cc];
__device__ __half g_Wt[(size_t)(3 * Cc) * Cc];
__device__ __half g_Wot[(size_t)Cc * Cc];

// ---------------- helpers ----------------
__device__ __forceinline__ uint32_t smem_u32(const void* p) {
    uint32_t a;
    asm("{ .reg .u64 t; cvta.to.shared.u64 t, %1; cvt.u32.u64 %0, t; }"
        : "=r"(a) : "l"(p));
    return a;
}
__device__ __forceinline__ void cp16(uint32_t s, const void* g) {
    asm volatile("cp.async.cg.shared.global [%0], [%1], 16;" :: "r"(s), "l"(g) : "memory");
}
__device__ __forceinline__ void mma_f16(float* c, const uint32_t* a,
                                        uint32_t b0, uint32_t b1) {
    asm volatile("mma.sync.aligned.m16n8k16.row.col.f32.f16.f16.f32 "
                 "{%0,%1,%2,%3}, {%4,%5,%6,%7}, {%8,%9}, {%0,%1,%2,%3};"
                 : "+f"(c[0]), "+f"(c[1]), "+f"(c[2]), "+f"(c[3])
                 : "r"(a[0]), "r"(a[1]), "r"(a[2]), "r"(a[3]), "r"(b0), "r"(b1));
}
__device__ __forceinline__ void ldsm_x4(uint32_t* r, uint32_t addr) {
    asm volatile("ldmatrix.sync.aligned.m8n8.x4.shared.b16 {%0,%1,%2,%3}, [%4];"
                 : "=r"(r[0]), "=r"(r[1]), "=r"(r[2]), "=r"(r[3]) : "r"(addr));
}
__device__ __forceinline__ uint32_t pack_h2(float lo, float hi) {
    __half2 h = __floats2half2_rn(lo, hi);
    return *(uint32_t*)&h;
}

// ---------------- 0) convert weights to f16 ----------------
__global__ __launch_bounds__(256) void k_cvt_w(const float* __restrict__ Win,
                                               const float* __restrict__ Wout) {
    int idx = blockIdx.x * blockDim.x + threadIdx.x;
    const int N1 = 3 * Cc * Cc;
    const int N2 = Cc * Cc;
    if (idx < N1) g_Wt[idx] = __float2half_rn(Win[idx]);
    else if (idx < N1 + N2) g_Wot[idx - N1] = __float2half_rn(Wout[idx - N1]);
}

// ---------------- 1) unique tokens -> f16 (pure convert: x rows then q rows) -
__global__ __launch_bounds__(256) void k_prep(const float* __restrict__ x,
                                              const float* __restrict__ q) {
    int idx = blockIdx.x * blockDim.x + threadIdx.x;
    if (idx >= CTXROWS * (Cc / 4)) return;
    int t  = idx / (Cc / 4);
    int c4 = idx % (Cc / 4);
    float4 val;
    if (t < Bb * NTOK) val = ((const float4*)(x + (size_t)t * Cc))[c4];
    else               val = ((const float4*)(q + (size_t)(t - Bb * NTOK) * Cc))[c4];
    __half2* dst = (__half2*)(g_tok + (size_t)t * Cc + c4 * 4);
    dst[0] = __floats2half2_rn(val.x, val.y);
    dst[1] = __floats2half2_rn(val.z, val.w);
}

// ---------------- 2) f16 mma.sync GEMM (NT), 3-stage + ldmatrix -------------
constexpr int RSH    = 72;
constexpr int TILEB  = 128 * RSH * 2;      // 18432 bytes
constexpr int NSTAGE = 3;
constexpr int SMEM_GEMM = 2 * NSTAGE * TILEB;  // 110592 -> 2 CTAs/SM

__global__ __launch_bounds__(256, 2) void k_gemm_mma(const float* __restrict__ bias,
                                                     float* __restrict__ out,
                                                     int M, int Nn, int mode) {
    extern __shared__ char smc[];
    uint32_t sb = smem_u32(smc);
    const __half* A  = (mode == 0) ? g_tok : g_ctx;
    const __half* Bw = (mode == 0) ? g_Wt  : g_Wot;
    int tid = threadIdx.x, wid = tid >> 5, lane = tid & 31;
    int grp = lane >> 2, tig = lane & 3;
    int wm = wid & 3, wn = wid >> 2;
    int mb = blockIdx.y, nb = blockIdx.x;

    int m8 = lane >> 3, r8 = lane & 7;
    uint32_t aoff = (uint32_t)((wm * 32 + (m8 & 1) * 8 + r8) * (RSH * 2) + (m8 >> 1) * 16);
    uint32_t boff = (uint32_t)((wn * 64 + (m8 >> 1) * 8 + r8) * (RSH * 2) + (m8 & 1) * 16);

    float acc[2][8][4];
#pragma unroll
    for (int i = 0; i < 2; i++)
#pragma unroll
        for (int j = 0; j < 8; j++)
#pragma unroll
            for (int k = 0; k < 4; k++) acc[i][j][k] = 0.f;

    auto copy_tile = [&](int kc, int buf) {
        uint32_t sa  = sb + buf * TILEB;
        uint32_t sbm = sb + NSTAGE * TILEB + buf * TILEB;
#pragma unroll
        for (int i = 0; i < 4; i++) {
            int idx = tid * 4 + i;
            int r = idx >> 3, c8 = idx & 7;
            int gm = mb * 128 + r;
            if (gm >= M) gm = M - 1;
            cp16(sa + r * (RSH * 2) + c8 * 16, A + (size_t)gm * Cc + kc + c8 * 8);
            int gn = nb * 128 + r;
            cp16(sbm + r * (RSH * 2) + c8 * 16, Bw + (size_t)gn * Cc + kc + c8 * 8);
        }
        asm volatile("cp.async.commit_group;" ::: "memory");
    };

    const int NCH = Cc / 64;   // 12
    copy_tile(0, 0);
    copy_tile(64, 1);

    int buf = 0;
    for (int ci = 0; ci < NCH; ci++) {
        if (ci < NCH - 1)
            asm volatile("cp.async.wait_group 1;" ::: "memory");
        else
            asm volatile("cp.async.wait_group 0;" ::: "memory");
        __syncthreads();
        if (ci + 2 < NCH) {
            int nbuf = buf + 2; if (nbuf >= NSTAGE) nbuf -= NSTAGE;
            copy_tile((ci + 2) * 64, nbuf);
        }

        uint32_t sa  = sb + buf * TILEB + aoff;
        uint32_t sbm = sb + NSTAGE * TILEB + buf * TILEB + boff;
#pragma unroll
        for (int ks = 0; ks < 4; ks++) {
            uint32_t a[2][4];
            ldsm_x4(a[0], sa + ks * 32);
            ldsm_x4(a[1], sa + ks * 32 + 16 * (RSH * 2));
            uint32_t bf[4][4];
#pragma unroll
            for (int p = 0; p < 4; p++)
                ldsm_x4(bf[p], sbm + ks * 32 + p * (16 * (RSH * 2)));
#pragma unroll
            for (int p = 0; p < 4; p++)
#pragma unroll
                for (int j = 0; j < 2; j++) {
                    int nt = p * 2 + j;
                    mma_f16(acc[0][nt], a[0], bf[p][2 * j], bf[p][2 * j + 1]);
                    mma_f16(acc[1][nt], a[1], bf[p][2 * j], bf[p][2 * j + 1]);
                }
        }
        buf++; if (buf >= NSTAGE) buf = 0;
    }

#pragma unroll
    for (int mt = 0; mt < 2; mt++) {
        int m0 = mb * 128 + wm * 32 + mt * 16 + grp;
#pragma unroll
        for (int nt = 0; nt < 8; nt++) {
            int n0 = nb * 128 + wn * 64 + nt * 8 + tig * 2;
#pragma unroll
            for (int h = 0; h < 2; h++) {
                int m = m0 + h * 8;
                if (m >= M) continue;
                float v0 = acc[mt][nt][h * 2 + 0];
                float v1 = acc[mt][nt][h * 2 + 1];
                if (mode == 0) {
                    // m -> (batch, pixel-or-query row p)
                    int b, p;
                    if (m < Bb * NTOK) { b = m >> 12; p = m & (NTOK - 1); }
                    else { int t = m - Bb * NTOK; b = t >> 6; p = NTOK + (t & (NQ - 1)); }
                    int which = n0 / Cc;
                    int hd = (n0 % Cc) / DH;
                    int dd = n0 % DH;
                    __half* dst = (which == 0) ? g_Q : (which == 1) ? g_K : g_V;
                    *(__half2*)(dst + (((size_t)(b * NH + hd)) * PROW + p) * DH + dd) =
                        __floats2half2_rn(v0, v1);
                } else {
                    *(float2*)(out + (size_t)m * Nn + n0) =
                        make_float2(v0 + bias[n0], v1 + bias[n0 + 1]);
                }
            }
        }
    }
}

// ---------------- 3) fused attention with window gather ---------------------
constexpr int PADL  = 320;
constexpr int KQ_STR = 72;
constexpr int VT_STR = 328;
constexpr int O_STR  = 68;
constexpr int H_VS   = PADL * KQ_STR;
constexpr int H_QS   = H_VS + 64 * VT_STR;
constexpr int H_END  = H_QS + 64 * KQ_STR;
constexpr int F_OB0  = (H_END * 2 + 15) / 16 * 4;
constexpr int F_OB1  = F_OB0 + 64 * O_STR;
constexpr int F_RMAX = F_OB1 + 64 * O_STR;
constexpr int F_RSUM = F_RMAX + 256;
constexpr int F_MSK  = F_RSUM + 256;
constexpr int SMEM_ATT = (F_MSK + PADL) * 4;

__global__ __launch_bounds__(512, 1) void k_attn_fused(const int* __restrict__ q_mask) {
    extern __shared__ char smc[];
    __half* Ks = (__half*)smc;
    __half* Vs = (__half*)smc + H_VS;
    __half* Qs = (__half*)smc + H_QS;
    float* smf = (float*)smc;
    float* Ob0 = smf + F_OB0;
    float* Ob1 = smf + F_OB1;
    float* rmax = smf + F_RMAX;
    float* rsum = smf + F_RSUM;
    float* msk  = smf + F_MSK;

    int z  = blockIdx.x;
    int i  = z / NH;            // window index (batch-major: i = b*25 + w)
    int hd = z % NH;
    int bp = i / R_;            // pixel batch
    int w  = i % R_;
    int bq = i % Bb;            // query replication batch (repeat-major quirk)
    int wy = w / NWX, wx = w % NWX;

    const __half* Kpix = g_K + ((size_t)(bp * NH + hd)) * PROW * DH;
    const __half* Kq   = g_K + ((size_t)(bq * NH + hd)) * PROW * DH + (size_t)NTOK * DH;
    const __half* Vpix = g_V + ((size_t)(bp * NH + hd)) * PROW * DH;
    const __half* Vq   = g_V + ((size_t)(bq * NH + hd)) * PROW * DH + (size_t)NTOK * DH;
    const __half* Qpix = g_Q + ((size_t)(bp * NH + hd)) * PROW * DH;
    const __half* Qq   = g_Q + ((size_t)(bq * NH + hd)) * PROW * DH + (size_t)NTOK * DH;

    int tid = threadIdx.x, wid = tid >> 5, lane = tid & 31;
    int grp = lane >> 2, tig = lane & 3;
    int wm = wid & 3, wn = wid >> 2;
    int lr0 = wm * 16 + grp, lr1 = lr0 + 8;

    for (int j = tid; j < PADL; j += 512) {
        float m = 0.f;
        if (j >= NWIN)
            m = (j < LL && q_mask[bq * NQ + j - NWIN] != 0) ? 0.f : -1e30f;
        msk[j] = m;
    }
    // K gather: rows of 64 halves (8 x uint4); padded pixels & tail -> zero
    for (int idx = tid; idx < PADL * 8; idx += 512) {
        int r = idx >> 3, c = idx & 7;
        uint4 v = make_uint4(0, 0, 0, 0);
        if (r < NWIN) {
            int py = wy * WSZ + r / WSZ, px = wx * WSZ + r % WSZ;
            if (py < HH && px < WW)
                v = ((const uint4*)(Kpix + (size_t)(py * WW + px) * DH))[c];
        } else if (r < LL) {
            v = ((const uint4*)(Kq + (size_t)(r - NWIN) * DH))[c];
        }
        *(uint4*)(Ks + r * KQ_STR + c * 8) = v;
    }
    // V gather transposed: Vs[dh][key]
    for (int idx = tid; idx < PADL * 32; idx += 512) {
        int key = idx >> 5, dhp = idx & 31;
        __half2 v = __floats2half2_rn(0.f, 0.f);
        if (key < NWIN) {
            int py = wy * WSZ + key / WSZ, px = wx * WSZ + key % WSZ;
            if (py < HH && px < WW)
                v = ((const __half2*)(Vpix + (size_t)(py * WW + px) * DH))[dhp];
        } else if (key < LL) {
            v = ((const __half2*)(Vq + (size_t)(key - NWIN) * DH))[dhp];
        }
        Vs[(2 * dhp) * VT_STR + key]     = __low2half(v);
        Vs[(2 * dhp + 1) * VT_STR + key] = __high2half(v);
    }

    for (int qt = 0; qt < 5; qt++) {
        int qbase = qt * 64;
        __syncthreads();

        // Q tile gather
        for (int idx = tid; idx < 64 * 8; idx += 512) {
            int r = idx >> 3, c = idx & 7;
            int gr = qbase + r;
            uint4 v = make_uint4(0, 0, 0, 0);
            if (gr < NWIN) {
                int py = wy * WSZ + gr / WSZ, px = wx * WSZ + gr % WSZ;
                if (py < HH && px < WW)
                    v = ((const uint4*)(Qpix + (size_t)(py * WW + px) * DH))[c];
            } else if (gr < LL) {
                v = ((const uint4*)(Qq + (size_t)(gr - NWIN) * DH))[c];
            }
            *(uint4*)(Qs + r * KQ_STR + c * 8) = v;
        }
        __syncthreads();

        // ---- S = Q @ K^T : warp m16 x n80 (10 tiles), k=64 in 4 k16 steps ----
        float sf[10][4];
#pragma unroll
        for (int t = 0; t < 10; t++)
#pragma unroll
            for (int k = 0; k < 4; k++) sf[t][k] = 0.f;
#pragma unroll
        for (int ks = 0; ks < 4; ks++) {
            int k0 = ks * 16;
            uint32_t a[4];
            a[0] = *(const uint32_t*)(Qs + lr0 * KQ_STR + k0 + 2 * tig);
            a[1] = *(const uint32_t*)(Qs + lr1 * KQ_STR + k0 + 2 * tig);
            a[2] = *(const uint32_t*)(Qs + lr0 * KQ_STR + k0 + 8 + 2 * tig);
            a[3] = *(const uint32_t*)(Qs + lr1 * KQ_STR + k0 + 8 + 2 * tig);
#pragma unroll
            for (int t = 0; t < 10; t++) {
                int n0 = wn * 80 + t * 8;
                uint32_t b0 = *(const uint32_t*)(Ks + (n0 + grp) * KQ_STR + k0 + 2 * tig);
                uint32_t b1 = *(const uint32_t*)(Ks + (n0 + grp) * KQ_STR + k0 + 8 + 2 * tig);
                mma_f16(sf[t], a, b0, b1);
            }
        }

        // ---- scale + mask + rowmax ----
        float mx0 = -3e38f, mx1 = -3e38f;
#pragma unroll
        for (int t = 0; t < 10; t++) {
            int jb = wn * 80 + t * 8 + 2 * tig;
            float m0 = msk[jb], m1 = msk[jb + 1];
            sf[t][0] = sf[t][0] * 0.125f + m0;
            sf[t][1] = sf[t][1] * 0.125f + m1;
            sf[t][2] = sf[t][2] * 0.125f + m0;
            sf[t][3] = sf[t][3] * 0.125f + m1;
            mx0 = fmaxf(mx0, fmaxf(sf[t][0], sf[t][1]));
            mx1 = fmaxf(mx1, fmaxf(sf[t][2], sf[t][3]));
        }
        mx0 = fmaxf(mx0, __shfl_xor_sync(~0u, mx0, 1));
        mx0 = fmaxf(mx0, __shfl_xor_sync(~0u, mx0, 2));
        mx1 = fmaxf(mx1, __shfl_xor_sync(~0u, mx1, 1));
        mx1 = fmaxf(mx1, __shfl_xor_sync(~0u, mx1, 2));
        if (tig == 0) {
            rmax[lr0 * 4 + wn] = mx0;
            rmax[lr1 * 4 + wn] = mx1;
        }
        __syncthreads();
        float4 r40 = *(float4*)(rmax + lr0 * 4);
        float4 r41 = *(float4*)(rmax + lr1 * 4);
        float M0 = fmaxf(fmaxf(r40.x, r40.y), fmaxf(r40.z, r40.w));
        float M1 = fmaxf(fmaxf(r41.x, r41.y), fmaxf(r41.z, r41.w));

        // ---- exp + row sums; pack P as half2 A-fragments ----
        float s0 = 0.f, s1 = 0.f;
        uint32_t pk[10][2];
#pragma unroll
        for (int t = 0; t < 10; t++) {
            float e0 = __expf(sf[t][0] - M0), e1 = __expf(sf[t][1] - M0);
            float e2 = __expf(sf[t][2] - M1), e3 = __expf(sf[t][3] - M1);
            s0 += e0 + e1; s1 += e2 + e3;
            pk[t][0] = pack_h2(e0, e1);
            pk[t][1] = pack_h2(e2, e3);
        }
        s0 += __shfl_xor_sync(~0u, s0, 1);
        s0 += __shfl_xor_sync(~0u, s0, 2);
        s1 += __shfl_xor_sync(~0u, s1, 1);
        s1 += __shfl_xor_sync(~0u, s1, 2);
        if (tig == 0) {
            rsum[lr0 * 4 + wn] = s0;
            rsum[lr1 * 4 + wn] = s1;
        }

        // ---- O_partial = P @ V over 80 keys ----
        float of[8][4];
#pragma unroll
        for (int nt = 0; nt < 8; nt++)
#pragma unroll
            for (int k = 0; k < 4; k++) of[nt][k] = 0.f;
#pragma unroll
        for (int kt = 0; kt < 5; kt++) {
            uint32_t a[4];
            a[0] = pk[2 * kt][0];
            a[1] = pk[2 * kt][1];
            a[2] = pk[2 * kt + 1][0];
            a[3] = pk[2 * kt + 1][1];
            int kb = wn * 80 + kt * 16;
#pragma unroll
            for (int nt = 0; nt < 8; nt++) {
                int n0 = nt * 8 + grp;
                uint32_t b0 = *(const uint32_t*)(Vs + n0 * VT_STR + kb + 2 * tig);
                uint32_t b1 = *(const uint32_t*)(Vs + n0 * VT_STR + kb + 8 + 2 * tig);
                mma_f16(of[nt], a, b0, b1);
            }
        }

        // ---- combine 4 key-slices ----
        if (wn < 2) {
            float* Ob = (wn == 0) ? Ob0 : Ob1;
#pragma unroll
            for (int nt = 0; nt < 8; nt++) {
                int c = nt * 8 + 2 * tig;
                *(float2*)(Ob + lr0 * O_STR + c) = make_float2(of[nt][0], of[nt][1]);
                *(float2*)(Ob + lr1 * O_STR + c) = make_float2(of[nt][2], of[nt][3]);
            }
        }
        __syncthreads();
        if (wn >= 2) {
            float* Ob = (wn == 2) ? Ob0 : Ob1;
#pragma unroll
            for (int nt = 0; nt < 8; nt++) {
                int c = nt * 8 + 2 * tig;
                float2 p0 = *(float2*)(Ob + lr0 * O_STR + c);
                float2 p1 = *(float2*)(Ob + lr1 * O_STR + c);
                *(float2*)(Ob + lr0 * O_STR + c) =
                    make_float2(p0.x + of[nt][0], p0.y + of[nt][1]);
                *(float2*)(Ob + lr1 * O_STR + c) =
                    make_float2(p1.x + of[nt][2], p1.y + of[nt][3]);
            }
        }
        __syncthreads();

        // ---- final merge + normalize + scatter ----
        {
            int r = tid >> 3;
            int c0 = (tid & 7) * 8;
            int grow = qbase + r;
            if (grow < LL) {
                float4 s4 = *(float4*)(rsum + r * 4);
                float inv = 1.f / (s4.x + s4.y + s4.z + s4.w);
                float4 x0 = *(float4*)(Ob0 + r * O_STR + c0);
                float4 x1 = *(float4*)(Ob1 + r * O_STR + c0);
                float4 y0 = *(float4*)(Ob0 + r * O_STR + c0 + 4);
                float4 y1 = *(float4*)(Ob1 + r * O_STR + c0 + 4);
                __half2 h0 = __floats2half2_rn((x0.x + x1.x) * inv, (x0.y + x1.y) * inv);
                __half2 h1 = __floats2half2_rn((x0.z + x1.z) * inv, (x0.w + x1.w) * inv);
                __half2 h2 = __floats2half2_rn((y0.x + y1.x) * inv, (y0.y + y1.y) * inv);
                __half2 h3 = __floats2half2_rn((y0.z + y1.z) * inv, (y0.w + y1.w) * inv);
                __half2* dst = nullptr;
                if (grow < NWIN) {
                    int py = wy * WSZ + grow / WSZ, px = wx * WSZ + grow % WSZ;
                    if (py < HH && px < WW)
                        dst = (__half2*)(g_ctx + ((size_t)bp * NTOK + py * WW + px) * Cc
                                         + hd * DH + c0);
                } else {
                    dst = (__half2*)(g_Oq + ((size_t)i * NQ + (grow - NWIN)) * Cc
                                     + hd * DH + c0);
                }
                if (dst) { dst[0] = h0; dst[1] = h1; dst[2] = h2; dst[3] = h3; }
            }
        }
    }
}

// ---------------- 4) ctx rows for queries: mean over windows ----------------
__global__ __launch_bounds__(256) void k_ctx_q() {
    int idx = blockIdx.x * blockDim.x + threadIdx.x;
    const int SEG = Cc / 2;
    if (idx >= Bb * NQ * SEG) return;
    int j = idx / SEG, c = idx % SEG;
    int b = j / NQ, lq = j % NQ;
    float a0 = 0.f, a1 = 0.f;
#pragma unroll
    for (int w = 0; w < R_; w++) {
        int i = w * Bb + b;   // repeat-major mean grouping
        __half2 v = ((const __half2*)(g_Oq + ((size_t)i * NQ + lq) * Cc))[c];
        float2 f = __half22float2(v);
        a0 += f.x; a1 += f.y;
    }
    const float inv = 1.f / (float)R_;
    ((__half2*)(g_ctx + (size_t)(Bb * NTOK + j) * Cc))[c] =
        __floats2half2_rn(a0 * inv, a1 * inv);
}

// ---------------- launch ----------------
extern "C" void kernel_launch(void* const* d_in, const int* in_sizes, int n_in,
                              void* d_out, int out_size) {
    const float* x     = (const float*)d_in[0];
    const float* q     = (const float*)d_in[1];
    const float* W_in  = (const float*)d_in[2];
    const float* W_out = (const float*)d_in[3];
    const float* b_out = (const float*)d_in[4];
    const int*   qmask = (const int*)d_in[5];
    float* out = (float*)d_out;

    static bool attr_set = false;
    if (!attr_set) {
        cudaFuncSetAttribute(k_gemm_mma, cudaFuncAttributeMaxDynamicSharedMemorySize,
                             SMEM_GEMM);
        cudaFuncSetAttribute(k_attn_fused, cudaFuncAttributeMaxDynamicSharedMemorySize,
                             SMEM_ATT);
        attr_set = true;
    }

    k_cvt_w<<<(4 * Cc * Cc + 255) / 256, 256>>>(W_in, W_out);
    k_prep<<<(CTXROWS * (Cc / 4) + 255) / 256, 256>>>(x, q);

    dim3 g_qkv(3 * Cc / 128, CTXROWS / 128);   // 18 x 130
    k_gemm_mma<<<g_qkv, 256, SMEM_GEMM>>>(nullptr, nullptr, CTXROWS, 3 * Cc, 0);

    k_attn_fused<<<BW * NH, 512, SMEM_ATT>>>(qmask);

    k_ctx_q<<<(Bb * NQ * (Cc / 2) + 255) / 256, 256>>>();

    dim3 g_out(Cc / 128, CTXROWS / 128);       // 6 x 130
    k_gemm_mma<<<g_out, 256, SMEM_GEMM>>>(b_out, out, CTXROWS, Cc, 1);
}

// round 12
// speedup vs baseline: 6.2127x; 1.0326x over previous
#include <cuda_runtime.h>
#include <cuda_fp16.h>
#include <cstdint>

// ---------------- problem constants ----------------
constexpr int Bb   = 4;
constexpr int NTOK = 4096;
constexpr int Cc   = 768;
constexpr int NQ   = 64;
constexpr int HH   = 64, WW = 64;
constexpr int WSZ  = 14;
constexpr int NH   = 12, DH = 64;
constexpr int NWX  = 5;
constexpr int R_   = 25;
constexpr int BW   = Bb * R_;           // 100
constexpr int NWIN = WSZ * WSZ;         // 196
constexpr int LL   = NWIN + NQ;         // 260
constexpr int CTXROWS = Bb * NTOK + Bb * NQ; // 16640
constexpr int PROW = NTOK + NQ;         // 4160 rows per (b,head)

// ---------------- scratch (f16 intermediates) ----------------
__device__ __half g_tok[(size_t)CTXROWS * Cc];
__device__ __half g_Q[(size_t)Bb * NH * PROW * DH];
__device__ __half g_K[(size_t)Bb * NH * PROW * DH];
__device__ __half g_V[(size_t)Bb * NH * PROW * DH];
__device__ __half g_Oq[(size_t)BW * NQ * Cc];
__device__ __half g_ctx[(size_t)CTXROWS * Cc];
__device__ __half g_Wt[(size_t)(3 * Cc) * Cc];
__device__ __half g_Wot[(size_t)Cc * Cc];

// ---------------- helpers ----------------
__device__ __forceinline__ uint32_t smem_u32(const void* p) {
    uint32_t a;
    asm("{ .reg .u64 t; cvta.to.shared.u64 t, %1; cvt.u32.u64 %0, t; }"
        : "=r"(a) : "l"(p));
    return a;
}
__device__ __forceinline__ void cp16(uint32_t s, const void* g) {
    asm volatile("cp.async.cg.shared.global [%0], [%1], 16;" :: "r"(s), "l"(g) : "memory");
}
__device__ __forceinline__ void cp16z(uint32_t s, const void* g, int sz) {
    asm volatile("cp.async.cg.shared.global [%0], [%1], 16, %2;"
                 :: "r"(s), "l"(g), "r"(sz) : "memory");
}
__device__ __forceinline__ void mma_f16(float* c, const uint32_t* a,
                                        uint32_t b0, uint32_t b1) {
    asm volatile("mma.sync.aligned.m16n8k16.row.col.f32.f16.f16.f32 "
                 "{%0,%1,%2,%3}, {%4,%5,%6,%7}, {%8,%9}, {%0,%1,%2,%3};"
                 : "+f"(c[0]), "+f"(c[1]), "+f"(c[2]), "+f"(c[3])
                 : "r"(a[0]), "r"(a[1]), "r"(a[2]), "r"(a[3]), "r"(b0), "r"(b1));
}
__device__ __forceinline__ void ldsm_x4(uint32_t* r, uint32_t addr) {
    asm volatile("ldmatrix.sync.aligned.m8n8.x4.shared.b16 {%0,%1,%2,%3}, [%4];"
                 : "=r"(r[0]), "=r"(r[1]), "=r"(r[2]), "=r"(r[3]) : "r"(addr));
}
__device__ __forceinline__ uint32_t pack_h2(float lo, float hi) {
    __half2 h = __floats2half2_rn(lo, hi);
    return *(uint32_t*)&h;
}

// ---------------- 0) convert weights to f16 ----------------
__global__ __launch_bounds__(256) void k_cvt_w(const float* __restrict__ Win,
                                               const float* __restrict__ Wout) {
    int idx = blockIdx.x * blockDim.x + threadIdx.x;
    const int N1 = 3 * Cc * Cc;
    const int N2 = Cc * Cc;
    if (idx < N1) g_Wt[idx] = __float2half_rn(Win[idx]);
    else if (idx < N1 + N2) g_Wot[idx - N1] = __float2half_rn(Wout[idx - N1]);
}

// ---------------- 1) unique tokens -> f16 ----------------
__global__ __launch_bounds__(256) void k_prep(const float* __restrict__ x,
                                              const float* __restrict__ q) {
    int idx = blockIdx.x * blockDim.x + threadIdx.x;
    if (idx >= CTXROWS * (Cc / 4)) return;
    int t  = idx / (Cc / 4);
    int c4 = idx % (Cc / 4);
    float4 val;
    if (t < Bb * NTOK) val = ((const float4*)(x + (size_t)t * Cc))[c4];
    else               val = ((const float4*)(q + (size_t)(t - Bb * NTOK) * Cc))[c4];
    __half2* dst = (__half2*)(g_tok + (size_t)t * Cc + c4 * 4);
    dst[0] = __floats2half2_rn(val.x, val.y);
    dst[1] = __floats2half2_rn(val.z, val.w);
}

// ---------------- 2) f16 mma.sync GEMM (NT), 3-stage + ldmatrix -------------
constexpr int RSH    = 72;
constexpr int TILEB  = 128 * RSH * 2;
constexpr int NSTAGE = 3;
constexpr int SMEM_GEMM = 2 * NSTAGE * TILEB;

__global__ __launch_bounds__(256, 2) void k_gemm_mma(const float* __restrict__ bias,
                                                     float* __restrict__ out,
                                                     int M, int Nn, int mode) {
    extern __shared__ char smc[];
    uint32_t sb = smem_u32(smc);
    const __half* A  = (mode == 0) ? g_tok : g_ctx;
    const __half* Bw = (mode == 0) ? g_Wt  : g_Wot;
    int tid = threadIdx.x, wid = tid >> 5, lane = tid & 31;
    int grp = lane >> 2, tig = lane & 3;
    int wm = wid & 3, wn = wid >> 2;
    int mb = blockIdx.y, nb = blockIdx.x;

    int m8 = lane >> 3, r8 = lane & 7;
    uint32_t aoff = (uint32_t)((wm * 32 + (m8 & 1) * 8 + r8) * (RSH * 2) + (m8 >> 1) * 16);
    uint32_t boff = (uint32_t)((wn * 64 + (m8 >> 1) * 8 + r8) * (RSH * 2) + (m8 & 1) * 16);

    float acc[2][8][4];
#pragma unroll
    for (int i = 0; i < 2; i++)
#pragma unroll
        for (int j = 0; j < 8; j++)
#pragma unroll
            for (int k = 0; k < 4; k++) acc[i][j][k] = 0.f;

    auto copy_tile = [&](int kc, int buf) {
        uint32_t sa  = sb + buf * TILEB;
        uint32_t sbm = sb + NSTAGE * TILEB + buf * TILEB;
#pragma unroll
        for (int i = 0; i < 4; i++) {
            int idx = tid * 4 + i;
            int r = idx >> 3, c8 = idx & 7;
            int gm = mb * 128 + r;
            if (gm >= M) gm = M - 1;
            cp16(sa + r * (RSH * 2) + c8 * 16, A + (size_t)gm * Cc + kc + c8 * 8);
            int gn = nb * 128 + r;
            cp16(sbm + r * (RSH * 2) + c8 * 16, Bw + (size_t)gn * Cc + kc + c8 * 8);
        }
        asm volatile("cp.async.commit_group;" ::: "memory");
    };

    const int NCH = Cc / 64;
    copy_tile(0, 0);
    copy_tile(64, 1);

    int buf = 0;
    for (int ci = 0; ci < NCH; ci++) {
        if (ci < NCH - 1)
            asm volatile("cp.async.wait_group 1;" ::: "memory");
        else
            asm volatile("cp.async.wait_group 0;" ::: "memory");
        __syncthreads();
        if (ci + 2 < NCH) {
            int nbuf = buf + 2; if (nbuf >= NSTAGE) nbuf -= NSTAGE;
            copy_tile((ci + 2) * 64, nbuf);
        }

        uint32_t sa  = sb + buf * TILEB + aoff;
        uint32_t sbm = sb + NSTAGE * TILEB + buf * TILEB + boff;
#pragma unroll
        for (int ks = 0; ks < 4; ks++) {
            uint32_t a[2][4];
            ldsm_x4(a[0], sa + ks * 32);
            ldsm_x4(a[1], sa + ks * 32 + 16 * (RSH * 2));
            uint32_t bf[4][4];
#pragma unroll
            for (int p = 0; p < 4; p++)
                ldsm_x4(bf[p], sbm + ks * 32 + p * (16 * (RSH * 2)));
#pragma unroll
            for (int p = 0; p < 4; p++)
#pragma unroll
                for (int j = 0; j < 2; j++) {
                    int nt = p * 2 + j;
                    mma_f16(acc[0][nt], a[0], bf[p][2 * j], bf[p][2 * j + 1]);
                    mma_f16(acc[1][nt], a[1], bf[p][2 * j], bf[p][2 * j + 1]);
                }
        }
        buf++; if (buf >= NSTAGE) buf = 0;
    }

#pragma unroll
    for (int mt = 0; mt < 2; mt++) {
        int m0 = mb * 128 + wm * 32 + mt * 16 + grp;
#pragma unroll
        for (int nt = 0; nt < 8; nt++) {
            int n0 = nb * 128 + wn * 64 + nt * 8 + tig * 2;
#pragma unroll
            for (int h = 0; h < 2; h++) {
                int m = m0 + h * 8;
                if (m >= M) continue;
                float v0 = acc[mt][nt][h * 2 + 0];
                float v1 = acc[mt][nt][h * 2 + 1];
                if (mode == 0) {
                    int b, p;
                    if (m < Bb * NTOK) { b = m >> 12; p = m & (NTOK - 1); }
                    else { int t = m - Bb * NTOK; b = t >> 6; p = NTOK + (t & (NQ - 1)); }
                    int which = n0 / Cc;
                    int hd = (n0 % Cc) / DH;
                    int dd = n0 % DH;
                    __half* dst = (which == 0) ? g_Q : (which == 1) ? g_K : g_V;
                    *(__half2*)(dst + (((size_t)(b * NH + hd)) * PROW + p) * DH + dd) =
                        __floats2half2_rn(v0, v1);
                } else {
                    *(float2*)(out + (size_t)m * Nn + n0) =
                        make_float2(v0 + bias[n0], v1 + bias[n0 + 1]);
                }
            }
        }
    }
}

// ---------------- 3) fused attention: ldsm frags + Q cp.async prefetch ------
constexpr int PADL   = 320;
constexpr int KQ_STR = 72;               // halves (144 B rows)
constexpr int VT_STR = 328;              // halves (656 B rows)
constexpr int O_STR  = 68;
constexpr int H_VS   = PADL * KQ_STR;            // 23040
constexpr int H_QS0  = H_VS + 64 * VT_STR;       // 44032
constexpr int H_QS1  = H_QS0 + 64 * KQ_STR;      // 48640
constexpr int H_END  = H_QS1 + 64 * KQ_STR;      // 53248 halves
constexpr int F_OB0  = (H_END * 2) / 16 * 4;     // 26624 floats (16B aligned)
constexpr int F_OB1  = F_OB0 + 64 * O_STR;
constexpr int F_RMAX = F_OB1 + 64 * O_STR;
constexpr int F_RSUM = F_RMAX + 256;
constexpr int F_MSK  = F_RSUM + 256;
constexpr int SMEM_ATT = (F_MSK + PADL) * 4;     // 144640 B

__global__ __launch_bounds__(512, 1) void k_attn_fused(const int* __restrict__ q_mask) {
    extern __shared__ char smc[];
    __half* Ks = (__half*)smc;
    __half* Vs = (__half*)smc + H_VS;
    float* smf = (float*)smc;
    float* Ob0 = smf + F_OB0;
    float* Ob1 = smf + F_OB1;
    float* rmax = smf + F_RMAX;
    float* rsum = smf + F_RSUM;
    float* msk  = smf + F_MSK;
    uint32_t sbase = smem_u32(smc);

    int z  = blockIdx.x;
    int i  = z / NH;
    int hd = z % NH;
    int bp = i / R_;
    int w  = i % R_;
    int bq = i % Bb;
    int wy = w / NWX, wx = w % NWX;

    const __half* Kpix = g_K + ((size_t)(bp * NH + hd)) * PROW * DH;
    const __half* Kq   = g_K + ((size_t)(bq * NH + hd)) * PROW * DH + (size_t)NTOK * DH;
    const __half* Vpix = g_V + ((size_t)(bp * NH + hd)) * PROW * DH;
    const __half* Vq   = g_V + ((size_t)(bq * NH + hd)) * PROW * DH + (size_t)NTOK * DH;
    const __half* Qpix = g_Q + ((size_t)(bp * NH + hd)) * PROW * DH;
    const __half* Qq   = g_Q + ((size_t)(bq * NH + hd)) * PROW * DH + (size_t)NTOK * DH;

    int tid = threadIdx.x, wid = tid >> 5, lane = tid & 31;
    int grp = lane >> 2, tig = lane & 3;
    int wm = wid & 3, wn = wid >> 2;
    int lr0 = wm * 16 + grp, lr1 = lr0 + 8;
    int m8 = lane >> 3, r8 = lane & 7;

    // ldsm byte offsets
    uint32_t q_off = sbase + (uint32_t)(H_QS0 * 2) +
                     (uint32_t)((wm * 16 + (m8 & 1) * 8 + r8) * 144 + (m8 >> 1) * 16);
    uint32_t k_off = sbase +
                     (uint32_t)((wn * 80 + (m8 >> 1) * 8 + r8) * 144 + (m8 & 1) * 16);
    uint32_t v_off = sbase + (uint32_t)(H_VS * 2) +
                     (uint32_t)(((m8 >> 1) * 8 + r8) * 656 + (m8 & 1) * 16);

    // Q prefetch: one cp16 per thread per tile
    auto prefetch_q = [&](int qt, int buf) {
        int r = tid >> 3, c = tid & 7;
        int gr = qt * 64 + r;
        const __half* src = Qpix;
        int sz = 0;
        if (gr < NWIN) {
            int py = wy * WSZ + gr / WSZ, px = wx * WSZ + gr % WSZ;
            if (py < HH && px < WW) { src = Qpix + (size_t)(py * WW + px) * DH + c * 8; sz = 16; }
        } else if (gr < LL) {
            src = Qq + (size_t)(gr - NWIN) * DH + c * 8; sz = 16;
        }
        uint32_t dst = sbase + (uint32_t)((buf ? H_QS1 : H_QS0) * 2) + r * 144 + c * 16;
        cp16z(dst, src, sz);
        asm volatile("cp.async.commit_group;" ::: "memory");
    };

    prefetch_q(0, 0);

    for (int j = tid; j < PADL; j += 512) {
        float m = 0.f;
        if (j >= NWIN)
            m = (j < LL && q_mask[bq * NQ + j - NWIN] != 0) ? 0.f : -1e30f;
        msk[j] = m;
    }
    for (int idx = tid; idx < PADL * 8; idx += 512) {
        int r = idx >> 3, c = idx & 7;
        uint4 v = make_uint4(0, 0, 0, 0);
        if (r < NWIN) {
            int py = wy * WSZ + r / WSZ, px = wx * WSZ + r % WSZ;
            if (py < HH && px < WW)
                v = ((const uint4*)(Kpix + (size_t)(py * WW + px) * DH))[c];
        } else if (r < LL) {
            v = ((const uint4*)(Kq + (size_t)(r - NWIN) * DH))[c];
        }
        *(uint4*)(Ks + r * KQ_STR + c * 8) = v;
    }
    for (int idx = tid; idx < PADL * 32; idx += 512) {
        int key = idx >> 5, dhp = idx & 31;
        __half2 v = __floats2half2_rn(0.f, 0.f);
        if (key < NWIN) {
            int py = wy * WSZ + key / WSZ, px = wx * WSZ + key % WSZ;
            if (py < HH && px < WW)
                v = ((const __half2*)(Vpix + (size_t)(py * WW + px) * DH))[dhp];
        } else if (key < LL) {
            v = ((const __half2*)(Vq + (size_t)(key - NWIN) * DH))[dhp];
        }
        Vs[(2 * dhp) * VT_STR + key]     = __low2half(v);
        Vs[(2 * dhp + 1) * VT_STR + key] = __high2half(v);
    }

    for (int qt = 0; qt < 5; qt++) {
        uint32_t qb = q_off + (uint32_t)((qt & 1) ? (H_QS1 - H_QS0) * 2 : 0);
        asm volatile("cp.async.wait_group 0;" ::: "memory");
        __syncthreads();   // D: Q(qt) ready, prev-tile Ob/rsum consumed

        // ---- S = Q @ K^T : 4 k16 steps, ldsm frags ----
        float sf[10][4];
#pragma unroll
        for (int t = 0; t < 10; t++)
#pragma unroll
            for (int k = 0; k < 4; k++) sf[t][k] = 0.f;
#pragma unroll
        for (int ks = 0; ks < 4; ks++) {
            uint32_t a[4];
            ldsm_x4(a, qb + ks * 32);
#pragma unroll
            for (int tp = 0; tp < 5; tp++) {
                uint32_t bb[4];
                ldsm_x4(bb, k_off + tp * (16 * 144) + ks * 32);
                mma_f16(sf[2 * tp],     a, bb[0], bb[1]);
                mma_f16(sf[2 * tp + 1], a, bb[2], bb[3]);
            }
        }

        // ---- scale + mask + rowmax ----
        float mx0 = -3e38f, mx1 = -3e38f;
#pragma unroll
        for (int t = 0; t < 10; t++) {
            int jb = wn * 80 + t * 8 + 2 * tig;
            float m0 = msk[jb], m1 = msk[jb + 1];
            sf[t][0] = sf[t][0] * 0.125f + m0;
            sf[t][1] = sf[t][1] * 0.125f + m1;
            sf[t][2] = sf[t][2] * 0.125f + m0;
            sf[t][3] = sf[t][3] * 0.125f + m1;
            mx0 = fmaxf(mx0, fmaxf(sf[t][0], sf[t][1]));
            mx1 = fmaxf(mx1, fmaxf(sf[t][2], sf[t][3]));
        }
        mx0 = fmaxf(mx0, __shfl_xor_sync(~0u, mx0, 1));
        mx0 = fmaxf(mx0, __shfl_xor_sync(~0u, mx0, 2));
        mx1 = fmaxf(mx1, __shfl_xor_sync(~0u, mx1, 1));
        mx1 = fmaxf(mx1, __shfl_xor_sync(~0u, mx1, 2));
        if (tig == 0) {
            rmax[lr0 * 4 + wn] = mx0;
            rmax[lr1 * 4 + wn] = mx1;
        }
        __syncthreads();   // A
        float4 r40 = *(float4*)(rmax + lr0 * 4);
        float4 r41 = *(float4*)(rmax + lr1 * 4);
        float M0 = fmaxf(fmaxf(r40.x, r40.y), fmaxf(r40.z, r40.w));
        float M1 = fmaxf(fmaxf(r41.x, r41.y), fmaxf(r41.z, r41.w));

        // prefetch next Q tile (buffer safe: last read two tiles ago)
        if (qt + 1 < 5) prefetch_q(qt + 1, (qt + 1) & 1);

        // ---- exp + row sums; pack P as half2 A-fragments ----
        float s0 = 0.f, s1 = 0.f;
        uint32_t pk[10][2];
#pragma unroll
        for (int t = 0; t < 10; t++) {
            float e0 = __expf(sf[t][0] - M0), e1 = __expf(sf[t][1] - M0);
            float e2 = __expf(sf[t][2] - M1), e3 = __expf(sf[t][3] - M1);
            s0 += e0 + e1; s1 += e2 + e3;
            pk[t][0] = pack_h2(e0, e1);
            pk[t][1] = pack_h2(e2, e3);
        }
        s0 += __shfl_xor_sync(~0u, s0, 1);
        s0 += __shfl_xor_sync(~0u, s0, 2);
        s1 += __shfl_xor_sync(~0u, s1, 1);
        s1 += __shfl_xor_sync(~0u, s1, 2);
        if (tig == 0) {
            rsum[lr0 * 4 + wn] = s0;
            rsum[lr1 * 4 + wn] = s1;
        }

        // ---- O_partial = P @ V over 80 keys: ldsm V frags ----
        float of[8][4];
#pragma unroll
        for (int nt = 0; nt < 8; nt++)
#pragma unroll
            for (int k = 0; k < 4; k++) of[nt][k] = 0.f;
#pragma unroll
        for (int kt = 0; kt < 5; kt++) {
            uint32_t a[4];
            a[0] = pk[2 * kt][0];
            a[1] = pk[2 * kt][1];
            a[2] = pk[2 * kt + 1][0];
            a[3] = pk[2 * kt + 1][1];
            uint32_t kb_b = (uint32_t)((wn * 80 + kt * 16) * 2);   // byte offset in row
#pragma unroll
            for (int v = 0; v < 4; v++) {
                uint32_t vf[4];
                ldsm_x4(vf, v_off + v * (16 * 656) + kb_b);
                mma_f16(of[2 * v],     a, vf[0], vf[1]);
                mma_f16(of[2 * v + 1], a, vf[2], vf[3]);
            }
        }

        // ---- combine 4 key-slices ----
        if (wn < 2) {
            float* Ob = (wn == 0) ? Ob0 : Ob1;
#pragma unroll
            for (int nt = 0; nt < 8; nt++) {
                int c = nt * 8 + 2 * tig;
                *(float2*)(Ob + lr0 * O_STR + c) = make_float2(of[nt][0], of[nt][1]);
                *(float2*)(Ob + lr1 * O_STR + c) = make_float2(of[nt][2], of[nt][3]);
            }
        }
        __syncthreads();   // B
        if (wn >= 2) {
            float* Ob = (wn == 2) ? Ob0 : Ob1;
#pragma unroll
            for (int nt = 0; nt < 8; nt++) {
                int c = nt * 8 + 2 * tig;
                float2 p0 = *(float2*)(Ob + lr0 * O_STR + c);
                float2 p1 = *(float2*)(Ob + lr1 * O_STR + c);
                *(float2*)(Ob + lr0 * O_STR + c) =
                    make_float2(p0.x + of[nt][0], p0.y + of[nt][1]);
                *(float2*)(Ob + lr1 * O_STR + c) =
                    make_float2(p1.x + of[nt][2], p1.y + of[nt][3]);
            }
        }
        __syncthreads();   // C

        // ---- final merge + normalize + scatter ----
        {
            int r = tid >> 3;
            int c0 = (tid & 7) * 8;
            int grow = qt * 64 + r;
            if (grow < LL) {
                float4 s4 = *(float4*)(rsum + r * 4);
                float inv = 1.f / (s4.x + s4.y + s4.z + s4.w);
                float4 x0 = *(float4*)(Ob0 + r * O_STR + c0);
                float4 x1 = *(float4*)(Ob1 + r * O_STR + c0);
                float4 y0 = *(float4*)(Ob0 + r * O_STR + c0 + 4);
                float4 y1 = *(float4*)(Ob1 + r * O_STR + c0 + 4);
                __half2 h0 = __floats2half2_rn((x0.x + x1.x) * inv, (x0.y + x1.y) * inv);
                __half2 h1 = __floats2half2_rn((x0.z + x1.z) * inv, (x0.w + x1.w) * inv);
                __half2 h2 = __floats2half2_rn((y0.x + y1.x) * inv, (y0.y + y1.y) * inv);
                __half2 h3 = __floats2half2_rn((y0.z + y1.z) * inv, (y0.w + y1.w) * inv);
                __half2* dst = nullptr;
                if (grow < NWIN) {
                    int py = wy * WSZ + grow / WSZ, px = wx * WSZ + grow % WSZ;
                    if (py < HH && px < WW)
                        dst = (__half2*)(g_ctx + ((size_t)bp * NTOK + py * WW + px) * Cc
                                         + hd * DH + c0);
                } else {
                    dst = (__half2*)(g_Oq + ((size_t)i * NQ + (grow - NWIN)) * Cc
                                     + hd * DH + c0);
                }
                if (dst) { dst[0] = h0; dst[1] = h1; dst[2] = h2; dst[3] = h3; }
            }
        }
    }
}

// ---------------- 4) ctx rows for queries: mean over windows ----------------
__global__ __launch_bounds__(256) void k_ctx_q() {
    int idx = blockIdx.x * blockDim.x + threadIdx.x;
    const int SEG = Cc / 2;
    if (idx >= Bb * NQ * SEG) return;
    int j = idx / SEG, c = idx % SEG;
    int b = j / NQ, lq = j % NQ;
    float a0 = 0.f, a1 = 0.f;
#pragma unroll
    for (int w = 0; w < R_; w++) {
        int i = w * Bb + b;
        __half2 v = ((const __half2*)(g_Oq + ((size_t)i * NQ + lq) * Cc))[c];
        float2 f = __half22float2(v);
        a0 += f.x; a1 += f.y;
    }
    const float inv = 1.f / (float)R_;
    ((__half2*)(g_ctx + (size_t)(Bb * NTOK + j) * Cc))[c] =
        __floats2half2_rn(a0 * inv, a1 * inv);
}

// ---------------- launch ----------------
extern "C" void kernel_launch(void* const* d_in, const int* in_sizes, int n_in,
                              void* d_out, int out_size) {
    const float* x     = (const float*)d_in[0];
    const float* q     = (const float*)d_in[1];
    const float* W_in  = (const float*)d_in[2];
    const float* W_out = (const float*)d_in[3];
    const float* b_out = (const float*)d_in[4];
    const int*   qmask = (const int*)d_in[5];
    float* out = (float*)d_out;

    static bool attr_set = false;
    if (!attr_set) {
        cudaFuncSetAttribute(k_gemm_mma, cudaFuncAttributeMaxDynamicSharedMemorySize,
                             SMEM_GEMM);
        cudaFuncSetAttribute(k_attn_fused, cudaFuncAttributeMaxDynamicSharedMemorySize,
                             SMEM_ATT);
        attr_set = true;
    }

    k_cvt_w<<<(4 * Cc * Cc + 255) / 256, 256>>>(W_in, W_out);
    k_prep<<<(CTXROWS * (Cc / 4) + 255) / 256, 256>>>(x, q);

    dim3 g_qkv(3 * Cc / 128, CTXROWS / 128);
    k_gemm_mma<<<g_qkv, 256, SMEM_GEMM>>>(nullptr, nullptr, CTXROWS, 3 * Cc, 0);

    k_attn_fused<<<BW * NH, 512, SMEM_ATT>>>(qmask);

    k_ctx_q<<<(Bb * NQ * (Cc / 2) + 255) / 256, 256>>>();

    dim3 g_out(Cc / 128, CTXROWS / 128);
    k_gemm_mma<<<g_out, 256, SMEM_GEMM>>>(b_out, out, CTXROWS, Cc, 1);
}

// round 13
// speedup vs baseline: 6.7869x; 1.0924x over previous
#include <cuda_runtime.h>
#include <cuda_fp16.h>
#include <cstdint>

// ---------------- problem constants ----------------
constexpr int Bb   = 4;
constexpr int NTOK = 4096;
constexpr int Cc   = 768;
constexpr int NQ   = 64;
constexpr int HH   = 64, WW = 64;
constexpr int WSZ  = 14;
constexpr int NH   = 12, DH = 64;
constexpr int NWX  = 5;
constexpr int R_   = 25;
constexpr int BW   = Bb * R_;           // 100
constexpr int NWIN = WSZ * WSZ;         // 196
constexpr int LL   = NWIN + NQ;         // 260
constexpr int CTXROWS = Bb * NTOK + Bb * NQ; // 16640
constexpr int PROW = NTOK + NQ;         // 4160 rows per (b,head)

// ---------------- scratch (f16 intermediates) ----------------
__device__ __half g_tok[(size_t)CTXROWS * Cc];
__device__ __half g_Q[(size_t)Bb * NH * PROW * DH];
__device__ __half g_K[(size_t)Bb * NH * PROW * DH];
__device__ __half g_V[(size_t)Bb * NH * PROW * DH];
__device__ __half g_Oq[(size_t)BW * NQ * Cc];
__device__ __half g_ctx[(size_t)CTXROWS * Cc];
__device__ __half g_Wt[(size_t)(3 * Cc) * Cc];
__device__ __half g_Wot[(size_t)Cc * Cc];

// ---------------- helpers ----------------
__device__ __forceinline__ uint32_t smem_u32(const void* p) {
    uint32_t a;
    asm("{ .reg .u64 t; cvta.to.shared.u64 t, %1; cvt.u32.u64 %0, t; }"
        : "=r"(a) : "l"(p));
    return a;
}
__device__ __forceinline__ void cp16(uint32_t s, const void* g) {
    asm volatile("cp.async.cg.shared.global [%0], [%1], 16;" :: "r"(s), "l"(g) : "memory");
}
__device__ __forceinline__ void cp16z(uint32_t s, const void* g, int sz) {
    asm volatile("cp.async.cg.shared.global [%0], [%1], 16, %2;"
                 :: "r"(s), "l"(g), "r"(sz) : "memory");
}
__device__ __forceinline__ void mma_f16(float* c, const uint32_t* a,
                                        uint32_t b0, uint32_t b1) {
    asm volatile("mma.sync.aligned.m16n8k16.row.col.f32.f16.f16.f32 "
                 "{%0,%1,%2,%3}, {%4,%5,%6,%7}, {%8,%9}, {%0,%1,%2,%3};"
                 : "+f"(c[0]), "+f"(c[1]), "+f"(c[2]), "+f"(c[3])
                 : "r"(a[0]), "r"(a[1]), "r"(a[2]), "r"(a[3]), "r"(b0), "r"(b1));
}
__device__ __forceinline__ void ldsm_x4(uint32_t* r, uint32_t addr) {
    asm volatile("ldmatrix.sync.aligned.m8n8.x4.shared.b16 {%0,%1,%2,%3}, [%4];"
                 : "=r"(r[0]), "=r"(r[1]), "=r"(r[2]), "=r"(r[3]) : "r"(addr));
}
__device__ __forceinline__ void ldsm_x4t(uint32_t* r, uint32_t addr) {
    asm volatile("ldmatrix.sync.aligned.m8n8.x4.trans.shared.b16 {%0,%1,%2,%3}, [%4];"
                 : "=r"(r[0]), "=r"(r[1]), "=r"(r[2]), "=r"(r[3]) : "r"(addr));
}
__device__ __forceinline__ void bar_grp(int id) {
    asm volatile("bar.sync %0, 128;" :: "r"(id) : "memory");
}
__device__ __forceinline__ uint32_t pack_h2(float lo, float hi) {
    __half2 h = __floats2half2_rn(lo, hi);
    return *(uint32_t*)&h;
}

// ---------------- 0) convert weights to f16 ----------------
__global__ __launch_bounds__(256) void k_cvt_w(const float* __restrict__ Win,
                                               const float* __restrict__ Wout) {
    int idx = blockIdx.x * blockDim.x + threadIdx.x;
    const int N1 = 3 * Cc * Cc;
    const int N2 = Cc * Cc;
    if (idx < N1) g_Wt[idx] = __float2half_rn(Win[idx]);
    else if (idx < N1 + N2) g_Wot[idx - N1] = __float2half_rn(Wout[idx - N1]);
}

// ---------------- 1) unique tokens -> f16 ----------------
__global__ __launch_bounds__(256) void k_prep(const float* __restrict__ x,
                                              const float* __restrict__ q) {
    int idx = blockIdx.x * blockDim.x + threadIdx.x;
    if (idx >= CTXROWS * (Cc / 4)) return;
    int t  = idx / (Cc / 4);
    int c4 = idx % (Cc / 4);
    float4 val;
    if (t < Bb * NTOK) val = ((const float4*)(x + (size_t)t * Cc))[c4];
    else               val = ((const float4*)(q + (size_t)(t - Bb * NTOK) * Cc))[c4];
    __half2* dst = (__half2*)(g_tok + (size_t)t * Cc + c4 * 4);
    dst[0] = __floats2half2_rn(val.x, val.y);
    dst[1] = __floats2half2_rn(val.z, val.w);
}

// ---------------- 2) f16 mma.sync GEMM (NT), 3-stage + ldmatrix -------------
constexpr int RSH    = 72;
constexpr int TILEB  = 128 * RSH * 2;
constexpr int NSTAGE = 3;
constexpr int SMEM_GEMM = 2 * NSTAGE * TILEB;

__global__ __launch_bounds__(256, 2) void k_gemm_mma(const float* __restrict__ bias,
                                                     float* __restrict__ out,
                                                     int M, int Nn, int mode) {
    extern __shared__ char smc[];
    uint32_t sb = smem_u32(smc);
    const __half* A  = (mode == 0) ? g_tok : g_ctx;
    const __half* Bw = (mode == 0) ? g_Wt  : g_Wot;
    int tid = threadIdx.x, wid = tid >> 5, lane = tid & 31;
    int grp = lane >> 2, tig = lane & 3;
    int wm = wid & 3, wn = wid >> 2;
    int mb = blockIdx.y, nb = blockIdx.x;

    int m8 = lane >> 3, r8 = lane & 7;
    uint32_t aoff = (uint32_t)((wm * 32 + (m8 & 1) * 8 + r8) * (RSH * 2) + (m8 >> 1) * 16);
    uint32_t boff = (uint32_t)((wn * 64 + (m8 >> 1) * 8 + r8) * (RSH * 2) + (m8 & 1) * 16);

    float acc[2][8][4];
#pragma unroll
    for (int i = 0; i < 2; i++)
#pragma unroll
        for (int j = 0; j < 8; j++)
#pragma unroll
            for (int k = 0; k < 4; k++) acc[i][j][k] = 0.f;

    auto copy_tile = [&](int kc, int buf) {
        uint32_t sa  = sb + buf * TILEB;
        uint32_t sbm = sb + NSTAGE * TILEB + buf * TILEB;
#pragma unroll
        for (int i = 0; i < 4; i++) {
            int idx = tid * 4 + i;
            int r = idx >> 3, c8 = idx & 7;
            int gm = mb * 128 + r;
            if (gm >= M) gm = M - 1;
            cp16(sa + r * (RSH * 2) + c8 * 16, A + (size_t)gm * Cc + kc + c8 * 8);
            int gn = nb * 128 + r;
            cp16(sbm + r * (RSH * 2) + c8 * 16, Bw + (size_t)gn * Cc + kc + c8 * 8);
        }
        asm volatile("cp.async.commit_group;" ::: "memory");
    };

    const int NCH = Cc / 64;
    copy_tile(0, 0);
    copy_tile(64, 1);

    int buf = 0;
    for (int ci = 0; ci < NCH; ci++) {
        if (ci < NCH - 1)
            asm volatile("cp.async.wait_group 1;" ::: "memory");
        else
            asm volatile("cp.async.wait_group 0;" ::: "memory");
        __syncthreads();
        if (ci + 2 < NCH) {
            int nbuf = buf + 2; if (nbuf >= NSTAGE) nbuf -= NSTAGE;
            copy_tile((ci + 2) * 64, nbuf);
        }

        uint32_t sa  = sb + buf * TILEB + aoff;
        uint32_t sbm = sb + NSTAGE * TILEB + buf * TILEB + boff;
#pragma unroll
        for (int ks = 0; ks < 4; ks++) {
            uint32_t a[2][4];
            ldsm_x4(a[0], sa + ks * 32);
            ldsm_x4(a[1], sa + ks * 32 + 16 * (RSH * 2));
            uint32_t bf[4][4];
#pragma unroll
            for (int p = 0; p < 4; p++)
                ldsm_x4(bf[p], sbm + ks * 32 + p * (16 * (RSH * 2)));
#pragma unroll
            for (int p = 0; p < 4; p++)
#pragma unroll
                for (int j = 0; j < 2; j++) {
                    int nt = p * 2 + j;
                    mma_f16(acc[0][nt], a[0], bf[p][2 * j], bf[p][2 * j + 1]);
                    mma_f16(acc[1][nt], a[1], bf[p][2 * j], bf[p][2 * j + 1]);
                }
        }
        buf++; if (buf >= NSTAGE) buf = 0;
    }

#pragma unroll
    for (int mt = 0; mt < 2; mt++) {
        int m0 = mb * 128 + wm * 32 + mt * 16 + grp;
#pragma unroll
        for (int nt = 0; nt < 8; nt++) {
            int n0 = nb * 128 + wn * 64 + nt * 8 + tig * 2;
#pragma unroll
            for (int h = 0; h < 2; h++) {
                int m = m0 + h * 8;
                if (m >= M) continue;
                float v0 = acc[mt][nt][h * 2 + 0];
                float v1 = acc[mt][nt][h * 2 + 1];
                if (mode == 0) {
                    int b, p;
                    if (m < Bb * NTOK) { b = m >> 12; p = m & (NTOK - 1); }
                    else { int t = m - Bb * NTOK; b = t >> 6; p = NTOK + (t & (NQ - 1)); }
                    int which = n0 / Cc;
                    int hd = (n0 % Cc) / DH;
                    int dd = n0 % DH;
                    __half* dst = (which == 0) ? g_Q : (which == 1) ? g_K : g_V;
                    *(__half2*)(dst + (((size_t)(b * NH + hd)) * PROW + p) * DH + dd) =
                        __floats2half2_rn(v0, v1);
                } else {
                    *(float2*)(out + (size_t)m * Nn + n0) =
                        make_float2(v0 + bias[n0], v1 + bias[n0 + 1]);
                }
            }
        }
    }
}

// ---------------- 3) fused attention: group-decoupled pipelines -------------
constexpr int PADL   = 320;
constexpr int KQ_STR = 72;               // halves (144 B rows)
constexpr int O_STR  = 68;
constexpr int H_K    = 0;
constexpr int H_V    = PADL * KQ_STR;            // 23040
constexpr int H_Q    = 2 * PADL * KQ_STR;        // 46080; 4 grp x 2 buf x 16 x 72
constexpr int H_END  = H_Q + 4 * 2 * 16 * KQ_STR; // 55296 halves
constexpr int F_OB0  = (H_END * 2) / 4;          // float idx (16B aligned)
constexpr int F_OB1  = F_OB0 + 64 * O_STR;
constexpr int F_RMAX = F_OB1 + 64 * O_STR;
constexpr int F_RSUM = F_RMAX + 256;
constexpr int F_MSK  = F_RSUM + 256;
constexpr int SMEM_ATT = (F_MSK + PADL) * 4;     // ~148.7 KB

__global__ __launch_bounds__(512, 1) void k_attn_fused(const int* __restrict__ q_mask) {
    extern __shared__ char smc[];
    __half* Ks = (__half*)smc;
    __half* Vs = (__half*)smc + H_V;
    float* smf = (float*)smc;
    float* Ob0 = smf + F_OB0;
    float* Ob1 = smf + F_OB1;
    float* rmax = smf + F_RMAX;
    float* rsum = smf + F_RSUM;
    float* msk  = smf + F_MSK;
    uint32_t sbase = smem_u32(smc);

    int z  = blockIdx.x;
    int i  = z / NH;
    int hd = z % NH;
    int bp = i / R_;
    int w  = i % R_;
    int bq = i % Bb;
    int wy = w / NWX, wx = w % NWX;

    const __half* Kpix = g_K + ((size_t)(bp * NH + hd)) * PROW * DH;
    const __half* Kq   = g_K + ((size_t)(bq * NH + hd)) * PROW * DH + (size_t)NTOK * DH;
    const __half* Vpix = g_V + ((size_t)(bp * NH + hd)) * PROW * DH;
    const __half* Vq   = g_V + ((size_t)(bq * NH + hd)) * PROW * DH + (size_t)NTOK * DH;
    const __half* Qpix = g_Q + ((size_t)(bp * NH + hd)) * PROW * DH;
    const __half* Qq   = g_Q + ((size_t)(bq * NH + hd)) * PROW * DH + (size_t)NTOK * DH;

    int tid = threadIdx.x, wid = tid >> 5, lane = tid & 31;
    int grp = lane >> 2, tig = lane & 3;
    int wm = wid & 3, wn = wid >> 2;       // group wm (rows), key slice wn
    int gth = (wid >> 2) * 32 + lane;      // thread index within group (0-127)
    int lr0 = wm * 16 + grp, lr1 = lr0 + 8;
    int m8 = lane >> 3, r8 = lane & 7;
    int barid = wm + 1;

    // group-local Q buffer base (halves)
    int qgrp = H_Q + wm * (2 * 16 * KQ_STR);
    uint32_t q_off = sbase + (uint32_t)(qgrp * 2) +
                     (uint32_t)(((m8 & 1) * 8 + r8) * 144 + (m8 >> 1) * 16);
    uint32_t k_off = sbase +
                     (uint32_t)((wn * 80 + (m8 >> 1) * 8 + r8) * 144 + (m8 & 1) * 16);
    // V trans ldsm: matrices {key+0,key+8} x {dh,dh+8}
    uint32_t v_off = sbase + (uint32_t)(H_V * 2) +
                     (uint32_t)(((m8 & 1) * 8 + r8) * 144 + (m8 >> 1) * 16);

    // group-local Q prefetch: 128 threads cover 16 rows x 8 segs
    auto prefetch_q = [&](int qt, int buf) {
        int r = gth >> 3, c = gth & 7;
        int gr = qt * 64 + wm * 16 + r;
        const __half* src = Qpix;
        int sz = 0;
        if (gr < NWIN) {
            int py = wy * WSZ + gr / WSZ, px = wx * WSZ + gr % WSZ;
            if (py < HH && px < WW) { src = Qpix + (size_t)(py * WW + px) * DH + c * 8; sz = 16; }
        } else if (gr < LL) {
            src = Qq + (size_t)(gr - NWIN) * DH + c * 8; sz = 16;
        }
        uint32_t dst = sbase + (uint32_t)((qgrp + buf * (16 * KQ_STR)) * 2) + r * 144 + c * 16;
        cp16z(dst, src, sz);
        asm volatile("cp.async.commit_group;" ::: "memory");
    };

    prefetch_q(0, 0);

    for (int j = tid; j < PADL; j += 512) {
        float m = 0.f;
        if (j >= NWIN)
            m = (j < LL && q_mask[bq * NQ + j - NWIN] != 0) ? 0.f : -1e30f;
        msk[j] = m;
    }
    // K and V fills: identical row-major [key][dh], vectorized
    for (int idx = tid; idx < PADL * 8; idx += 512) {
        int r = idx >> 3, c = idx & 7;
        uint4 kv = make_uint4(0, 0, 0, 0), vv = make_uint4(0, 0, 0, 0);
        if (r < NWIN) {
            int py = wy * WSZ + r / WSZ, px = wx * WSZ + r % WSZ;
            if (py < HH && px < WW) {
                kv = ((const uint4*)(Kpix + (size_t)(py * WW + px) * DH))[c];
                vv = ((const uint4*)(Vpix + (size_t)(py * WW + px) * DH))[c];
            }
        } else if (r < LL) {
            kv = ((const uint4*)(Kq + (size_t)(r - NWIN) * DH))[c];
            vv = ((const uint4*)(Vq + (size_t)(r - NWIN) * DH))[c];
        }
        *(uint4*)(Ks + r * KQ_STR + c * 8) = kv;
        *(uint4*)(Vs + r * KQ_STR + c * 8) = vv;
    }
    __syncthreads();   // K/V/mask ready for all groups

    for (int qt = 0; qt < 5; qt++) {
        uint32_t qb = q_off + (uint32_t)((qt & 1) * (16 * KQ_STR * 2));
        asm volatile("cp.async.wait_group 0;" ::: "memory");
        bar_grp(barid);   // Q(qt) ready; prev-tile Ob/rsum consumed (group-local)

        // ---- S = Q @ K^T ----
        float sf[10][4];
#pragma unroll
        for (int t = 0; t < 10; t++)
#pragma unroll
            for (int k = 0; k < 4; k++) sf[t][k] = 0.f;
#pragma unroll
        for (int ks = 0; ks < 4; ks++) {
            uint32_t a[4];
            ldsm_x4(a, qb + ks * 32);
#pragma unroll
            for (int tp = 0; tp < 5; tp++) {
                uint32_t bb[4];
                ldsm_x4(bb, k_off + tp * (16 * 144) + ks * 32);
                mma_f16(sf[2 * tp],     a, bb[0], bb[1]);
                mma_f16(sf[2 * tp + 1], a, bb[2], bb[3]);
            }
        }

        // ---- scale + mask + rowmax ----
        float mx0 = -3e38f, mx1 = -3e38f;
#pragma unroll
        for (int t = 0; t < 10; t++) {
            int jb = wn * 80 + t * 8 + 2 * tig;
            float m0 = msk[jb], m1 = msk[jb + 1];
            sf[t][0] = sf[t][0] * 0.125f + m0;
            sf[t][1] = sf[t][1] * 0.125f + m1;
            sf[t][2] = sf[t][2] * 0.125f + m0;
            sf[t][3] = sf[t][3] * 0.125f + m1;
            mx0 = fmaxf(mx0, fmaxf(sf[t][0], sf[t][1]));
            mx1 = fmaxf(mx1, fmaxf(sf[t][2], sf[t][3]));
        }
        mx0 = fmaxf(mx0, __shfl_xor_sync(~0u, mx0, 1));
        mx0 = fmaxf(mx0, __shfl_xor_sync(~0u, mx0, 2));
        mx1 = fmaxf(mx1, __shfl_xor_sync(~0u, mx1, 1));
        mx1 = fmaxf(mx1, __shfl_xor_sync(~0u, mx1, 2));
        if (tig == 0) {
            rmax[lr0 * 4 + wn] = mx0;
            rmax[lr1 * 4 + wn] = mx1;
        }
        bar_grp(barid);
        float4 r40 = *(float4*)(rmax + lr0 * 4);
        float4 r41 = *(float4*)(rmax + lr1 * 4);
        float M0 = fmaxf(fmaxf(r40.x, r40.y), fmaxf(r40.z, r40.w));
        float M1 = fmaxf(fmaxf(r41.x, r41.y), fmaxf(r41.z, r41.w));

        if (qt + 1 < 5) prefetch_q(qt + 1, (qt + 1) & 1);

        // ---- exp + row sums; pack P ----
        float s0 = 0.f, s1 = 0.f;
        uint32_t pk[10][2];
#pragma unroll
        for (int t = 0; t < 10; t++) {
            float e0 = __expf(sf[t][0] - M0), e1 = __expf(sf[t][1] - M0);
            float e2 = __expf(sf[t][2] - M1), e3 = __expf(sf[t][3] - M1);
            s0 += e0 + e1; s1 += e2 + e3;
            pk[t][0] = pack_h2(e0, e1);
            pk[t][1] = pack_h2(e2, e3);
        }
        s0 += __shfl_xor_sync(~0u, s0, 1);
        s0 += __shfl_xor_sync(~0u, s0, 2);
        s1 += __shfl_xor_sync(~0u, s1, 1);
        s1 += __shfl_xor_sync(~0u, s1, 2);
        if (tig == 0) {
            rsum[lr0 * 4 + wn] = s0;
            rsum[lr1 * 4 + wn] = s1;
        }

        // ---- O_partial = P @ V (ldsm.trans B-frags) ----
        float of[8][4];
#pragma unroll
        for (int nt = 0; nt < 8; nt++)
#pragma unroll
            for (int k = 0; k < 4; k++) of[nt][k] = 0.f;
#pragma unroll
        for (int kt = 0; kt < 5; kt++) {
            uint32_t a[4];
            a[0] = pk[2 * kt][0];
            a[1] = pk[2 * kt][1];
            a[2] = pk[2 * kt + 1][0];
            a[3] = pk[2 * kt + 1][1];
            uint32_t vb = v_off + (uint32_t)((wn * 80 + kt * 16) * 144);
#pragma unroll
            for (int v = 0; v < 4; v++) {
                uint32_t vf[4];
                ldsm_x4t(vf, vb + v * 32);
                mma_f16(of[2 * v],     a, vf[0], vf[1]);
                mma_f16(of[2 * v + 1], a, vf[2], vf[3]);
            }
        }

        // ---- combine 4 key-slices (group-local) ----
        if (wn < 2) {
            float* Ob = (wn == 0) ? Ob0 : Ob1;
#pragma unroll
            for (int nt = 0; nt < 8; nt++) {
                int c = nt * 8 + 2 * tig;
                *(float2*)(Ob + lr0 * O_STR + c) = make_float2(of[nt][0], of[nt][1]);
                *(float2*)(Ob + lr1 * O_STR + c) = make_float2(of[nt][2], of[nt][3]);
            }
        }
        bar_grp(barid);
        if (wn >= 2) {
            float* Ob = (wn == 2) ? Ob0 : Ob1;
#pragma unroll
            for (int nt = 0; nt < 8; nt++) {
                int c = nt * 8 + 2 * tig;
                float2 p0 = *(float2*)(Ob + lr0 * O_STR + c);
                float2 p1 = *(float2*)(Ob + lr1 * O_STR + c);
                *(float2*)(Ob + lr0 * O_STR + c) =
                    make_float2(p0.x + of[nt][0], p0.y + of[nt][1]);
                *(float2*)(Ob + lr1 * O_STR + c) =
                    make_float2(p1.x + of[nt][2], p1.y + of[nt][3]);
            }
        }
        bar_grp(barid);

        // ---- final merge + normalize + scatter (group-local rows) ----
        {
            int r = wm * 16 + (gth >> 3);
            int c0 = (gth & 7) * 8;
            int grow = qt * 64 + r;
            if (grow < LL) {
                float4 s4 = *(float4*)(rsum + r * 4);
                float inv = 1.f / (s4.x + s4.y + s4.z + s4.w);
                float4 x0 = *(float4*)(Ob0 + r * O_STR + c0);
                float4 x1 = *(float4*)(Ob1 + r * O_STR + c0);
                float4 y0 = *(float4*)(Ob0 + r * O_STR + c0 + 4);
                float4 y1 = *(float4*)(Ob1 + r * O_STR + c0 + 4);
                __half2 h0 = __floats2half2_rn((x0.x + x1.x) * inv, (x0.y + x1.y) * inv);
                __half2 h1 = __floats2half2_rn((x0.z + x1.z) * inv, (x0.w + x1.w) * inv);
                __half2 h2 = __floats2half2_rn((y0.x + y1.x) * inv, (y0.y + y1.y) * inv);
                __half2 h3 = __floats2half2_rn((y0.z + y1.z) * inv, (y0.w + y1.w) * inv);
                __half2* dst = nullptr;
                if (grow < NWIN) {
                    int py = wy * WSZ + grow / WSZ, px = wx * WSZ + grow % WSZ;
                    if (py < HH && px < WW)
                        dst = (__half2*)(g_ctx + ((size_t)bp * NTOK + py * WW + px) * Cc
                                         + hd * DH + c0);
                } else {
                    dst = (__half2*)(g_Oq + ((size_t)i * NQ + (grow - NWIN)) * Cc
                                     + hd * DH + c0);
                }
                if (dst) { dst[0] = h0; dst[1] = h1; dst[2] = h2; dst[3] = h3; }
            }
        }
    }
}

// ---------------- 4) ctx rows for queries: mean over windows ----------------
__global__ __launch_bounds__(256) void k_ctx_q() {
    int idx = blockIdx.x * blockDim.x + threadIdx.x;
    const int SEG = Cc / 2;
    if (idx >= Bb * NQ * SEG) return;
    int j = idx / SEG, c = idx % SEG;
    int b = j / NQ, lq = j % NQ;
    float a0 = 0.f, a1 = 0.f;
#pragma unroll
    for (int w = 0; w < R_; w++) {
        int i = w * Bb + b;
        __half2 v = ((const __half2*)(g_Oq + ((size_t)i * NQ + lq) * Cc))[c];
        float2 f = __half22float2(v);
        a0 += f.x; a1 += f.y;
    }
    const float inv = 1.f / (float)R_;
    ((__half2*)(g_ctx + (size_t)(Bb * NTOK + j) * Cc))[c] =
        __floats2half2_rn(a0 * inv, a1 * inv);
}

// ---------------- launch ----------------
extern "C" void kernel_launch(void* const* d_in, const int* in_sizes, int n_in,
                              void* d_out, int out_size) {
    const float* x     = (const float*)d_in[0];
    const float* q     = (const float*)d_in[1];
    const float* W_in  = (const float*)d_in[2];
    const float* W_out = (const float*)d_in[3];
    const float* b_out = (const float*)d_in[4];
    const int*   qmask = (const int*)d_in[5];
    float* out = (float*)d_out;

    static bool attr_set = false;
    if (!attr_set) {
        cudaFuncSetAttribute(k_gemm_mma, cudaFuncAttributeMaxDynamicSharedMemorySize,
                             SMEM_GEMM);
        cudaFuncSetAttribute(k_attn_fused, cudaFuncAttributeMaxDynamicSharedMemorySize,
                             SMEM_ATT);
        attr_set = true;
    }

    k_cvt_w<<<(4 * Cc * Cc + 255) / 256, 256>>>(W_in, W_out);
    k_prep<<<(CTXROWS * (Cc / 4) + 255) / 256, 256>>>(x, q);

    dim3 g_qkv(3 * Cc / 128, CTXROWS / 128);
    k_gemm_mma<<<g_qkv, 256, SMEM_GEMM>>>(nullptr, nullptr, CTXROWS, 3 * Cc, 0);

    k_attn_fused<<<BW * NH, 512, SMEM_ATT>>>(qmask);

    k_ctx_q<<<(Bb * NQ * (Cc / 2) + 255) / 256, 256>>>();

    dim3 g_out(Cc / 128, CTXROWS / 128);
    k_gemm_mma<<<g_out, 256, SMEM_GEMM>>>(b_out, out, CTXROWS, Cc, 1);
}

// round 14
// speedup vs baseline: 6.8918x; 1.0155x over previous
#include <cuda_runtime.h>
#include <cuda_fp16.h>
#include <cstdint>

// ---------------- problem constants ----------------
constexpr int Bb   = 4;
constexpr int NTOK = 4096;
constexpr int Cc   = 768;
constexpr int NQ   = 64;
constexpr int HH   = 64, WW = 64;
constexpr int WSZ  = 14;
constexpr int NH   = 12, DH = 64;
constexpr int NWX  = 5;
constexpr int R_   = 25;
constexpr int BW   = Bb * R_;           // 100
constexpr int NWIN = WSZ * WSZ;         // 196
constexpr int LL   = NWIN + NQ;         // 260
constexpr int CTXROWS = Bb * NTOK + Bb * NQ; // 16640
constexpr int PROW = NTOK + NQ;         // 4160 rows per (b,head)

// ---------------- scratch (f16 intermediates) ----------------
__device__ __half g_tok[(size_t)CTXROWS * Cc];
__device__ __half g_Q[(size_t)Bb * NH * PROW * DH];
__device__ __half g_K[(size_t)Bb * NH * PROW * DH];
__device__ __half g_V[(size_t)Bb * NH * PROW * DH];
__device__ __half g_Oq[(size_t)BW * NQ * Cc];
__device__ __half g_ctx[(size_t)CTXROWS * Cc];
__device__ __half g_Wt[(size_t)(3 * Cc) * Cc];
__device__ __half g_Wot[(size_t)Cc * Cc];

// ---------------- helpers ----------------
__device__ __forceinline__ uint32_t smem_u32(const void* p) {
    uint32_t a;
    asm("{ .reg .u64 t; cvta.to.shared.u64 t, %1; cvt.u32.u64 %0, t; }"
        : "=r"(a) : "l"(p));
    return a;
}
__device__ __forceinline__ void cp16(uint32_t s, const void* g) {
    asm volatile("cp.async.cg.shared.global [%0], [%1], 16;" :: "r"(s), "l"(g) : "memory");
}
__device__ __forceinline__ void cp16z(uint32_t s, const void* g, int sz) {
    asm volatile("cp.async.cg.shared.global [%0], [%1], 16, %2;"
                 :: "r"(s), "l"(g), "r"(sz) : "memory");
}
__device__ __forceinline__ void mma_f16(float* c, const uint32_t* a,
                                        uint32_t b0, uint32_t b1) {
    asm volatile("mma.sync.aligned.m16n8k16.row.col.f32.f16.f16.f32 "
                 "{%0,%1,%2,%3}, {%4,%5,%6,%7}, {%8,%9}, {%0,%1,%2,%3};"
                 : "+f"(c[0]), "+f"(c[1]), "+f"(c[2]), "+f"(c[3])
                 : "r"(a[0]), "r"(a[1]), "r"(a[2]), "r"(a[3]), "r"(b0), "r"(b1));
}
__device__ __forceinline__ void ldsm_x4(uint32_t* r, uint32_t addr) {
    asm volatile("ldmatrix.sync.aligned.m8n8.x4.shared.b16 {%0,%1,%2,%3}, [%4];"
                 : "=r"(r[0]), "=r"(r[1]), "=r"(r[2]), "=r"(r[3]) : "r"(addr));
}
__device__ __forceinline__ void ldsm_x4t(uint32_t* r, uint32_t addr) {
    asm volatile("ldmatrix.sync.aligned.m8n8.x4.trans.shared.b16 {%0,%1,%2,%3}, [%4];"
                 : "=r"(r[0]), "=r"(r[1]), "=r"(r[2]), "=r"(r[3]) : "r"(addr));
}
__device__ __forceinline__ void bar_grp(int id) {
    asm volatile("bar.sync %0, 128;" :: "r"(id) : "memory");
}
// packed 2^x on half2: x <= 0 (masked -> -inf -> 0)
__device__ __forceinline__ uint32_t ex2_h2(float lo, float hi) {
    __half2 h = __floats2half2_rn(lo, hi);
    uint32_t u = *(uint32_t*)&h, r;
    asm("ex2.approx.f16x2 %0, %1;" : "=r"(r) : "r"(u));
    return r;
}

// ---------------- 0) convert weights to f16 ----------------
__global__ __launch_bounds__(256) void k_cvt_w(const float* __restrict__ Win,
                                               const float* __restrict__ Wout) {
    int idx = blockIdx.x * blockDim.x + threadIdx.x;
    const int N1 = 3 * Cc * Cc;
    const int N2 = Cc * Cc;
    if (idx < N1) g_Wt[idx] = __float2half_rn(Win[idx]);
    else if (idx < N1 + N2) g_Wot[idx - N1] = __float2half_rn(Wout[idx - N1]);
}

// ---------------- 1) unique tokens -> f16 ----------------
__global__ __launch_bounds__(256) void k_prep(const float* __restrict__ x,
                                              const float* __restrict__ q) {
    int idx = blockIdx.x * blockDim.x + threadIdx.x;
    if (idx >= CTXROWS * (Cc / 4)) return;
    int t  = idx / (Cc / 4);
    int c4 = idx % (Cc / 4);
    float4 val;
    if (t < Bb * NTOK) val = ((const float4*)(x + (size_t)t * Cc))[c4];
    else               val = ((const float4*)(q + (size_t)(t - Bb * NTOK) * Cc))[c4];
    __half2* dst = (__half2*)(g_tok + (size_t)t * Cc + c4 * 4);
    dst[0] = __floats2half2_rn(val.x, val.y);
    dst[1] = __floats2half2_rn(val.z, val.w);
}

// ---------------- 2) f16 mma.sync GEMM (NT), 3-stage + ldmatrix -------------
constexpr int RSH    = 72;
constexpr int TILEB  = 128 * RSH * 2;
constexpr int NSTAGE = 3;
constexpr int SMEM_GEMM = 2 * NSTAGE * TILEB;

__global__ __launch_bounds__(256, 2) void k_gemm_mma(const float* __restrict__ bias,
                                                     float* __restrict__ out,
                                                     int M, int Nn, int mode) {
    extern __shared__ char smc[];
    uint32_t sb = smem_u32(smc);
    const __half* A  = (mode == 0) ? g_tok : g_ctx;
    const __half* Bw = (mode == 0) ? g_Wt  : g_Wot;
    int tid = threadIdx.x, wid = tid >> 5, lane = tid & 31;
    int grp = lane >> 2, tig = lane & 3;
    int wm = wid & 3, wn = wid >> 2;
    int mb = blockIdx.y, nb = blockIdx.x;

    int m8 = lane >> 3, r8 = lane & 7;
    uint32_t aoff = (uint32_t)((wm * 32 + (m8 & 1) * 8 + r8) * (RSH * 2) + (m8 >> 1) * 16);
    uint32_t boff = (uint32_t)((wn * 64 + (m8 >> 1) * 8 + r8) * (RSH * 2) + (m8 & 1) * 16);

    float acc[2][8][4];
#pragma unroll
    for (int i = 0; i < 2; i++)
#pragma unroll
        for (int j = 0; j < 8; j++)
#pragma unroll
            for (int k = 0; k < 4; k++) acc[i][j][k] = 0.f;

    auto copy_tile = [&](int kc, int buf) {
        uint32_t sa  = sb + buf * TILEB;
        uint32_t sbm = sb + NSTAGE * TILEB + buf * TILEB;
#pragma unroll
        for (int i = 0; i < 4; i++) {
            int idx = tid * 4 + i;
            int r = idx >> 3, c8 = idx & 7;
            int gm = mb * 128 + r;
            if (gm >= M) gm = M - 1;
            cp16(sa + r * (RSH * 2) + c8 * 16, A + (size_t)gm * Cc + kc + c8 * 8);
            int gn = nb * 128 + r;
            cp16(sbm + r * (RSH * 2) + c8 * 16, Bw + (size_t)gn * Cc + kc + c8 * 8);
        }
        asm volatile("cp.async.commit_group;" ::: "memory");
    };

    const int NCH = Cc / 64;
    copy_tile(0, 0);
    copy_tile(64, 1);

    int buf = 0;
    for (int ci = 0; ci < NCH; ci++) {
        if (ci < NCH - 1)
            asm volatile("cp.async.wait_group 1;" ::: "memory");
        else
            asm volatile("cp.async.wait_group 0;" ::: "memory");
        __syncthreads();
        if (ci + 2 < NCH) {
            int nbuf = buf + 2; if (nbuf >= NSTAGE) nbuf -= NSTAGE;
            copy_tile((ci + 2) * 64, nbuf);
        }

        uint32_t sa  = sb + buf * TILEB + aoff;
        uint32_t sbm = sb + NSTAGE * TILEB + buf * TILEB + boff;
#pragma unroll
        for (int ks = 0; ks < 4; ks++) {
            uint32_t a[2][4];
            ldsm_x4(a[0], sa + ks * 32);
            ldsm_x4(a[1], sa + ks * 32 + 16 * (RSH * 2));
            uint32_t bf[4][4];
#pragma unroll
            for (int p = 0; p < 4; p++)
                ldsm_x4(bf[p], sbm + ks * 32 + p * (16 * (RSH * 2)));
#pragma unroll
            for (int p = 0; p < 4; p++)
#pragma unroll
                for (int j = 0; j < 2; j++) {
                    int nt = p * 2 + j;
                    mma_f16(acc[0][nt], a[0], bf[p][2 * j], bf[p][2 * j + 1]);
                    mma_f16(acc[1][nt], a[1], bf[p][2 * j], bf[p][2 * j + 1]);
                }
        }
        buf++; if (buf >= NSTAGE) buf = 0;
    }

#pragma unroll
    for (int mt = 0; mt < 2; mt++) {
        int m0 = mb * 128 + wm * 32 + mt * 16 + grp;
#pragma unroll
        for (int nt = 0; nt < 8; nt++) {
            int n0 = nb * 128 + wn * 64 + nt * 8 + tig * 2;
#pragma unroll
            for (int h = 0; h < 2; h++) {
                int m = m0 + h * 8;
                if (m >= M) continue;
                float v0 = acc[mt][nt][h * 2 + 0];
                float v1 = acc[mt][nt][h * 2 + 1];
                if (mode == 0) {
                    int b, p;
                    if (m < Bb * NTOK) { b = m >> 12; p = m & (NTOK - 1); }
                    else { int t = m - Bb * NTOK; b = t >> 6; p = NTOK + (t & (NQ - 1)); }
                    int which = n0 / Cc;
                    int hd = (n0 % Cc) / DH;
                    int dd = n0 % DH;
                    __half* dst = (which == 0) ? g_Q : (which == 1) ? g_K : g_V;
                    *(__half2*)(dst + (((size_t)(b * NH + hd)) * PROW + p) * DH + dd) =
                        __floats2half2_rn(v0, v1);
                } else {
                    *(float2*)(out + (size_t)m * Nn + n0) =
                        make_float2(v0 + bias[n0], v1 + bias[n0 + 1]);
                }
            }
        }
    }
}

// ---------------- 3) fused attention: group pipelines + f16x2 ex2 -----------
constexpr int PADL   = 320;
constexpr int KQ_STR = 72;
constexpr int O_STR  = 68;
constexpr int H_V    = PADL * KQ_STR;
constexpr int H_Q    = 2 * PADL * KQ_STR;
constexpr int H_END  = H_Q + 4 * 2 * 16 * KQ_STR;
constexpr int F_OB0  = (H_END * 2) / 4;
constexpr int F_OB1  = F_OB0 + 64 * O_STR;
constexpr int F_RMAX = F_OB1 + 64 * O_STR;
constexpr int F_RSUM = F_RMAX + 256;
constexpr int F_MSK  = F_RSUM + 256;
constexpr int SMEM_ATT = (F_MSK + PADL) * 4;

// 0.125 * log2(e)
#define SCL2 0.18033688011112042f

__global__ __launch_bounds__(512, 1) void k_attn_fused(const int* __restrict__ q_mask) {
    extern __shared__ char smc[];
    __half* Ks = (__half*)smc;
    __half* Vs = (__half*)smc + H_V;
    float* smf = (float*)smc;
    float* Ob0 = smf + F_OB0;
    float* Ob1 = smf + F_OB1;
    float* rmax = smf + F_RMAX;
    float* rsum = smf + F_RSUM;
    float* msk  = smf + F_MSK;
    uint32_t sbase = smem_u32(smc);

    int z  = blockIdx.x;
    int i  = z / NH;
    int hd = z % NH;
    int bp = i / R_;
    int w  = i % R_;
    int bq = i % Bb;
    int wy = w / NWX, wx = w % NWX;

    const __half* Kpix = g_K + ((size_t)(bp * NH + hd)) * PROW * DH;
    const __half* Kq   = g_K + ((size_t)(bq * NH + hd)) * PROW * DH + (size_t)NTOK * DH;
    const __half* Vpix = g_V + ((size_t)(bp * NH + hd)) * PROW * DH;
    const __half* Vq   = g_V + ((size_t)(bq * NH + hd)) * PROW * DH + (size_t)NTOK * DH;
    const __half* Qpix = g_Q + ((size_t)(bp * NH + hd)) * PROW * DH;
    const __half* Qq   = g_Q + ((size_t)(bq * NH + hd)) * PROW * DH + (size_t)NTOK * DH;

    int tid = threadIdx.x, wid = tid >> 5, lane = tid & 31;
    int grp = lane >> 2, tig = lane & 3;
    int wm = wid & 3, wn = wid >> 2;
    int gth = (wid >> 2) * 32 + lane;
    int lr0 = wm * 16 + grp, lr1 = lr0 + 8;
    int m8 = lane >> 3, r8 = lane & 7;
    int barid = wm + 1;

    int qgrp = H_Q + wm * (2 * 16 * KQ_STR);
    uint32_t q_off = sbase + (uint32_t)(qgrp * 2) +
                     (uint32_t)(((m8 & 1) * 8 + r8) * 144 + (m8 >> 1) * 16);
    uint32_t k_off = sbase +
                     (uint32_t)((wn * 80 + (m8 >> 1) * 8 + r8) * 144 + (m8 & 1) * 16);
    uint32_t v_off = sbase + (uint32_t)(H_V * 2) +
                     (uint32_t)(((m8 & 1) * 8 + r8) * 144 + (m8 >> 1) * 16);

    auto prefetch_q = [&](int qt, int buf) {
        int r = gth >> 3, c = gth & 7;
        int gr = qt * 64 + wm * 16 + r;
        const __half* src = Qpix;
        int sz = 0;
        if (gr < NWIN) {
            int py = wy * WSZ + gr / WSZ, px = wx * WSZ + gr % WSZ;
            if (py < HH && px < WW) { src = Qpix + (size_t)(py * WW + px) * DH + c * 8; sz = 16; }
        } else if (gr < LL) {
            src = Qq + (size_t)(gr - NWIN) * DH + c * 8; sz = 16;
        }
        uint32_t dst = sbase + (uint32_t)((qgrp + buf * (16 * KQ_STR)) * 2) + r * 144 + c * 16;
        cp16z(dst, src, sz);
        asm volatile("cp.async.commit_group;" ::: "memory");
    };

    prefetch_q(0, 0);

    for (int j = tid; j < PADL; j += 512) {
        float m = 0.f;
        if (j >= NWIN)
            m = (j < LL && q_mask[bq * NQ + j - NWIN] != 0) ? 0.f : -1e30f;
        msk[j] = m;
    }
    for (int idx = tid; idx < PADL * 8; idx += 512) {
        int r = idx >> 3, c = idx & 7;
        uint4 kv = make_uint4(0, 0, 0, 0), vv = make_uint4(0, 0, 0, 0);
        if (r < NWIN) {
            int py = wy * WSZ + r / WSZ, px = wx * WSZ + r % WSZ;
            if (py < HH && px < WW) {
                kv = ((const uint4*)(Kpix + (size_t)(py * WW + px) * DH))[c];
                vv = ((const uint4*)(Vpix + (size_t)(py * WW + px) * DH))[c];
            }
        } else if (r < LL) {
            kv = ((const uint4*)(Kq + (size_t)(r - NWIN) * DH))[c];
            vv = ((const uint4*)(Vq + (size_t)(r - NWIN) * DH))[c];
        }
        *(uint4*)(Ks + r * KQ_STR + c * 8) = kv;
        *(uint4*)(Vs + r * KQ_STR + c * 8) = vv;
    }
    __syncthreads();

    for (int qt = 0; qt < 5; qt++) {
        uint32_t qb = q_off + (uint32_t)((qt & 1) * (16 * KQ_STR * 2));
        asm volatile("cp.async.wait_group 0;" ::: "memory");
        bar_grp(barid);

        // ---- S = Q @ K^T ----
        float sf[10][4];
#pragma unroll
        for (int t = 0; t < 10; t++)
#pragma unroll
            for (int k = 0; k < 4; k++) sf[t][k] = 0.f;
#pragma unroll
        for (int ks = 0; ks < 4; ks++) {
            uint32_t a[4];
            ldsm_x4(a, qb + ks * 32);
#pragma unroll
            for (int tp = 0; tp < 5; tp++) {
                uint32_t bb[4];
                ldsm_x4(bb, k_off + tp * (16 * 144) + ks * 32);
                mma_f16(sf[2 * tp],     a, bb[0], bb[1]);
                mma_f16(sf[2 * tp + 1], a, bb[2], bb[3]);
            }
        }

        // ---- scale (log2 domain) + mask + rowmax ----
        float mx0 = -3e38f, mx1 = -3e38f;
#pragma unroll
        for (int t = 0; t < 10; t++) {
            int jb = wn * 80 + t * 8 + 2 * tig;
            float m0 = msk[jb], m1 = msk[jb + 1];
            sf[t][0] = sf[t][0] * SCL2 + m0;
            sf[t][1] = sf[t][1] * SCL2 + m1;
            sf[t][2] = sf[t][2] * SCL2 + m0;
            sf[t][3] = sf[t][3] * SCL2 + m1;
            mx0 = fmaxf(mx0, fmaxf(sf[t][0], sf[t][1]));
            mx1 = fmaxf(mx1, fmaxf(sf[t][2], sf[t][3]));
        }
        mx0 = fmaxf(mx0, __shfl_xor_sync(~0u, mx0, 1));
        mx0 = fmaxf(mx0, __shfl_xor_sync(~0u, mx0, 2));
        mx1 = fmaxf(mx1, __shfl_xor_sync(~0u, mx1, 1));
        mx1 = fmaxf(mx1, __shfl_xor_sync(~0u, mx1, 2));
        if (tig == 0) {
            rmax[lr0 * 4 + wn] = mx0;
            rmax[lr1 * 4 + wn] = mx1;
        }
        bar_grp(barid);
        float4 r40 = *(float4*)(rmax + lr0 * 4);
        float4 r41 = *(float4*)(rmax + lr1 * 4);
        float M0 = fmaxf(fmaxf(r40.x, r40.y), fmaxf(r40.z, r40.w));
        float M1 = fmaxf(fmaxf(r41.x, r41.y), fmaxf(r41.z, r41.w));

        if (qt + 1 < 5) prefetch_q(qt + 1, (qt + 1) & 1);

        // ---- P = 2^(s - M) via f16x2 ex2; row sums from exact P ----
        float s0 = 0.f, s1 = 0.f;
        uint32_t pk[10][2];
#pragma unroll
        for (int t = 0; t < 10; t++) {
            uint32_t p0 = ex2_h2(sf[t][0] - M0, sf[t][1] - M0);
            uint32_t p1 = ex2_h2(sf[t][2] - M1, sf[t][3] - M1);
            pk[t][0] = p0;
            pk[t][1] = p1;
            float2 f0 = __half22float2(*(__half2*)&p0);
            float2 f1 = __half22float2(*(__half2*)&p1);
            s0 += f0.x + f0.y;
            s1 += f1.x + f1.y;
        }
        s0 += __shfl_xor_sync(~0u, s0, 1);
        s0 += __shfl_xor_sync(~0u, s0, 2);
        s1 += __shfl_xor_sync(~0u, s1, 1);
        s1 += __shfl_xor_sync(~0u, s1, 2);
        if (tig == 0) {
            rsum[lr0 * 4 + wn] = s0;
            rsum[lr1 * 4 + wn] = s1;
        }

        // ---- O_partial = P @ V (ldsm.trans B-frags) ----
        float of[8][4];
#pragma unroll
        for (int nt = 0; nt < 8; nt++)
#pragma unroll
            for (int k = 0; k < 4; k++) of[nt][k] = 0.f;
#pragma unroll
        for (int kt = 0; kt < 5; kt++) {
            uint32_t a[4];
            a[0] = pk[2 * kt][0];
            a[1] = pk[2 * kt][1];
            a[2] = pk[2 * kt + 1][0];
            a[3] = pk[2 * kt + 1][1];
            uint32_t vb = v_off + (uint32_t)((wn * 80 + kt * 16) * 144);
#pragma unroll
            for (int v = 0; v < 4; v++) {
                uint32_t vf[4];
                ldsm_x4t(vf, vb + v * 32);
                mma_f16(of[2 * v],     a, vf[0], vf[1]);
                mma_f16(of[2 * v + 1], a, vf[2], vf[3]);
            }
        }

        // ---- combine 4 key-slices (group-local) ----
        if (wn < 2) {
            float* Ob = (wn == 0) ? Ob0 : Ob1;
#pragma unroll
            for (int nt = 0; nt < 8; nt++) {
                int c = nt * 8 + 2 * tig;
                *(float2*)(Ob + lr0 * O_STR + c) = make_float2(of[nt][0], of[nt][1]);
                *(float2*)(Ob + lr1 * O_STR + c) = make_float2(of[nt][2], of[nt][3]);
            }
        }
        bar_grp(barid);
        if (wn >= 2) {
            float* Ob = (wn == 2) ? Ob0 : Ob1;
#pragma unroll
            for (int nt = 0; nt < 8; nt++) {
                int c = nt * 8 + 2 * tig;
                float2 p0 = *(float2*)(Ob + lr0 * O_STR + c);
                float2 p1 = *(float2*)(Ob + lr1 * O_STR + c);
                *(float2*)(Ob + lr0 * O_STR + c) =
                    make_float2(p0.x + of[nt][0], p0.y + of[nt][1]);
                *(float2*)(Ob + lr1 * O_STR + c) =
                    make_float2(p1.x + of[nt][2], p1.y + of[nt][3]);
            }
        }
        bar_grp(barid);

        // ---- final merge + normalize + scatter (group-local rows) ----
        {
            int r = wm * 16 + (gth >> 3);
            int c0 = (gth & 7) * 8;
            int grow = qt * 64 + r;
            if (grow < LL) {
                float4 s4 = *(float4*)(rsum + r * 4);
                float inv = 1.f / (s4.x + s4.y + s4.z + s4.w);
                float4 x0 = *(float4*)(Ob0 + r * O_STR + c0);
                float4 x1 = *(float4*)(Ob1 + r * O_STR + c0);
                float4 y0 = *(float4*)(Ob0 + r * O_STR + c0 + 4);
                float4 y1 = *(float4*)(Ob1 + r * O_STR + c0 + 4);
                __half2 h0 = __floats2half2_rn((x0.x + x1.x) * inv, (x0.y + x1.y) * inv);
                __half2 h1 = __floats2half2_rn((x0.z + x1.z) * inv, (x0.w + x1.w) * inv);
                __half2 h2 = __floats2half2_rn((y0.x + y1.x) * inv, (y0.y + y1.y) * inv);
                __half2 h3 = __floats2half2_rn((y0.z + y1.z) * inv, (y0.w + y1.w) * inv);
                __half2* dst = nullptr;
                if (grow < NWIN) {
                    int py = wy * WSZ + grow / WSZ, px = wx * WSZ + grow % WSZ;
                    if (py < HH && px < WW)
                        dst = (__half2*)(g_ctx + ((size_t)bp * NTOK + py * WW + px) * Cc
                                         + hd * DH + c0);
                } else {
                    dst = (__half2*)(g_Oq + ((size_t)i * NQ + (grow - NWIN)) * Cc
                                     + hd * DH + c0);
                }
                if (dst) { dst[0] = h0; dst[1] = h1; dst[2] = h2; dst[3] = h3; }
            }
        }
    }
}

// ---------------- 4) ctx rows for queries: mean over windows ----------------
__global__ __launch_bounds__(256) void k_ctx_q() {
    int idx = blockIdx.x * blockDim.x + threadIdx.x;
    const int SEG = Cc / 2;
    if (idx >= Bb * NQ * SEG) return;
    int j = idx / SEG, c = idx % SEG;
    int b = j / NQ, lq = j % NQ;
    float a0 = 0.f, a1 = 0.f;
#pragma unroll
    for (int w = 0; w < R_; w++) {
        int i = w * Bb + b;
        __half2 v = ((const __half2*)(g_Oq + ((size_t)i * NQ + lq) * Cc))[c];
        float2 f = __half22float2(v);
        a0 += f.x; a1 += f.y;
    }
    const float inv = 1.f / (float)R_;
    ((__half2*)(g_ctx + (size_t)(Bb * NTOK + j) * Cc))[c] =
        __floats2half2_rn(a0 * inv, a1 * inv);
}

// ---------------- launch ----------------
extern "C" void kernel_launch(void* const* d_in, const int* in_sizes, int n_in,
                              void* d_out, int out_size) {
    const float* x     = (const float*)d_in[0];
    const float* q     = (const float*)d_in[1];
    const float* W_in  = (const float*)d_in[2];
    const float* W_out = (const float*)d_in[3];
    const float* b_out = (const float*)d_in[4];
    const int*   qmask = (const int*)d_in[5];
    float* out = (float*)d_out;

    static bool attr_set = false;
    if (!attr_set) {
        cudaFuncSetAttribute(k_gemm_mma, cudaFuncAttributeMaxDynamicSharedMemorySize,
                             SMEM_GEMM);
        cudaFuncSetAttribute(k_attn_fused, cudaFuncAttributeMaxDynamicSharedMemorySize,
                             SMEM_ATT);
        attr_set = true;
    }

    k_cvt_w<<<(4 * Cc * Cc + 255) / 256, 256>>>(W_in, W_out);
    k_prep<<<(CTXROWS * (Cc / 4) + 255) / 256, 256>>>(x, q);

    dim3 g_qkv(3 * Cc / 128, CTXROWS / 128);
    k_gemm_mma<<<g_qkv, 256, SMEM_GEMM>>>(nullptr, nullptr, CTXROWS, 3 * Cc, 0);

    k_attn_fused<<<BW * NH, 512, SMEM_ATT>>>(qmask);

    k_ctx_q<<<(Bb * NQ * (Cc / 2) + 255) / 256, 256>>>();

    dim3 g_out(Cc / 128, CTXROWS / 128);
    k_gemm_mma<<<g_out, 256, SMEM_GEMM>>>(b_out, out, CTXROWS, Cc, 1);
}

// round 15
// speedup vs baseline: 6.9819x; 1.0131x over previous
#include <cuda_runtime.h>
#include <cuda_fp16.h>
#include <cstdint>

// ---------------- problem constants ----------------
constexpr int Bb   = 4;
constexpr int NTOK = 4096;
constexpr int Cc   = 768;
constexpr int NQ   = 64;
constexpr int HH   = 64, WW = 64;
constexpr int WSZ  = 14;
constexpr int NH   = 12, DH = 64;
constexpr int NWX  = 5;
constexpr int R_   = 25;
constexpr int BW   = Bb * R_;           // 100
constexpr int NWIN = WSZ * WSZ;         // 196
constexpr int LL   = NWIN + NQ;         // 260
constexpr int CTXROWS = Bb * NTOK + Bb * NQ; // 16640
constexpr int PROW = NTOK + NQ;         // 4160 rows per (b,head)

// ---------------- scratch (f16 intermediates) ----------------
__device__ __half g_tok[(size_t)CTXROWS * Cc];
__device__ __half g_Q[(size_t)Bb * NH * PROW * DH];
__device__ __half g_K[(size_t)Bb * NH * PROW * DH];
__device__ __half g_V[(size_t)Bb * NH * PROW * DH];
__device__ __half g_Oq[(size_t)BW * NQ * Cc];
__device__ __half g_ctx[(size_t)CTXROWS * Cc];
__device__ __half g_Wt[(size_t)(3 * Cc) * Cc];
__device__ __half g_Wot[(size_t)Cc * Cc];

// ---------------- helpers ----------------
__device__ __forceinline__ uint32_t smem_u32(const void* p) {
    uint32_t a;
    asm("{ .reg .u64 t; cvta.to.shared.u64 t, %1; cvt.u32.u64 %0, t; }"
        : "=r"(a) : "l"(p));
    return a;
}
__device__ __forceinline__ void cp16(uint32_t s, const void* g) {
    asm volatile("cp.async.cg.shared.global [%0], [%1], 16;" :: "r"(s), "l"(g) : "memory");
}
__device__ __forceinline__ void cp16z(uint32_t s, const void* g, int sz) {
    asm volatile("cp.async.cg.shared.global [%0], [%1], 16, %2;"
                 :: "r"(s), "l"(g), "r"(sz) : "memory");
}
__device__ __forceinline__ void mma_f16(float* c, const uint32_t* a,
                                        uint32_t b0, uint32_t b1) {
    asm volatile("mma.sync.aligned.m16n8k16.row.col.f32.f16.f16.f32 "
                 "{%0,%1,%2,%3}, {%4,%5,%6,%7}, {%8,%9}, {%0,%1,%2,%3};"
                 : "+f"(c[0]), "+f"(c[1]), "+f"(c[2]), "+f"(c[3])
                 : "r"(a[0]), "r"(a[1]), "r"(a[2]), "r"(a[3]), "r"(b0), "r"(b1));
}
__device__ __forceinline__ void ldsm_x4(uint32_t* r, uint32_t addr) {
    asm volatile("ldmatrix.sync.aligned.m8n8.x4.shared.b16 {%0,%1,%2,%3}, [%4];"
                 : "=r"(r[0]), "=r"(r[1]), "=r"(r[2]), "=r"(r[3]) : "r"(addr));
}
__device__ __forceinline__ void ldsm_x4t(uint32_t* r, uint32_t addr) {
    asm volatile("ldmatrix.sync.aligned.m8n8.x4.trans.shared.b16 {%0,%1,%2,%3}, [%4];"
                 : "=r"(r[0]), "=r"(r[1]), "=r"(r[2]), "=r"(r[3]) : "r"(addr));
}
__device__ __forceinline__ void bar_grp(int id) {
    asm volatile("bar.sync %0, 128;" :: "r"(id) : "memory");
}
__device__ __forceinline__ uint32_t ex2_h2(float lo, float hi) {
    __half2 h = __floats2half2_rn(lo, hi);
    uint32_t u = *(uint32_t*)&h, r;
    asm("ex2.approx.f16x2 %0, %1;" : "=r"(r) : "r"(u));
    return r;
}

// ---------------- 0) convert weights to f16 ----------------
__global__ __launch_bounds__(256) void k_cvt_w(const float* __restrict__ Win,
                                               const float* __restrict__ Wout) {
    int idx = blockIdx.x * blockDim.x + threadIdx.x;
    const int N1 = 3 * Cc * Cc;
    const int N2 = Cc * Cc;
    if (idx < N1) g_Wt[idx] = __float2half_rn(Win[idx]);
    else if (idx < N1 + N2) g_Wot[idx - N1] = __float2half_rn(Wout[idx - N1]);
}

// ---------------- 1) unique tokens -> f16 ----------------
__global__ __launch_bounds__(256) void k_prep(const float* __restrict__ x,
                                              const float* __restrict__ q) {
    int idx = blockIdx.x * blockDim.x + threadIdx.x;
    if (idx >= CTXROWS * (Cc / 4)) return;
    int t  = idx / (Cc / 4);
    int c4 = idx % (Cc / 4);
    float4 val;
    if (t < Bb * NTOK) val = ((const float4*)(x + (size_t)t * Cc))[c4];
    else               val = ((const float4*)(q + (size_t)(t - Bb * NTOK) * Cc))[c4];
    __half2* dst = (__half2*)(g_tok + (size_t)t * Cc + c4 * 4);
    dst[0] = __floats2half2_rn(val.x, val.y);
    dst[1] = __floats2half2_rn(val.z, val.w);
}

// ---------------- 2) f16 mma.sync GEMM (NT), 3-stage + ldmatrix -------------
constexpr int RSH    = 72;
constexpr int TILEB  = 128 * RSH * 2;
constexpr int NSTAGE = 3;
constexpr int SMEM_GEMM = 2 * NSTAGE * TILEB;

__global__ __launch_bounds__(256, 2) void k_gemm_mma(const float* __restrict__ bias,
                                                     float* __restrict__ out,
                                                     int M, int Nn, int mode) {
    extern __shared__ char smc[];
    uint32_t sb = smem_u32(smc);
    const __half* A  = (mode == 0) ? g_tok : g_ctx;
    const __half* Bw = (mode == 0) ? g_Wt  : g_Wot;
    int tid = threadIdx.x, wid = tid >> 5, lane = tid & 31;
    int grp = lane >> 2, tig = lane & 3;
    int wm = wid & 3, wn = wid >> 2;
    int mb = blockIdx.y, nb = blockIdx.x;

    int m8 = lane >> 3, r8 = lane & 7;
    uint32_t aoff = (uint32_t)((wm * 32 + (m8 & 1) * 8 + r8) * (RSH * 2) + (m8 >> 1) * 16);
    uint32_t boff = (uint32_t)((wn * 64 + (m8 >> 1) * 8 + r8) * (RSH * 2) + (m8 & 1) * 16);

    float acc[2][8][4];
#pragma unroll
    for (int i = 0; i < 2; i++)
#pragma unroll
        for (int j = 0; j < 8; j++)
#pragma unroll
            for (int k = 0; k < 4; k++) acc[i][j][k] = 0.f;

    auto copy_tile = [&](int kc, int buf) {
        uint32_t sa  = sb + buf * TILEB;
        uint32_t sbm = sb + NSTAGE * TILEB + buf * TILEB;
#pragma unroll
        for (int i = 0; i < 4; i++) {
            int idx = tid * 4 + i;
            int r = idx >> 3, c8 = idx & 7;
            int gm = mb * 128 + r;
            if (gm >= M) gm = M - 1;
            cp16(sa + r * (RSH * 2) + c8 * 16, A + (size_t)gm * Cc + kc + c8 * 8);
            int gn = nb * 128 + r;
            cp16(sbm + r * (RSH * 2) + c8 * 16, Bw + (size_t)gn * Cc + kc + c8 * 8);
        }
        asm volatile("cp.async.commit_group;" ::: "memory");
    };

    const int NCH = Cc / 64;
    copy_tile(0, 0);
    copy_tile(64, 1);

    int buf = 0;
    for (int ci = 0; ci < NCH; ci++) {
        if (ci < NCH - 1)
            asm volatile("cp.async.wait_group 1;" ::: "memory");
        else
            asm volatile("cp.async.wait_group 0;" ::: "memory");
        __syncthreads();
        if (ci + 2 < NCH) {
            int nbuf = buf + 2; if (nbuf >= NSTAGE) nbuf -= NSTAGE;
            copy_tile((ci + 2) * 64, nbuf);
        }

        uint32_t sa  = sb + buf * TILEB + aoff;
        uint32_t sbm = sb + NSTAGE * TILEB + buf * TILEB + boff;
#pragma unroll
        for (int ks = 0; ks < 4; ks++) {
            uint32_t a[2][4];
            ldsm_x4(a[0], sa + ks * 32);
            ldsm_x4(a[1], sa + ks * 32 + 16 * (RSH * 2));
            uint32_t bf[4][4];
#pragma unroll
            for (int p = 0; p < 4; p++)
                ldsm_x4(bf[p], sbm + ks * 32 + p * (16 * (RSH * 2)));
#pragma unroll
            for (int p = 0; p < 4; p++)
#pragma unroll
                for (int j = 0; j < 2; j++) {
                    int nt = p * 2 + j;
                    mma_f16(acc[0][nt], a[0], bf[p][2 * j], bf[p][2 * j + 1]);
                    mma_f16(acc[1][nt], a[1], bf[p][2 * j], bf[p][2 * j + 1]);
                }
        }
        buf++; if (buf >= NSTAGE) buf = 0;
    }

#pragma unroll
    for (int mt = 0; mt < 2; mt++) {
        int m0 = mb * 128 + wm * 32 + mt * 16 + grp;
#pragma unroll
        for (int nt = 0; nt < 8; nt++) {
            int n0 = nb * 128 + wn * 64 + nt * 8 + tig * 2;
#pragma unroll
            for (int h = 0; h < 2; h++) {
                int m = m0 + h * 8;
                if (m >= M) continue;
                float v0 = acc[mt][nt][h * 2 + 0];
                float v1 = acc[mt][nt][h * 2 + 1];
                if (mode == 0) {
                    int b, p;
                    if (m < Bb * NTOK) { b = m >> 12; p = m & (NTOK - 1); }
                    else { int t = m - Bb * NTOK; b = t >> 6; p = NTOK + (t & (NQ - 1)); }
                    int which = n0 / Cc;
                    int hd = (n0 % Cc) / DH;
                    int dd = n0 % DH;
                    __half* dst = (which == 0) ? g_Q : (which == 1) ? g_K : g_V;
                    *(__half2*)(dst + (((size_t)(b * NH + hd)) * PROW + p) * DH + dd) =
                        __floats2half2_rn(v0, v1);
                } else {
                    *(float2*)(out + (size_t)m * Nn + n0) =
                        make_float2(v0 + bias[n0], v1 + bias[n0 + 1]);
                }
            }
        }
    }
}

// ---------------- 3) fused attention: group pipelines, early-exit groups ----
constexpr int PADL   = 320;
constexpr int KQ_STR = 72;
constexpr int O_STR  = 68;
constexpr int H_V    = PADL * KQ_STR;
constexpr int H_Q    = 2 * PADL * KQ_STR;
constexpr int H_END  = H_Q + 4 * 2 * 16 * KQ_STR;
constexpr int F_OB0  = (H_END * 2) / 4;
constexpr int F_OB1  = F_OB0 + 64 * O_STR;
constexpr int F_RMAX = F_OB1 + 64 * O_STR;
constexpr int F_RSUM = F_RMAX + 256;
constexpr int F_MSK  = F_RSUM + 256;
constexpr int SMEM_ATT = (F_MSK + PADL) * 4;

// 0.125 * log2(e)
#define SCL2 0.18033688011112042f

__global__ __launch_bounds__(512, 1) void k_attn_fused(const int* __restrict__ q_mask) {
    extern __shared__ char smc[];
    __half* Ks = (__half*)smc;
    __half* Vs = (__half*)smc + H_V;
    float* smf = (float*)smc;
    float* Ob0 = smf + F_OB0;
    float* Ob1 = smf + F_OB1;
    float* rmax = smf + F_RMAX;
    float* rsum = smf + F_RSUM;
    float* msk  = smf + F_MSK;
    uint32_t sbase = smem_u32(smc);

    int z  = blockIdx.x;
    int i  = z / NH;
    int hd = z % NH;
    int bp = i / R_;
    int w  = i % R_;
    int bq = i % Bb;
    int wy = w / NWX, wx = w % NWX;

    const __half* Kpix = g_K + ((size_t)(bp * NH + hd)) * PROW * DH;
    const __half* Kq   = g_K + ((size_t)(bq * NH + hd)) * PROW * DH + (size_t)NTOK * DH;
    const __half* Vpix = g_V + ((size_t)(bp * NH + hd)) * PROW * DH;
    const __half* Vq   = g_V + ((size_t)(bq * NH + hd)) * PROW * DH + (size_t)NTOK * DH;
    const __half* Qpix = g_Q + ((size_t)(bp * NH + hd)) * PROW * DH;
    const __half* Qq   = g_Q + ((size_t)(bq * NH + hd)) * PROW * DH + (size_t)NTOK * DH;

    int tid = threadIdx.x, wid = tid >> 5, lane = tid & 31;
    int grp = lane >> 2, tig = lane & 3;
    int wm = wid & 3, wn = wid >> 2;
    int gth = (wid >> 2) * 32 + lane;
    int lr0 = wm * 16 + grp, lr1 = lr0 + 8;
    int m8 = lane >> 3, r8 = lane & 7;
    int barid = wm + 1;
    // group wm covers rows qt*64 + wm*16 .. +15; valid tiles:
    const int NT = (wm == 0) ? 5 : 4;

    int qgrp = H_Q + wm * (2 * 16 * KQ_STR);
    uint32_t q_off = sbase + (uint32_t)(qgrp * 2) +
                     (uint32_t)(((m8 & 1) * 8 + r8) * 144 + (m8 >> 1) * 16);
    uint32_t k_off = sbase +
                     (uint32_t)((wn * 80 + (m8 >> 1) * 8 + r8) * 144 + (m8 & 1) * 16);
    uint32_t v_off = sbase + (uint32_t)(H_V * 2) +
                     (uint32_t)(((m8 & 1) * 8 + r8) * 144 + (m8 >> 1) * 16);

    auto prefetch_q = [&](int qt, int buf) {
        int r = gth >> 3, c = gth & 7;
        int gr = qt * 64 + wm * 16 + r;
        const __half* src = Qpix;
        int sz = 0;
        if (gr < NWIN) {
            int py = wy * WSZ + gr / WSZ, px = wx * WSZ + gr % WSZ;
            if (py < HH && px < WW) { src = Qpix + (size_t)(py * WW + px) * DH + c * 8; sz = 16; }
        } else if (gr < LL) {
            src = Qq + (size_t)(gr - NWIN) * DH + c * 8; sz = 16;
        }
        uint32_t dst = sbase + (uint32_t)((qgrp + buf * (16 * KQ_STR)) * 2) + r * 144 + c * 16;
        cp16z(dst, src, sz);
        asm volatile("cp.async.commit_group;" ::: "memory");
    };

    prefetch_q(0, 0);

    for (int j = tid; j < PADL; j += 512) {
        float m = 0.f;
        if (j >= NWIN)
            m = (j < LL && q_mask[bq * NQ + j - NWIN] != 0) ? 0.f : -1e30f;
        msk[j] = m;
    }
    for (int idx = tid; idx < PADL * 8; idx += 512) {
        int r = idx >> 3, c = idx & 7;
        uint4 kv = make_uint4(0, 0, 0, 0), vv = make_uint4(0, 0, 0, 0);
        if (r < NWIN) {
            int py = wy * WSZ + r / WSZ, px = wx * WSZ + r % WSZ;
            if (py < HH && px < WW) {
                kv = ((const uint4*)(Kpix + (size_t)(py * WW + px) * DH))[c];
                vv = ((const uint4*)(Vpix + (size_t)(py * WW + px) * DH))[c];
            }
        } else if (r < LL) {
            kv = ((const uint4*)(Kq + (size_t)(r - NWIN) * DH))[c];
            vv = ((const uint4*)(Vq + (size_t)(r - NWIN) * DH))[c];
        }
        *(uint4*)(Ks + r * KQ_STR + c * 8) = kv;
        *(uint4*)(Vs + r * KQ_STR + c * 8) = vv;
    }
    __syncthreads();

    for (int qt = 0; qt < NT; qt++) {
        uint32_t qb = q_off + (uint32_t)((qt & 1) * (16 * KQ_STR * 2));
        asm volatile("cp.async.wait_group 0;" ::: "memory");
        bar_grp(barid);

        // ---- S = Q @ K^T ----
        float sf[10][4];
#pragma unroll
        for (int t = 0; t < 10; t++)
#pragma unroll
            for (int k = 0; k < 4; k++) sf[t][k] = 0.f;
#pragma unroll
        for (int ks = 0; ks < 4; ks++) {
            uint32_t a[4];
            ldsm_x4(a, qb + ks * 32);
#pragma unroll
            for (int tp = 0; tp < 5; tp++) {
                uint32_t bb[4];
                ldsm_x4(bb, k_off + tp * (16 * 144) + ks * 32);
                mma_f16(sf[2 * tp],     a, bb[0], bb[1]);
                mma_f16(sf[2 * tp + 1], a, bb[2], bb[3]);
            }
        }

        // ---- scale (log2 domain) + mask + rowmax ----
        float mx0 = -3e38f, mx1 = -3e38f;
#pragma unroll
        for (int t = 0; t < 10; t++) {
            int jb = wn * 80 + t * 8 + 2 * tig;
            float m0 = msk[jb], m1 = msk[jb + 1];
            sf[t][0] = sf[t][0] * SCL2 + m0;
            sf[t][1] = sf[t][1] * SCL2 + m1;
            sf[t][2] = sf[t][2] * SCL2 + m0;
            sf[t][3] = sf[t][3] * SCL2 + m1;
            mx0 = fmaxf(mx0, fmaxf(sf[t][0], sf[t][1]));
            mx1 = fmaxf(mx1, fmaxf(sf[t][2], sf[t][3]));
        }
        mx0 = fmaxf(mx0, __shfl_xor_sync(~0u, mx0, 1));
        mx0 = fmaxf(mx0, __shfl_xor_sync(~0u, mx0, 2));
        mx1 = fmaxf(mx1, __shfl_xor_sync(~0u, mx1, 1));
        mx1 = fmaxf(mx1, __shfl_xor_sync(~0u, mx1, 2));
        if (tig == 0) {
            rmax[lr0 * 4 + wn] = mx0;
            rmax[lr1 * 4 + wn] = mx1;
        }
        bar_grp(barid);
        float4 r40 = *(float4*)(rmax + lr0 * 4);
        float4 r41 = *(float4*)(rmax + lr1 * 4);
        float M0 = fmaxf(fmaxf(r40.x, r40.y), fmaxf(r40.z, r40.w));
        float M1 = fmaxf(fmaxf(r41.x, r41.y), fmaxf(r41.z, r41.w));

        if (qt + 1 < NT) prefetch_q(qt + 1, (qt + 1) & 1);

        // ---- P = 2^(s - M) via f16x2 ex2; row sums from exact P ----
        float s0 = 0.f, s1 = 0.f;
        uint32_t pk[10][2];
#pragma unroll
        for (int t = 0; t < 10; t++) {
            uint32_t p0 = ex2_h2(sf[t][0] - M0, sf[t][1] - M0);
            uint32_t p1 = ex2_h2(sf[t][2] - M1, sf[t][3] - M1);
            pk[t][0] = p0;
            pk[t][1] = p1;
            float2 f0 = __half22float2(*(__half2*)&p0);
            float2 f1 = __half22float2(*(__half2*)&p1);
            s0 += f0.x + f0.y;
            s1 += f1.x + f1.y;
        }
        s0 += __shfl_xor_sync(~0u, s0, 1);
        s0 += __shfl_xor_sync(~0u, s0, 2);
        s1 += __shfl_xor_sync(~0u, s1, 1);
        s1 += __shfl_xor_sync(~0u, s1, 2);
        if (tig == 0) {
            rsum[lr0 * 4 + wn] = s0;
            rsum[lr1 * 4 + wn] = s1;
        }

        // ---- O_partial = P @ V (ldsm.trans B-frags) ----
        float of[8][4];
#pragma unroll
        for (int nt = 0; nt < 8; nt++)
#pragma unroll
            for (int k = 0; k < 4; k++) of[nt][k] = 0.f;
#pragma unroll
        for (int kt = 0; kt < 5; kt++) {
            uint32_t a[4];
            a[0] = pk[2 * kt][0];
            a[1] = pk[2 * kt][1];
            a[2] = pk[2 * kt + 1][0];
            a[3] = pk[2 * kt + 1][1];
            uint32_t vb = v_off + (uint32_t)((wn * 80 + kt * 16) * 144);
#pragma unroll
            for (int v = 0; v < 4; v++) {
                uint32_t vf[4];
                ldsm_x4t(vf, vb + v * 32);
                mma_f16(of[2 * v],     a, vf[0], vf[1]);
                mma_f16(of[2 * v + 1], a, vf[2], vf[3]);
            }
        }

        // ---- combine 4 key-slices (group-local) ----
        if (wn < 2) {
            float* Ob = (wn == 0) ? Ob0 : Ob1;
#pragma unroll
            for (int nt = 0; nt < 8; nt++) {
                int c = nt * 8 + 2 * tig;
                *(float2*)(Ob + lr0 * O_STR + c) = make_float2(of[nt][0], of[nt][1]);
                *(float2*)(Ob + lr1 * O_STR + c) = make_float2(of[nt][2], of[nt][3]);
            }
        }
        bar_grp(barid);
        if (wn >= 2) {
            float* Ob = (wn == 2) ? Ob0 : Ob1;
#pragma unroll
            for (int nt = 0; nt < 8; nt++) {
                int c = nt * 8 + 2 * tig;
                float2 p0 = *(float2*)(Ob + lr0 * O_STR + c);
                float2 p1 = *(float2*)(Ob + lr1 * O_STR + c);
                *(float2*)(Ob + lr0 * O_STR + c) =
                    make_float2(p0.x + of[nt][0], p0.y + of[nt][1]);
                *(float2*)(Ob + lr1 * O_STR + c) =
                    make_float2(p1.x + of[nt][2], p1.y + of[nt][3]);
            }
        }
        bar_grp(barid);

        // ---- final merge + normalize + scatter (group-local rows) ----
        {
            int r = wm * 16 + (gth >> 3);
            int c0 = (gth & 7) * 8;
            int grow = qt * 64 + r;
            if (grow < LL) {
                float4 s4 = *(float4*)(rsum + r * 4);
                float inv = 1.f / (s4.x + s4.y + s4.z + s4.w);
                float4 x0 = *(float4*)(Ob0 + r * O_STR + c0);
                float4 x1 = *(float4*)(Ob1 + r * O_STR + c0);
                float4 y0 = *(float4*)(Ob0 + r * O_STR + c0 + 4);
                float4 y1 = *(float4*)(Ob1 + r * O_STR + c0 + 4);
                __half2 h0 = __floats2half2_rn((x0.x + x1.x) * inv, (x0.y + x1.y) * inv);
                __half2 h1 = __floats2half2_rn((x0.z + x1.z) * inv, (x0.w + x1.w) * inv);
                __half2 h2 = __floats2half2_rn((y0.x + y1.x) * inv, (y0.y + y1.y) * inv);
                __half2 h3 = __floats2half2_rn((y0.z + y1.z) * inv, (y0.w + y1.w) * inv);
                __half2* dst = nullptr;
                if (grow < NWIN) {
                    int py = wy * WSZ + grow / WSZ, px = wx * WSZ + grow % WSZ;
                    if (py < HH && px < WW)
                        dst = (__half2*)(g_ctx + ((size_t)bp * NTOK + py * WW + px) * Cc
                                         + hd * DH + c0);
                } else {
                    dst = (__half2*)(g_Oq + ((size_t)i * NQ + (grow - NWIN)) * Cc
                                     + hd * DH + c0);
                }
                if (dst) { dst[0] = h0; dst[1] = h1; dst[2] = h2; dst[3] = h3; }
            }
        }
    }
}

// ---------------- 4) ctx rows for queries: mean over windows ----------------
__global__ __launch_bounds__(256) void k_ctx_q() {
    int idx = blockIdx.x * blockDim.x + threadIdx.x;
    const int SEG = Cc / 2;
    if (idx >= Bb * NQ * SEG) return;
    int j = idx / SEG, c = idx % SEG;
    int b = j / NQ, lq = j % NQ;
    float a0 = 0.f, a1 = 0.f;
#pragma unroll
    for (int w = 0; w < R_; w++) {
        int i = w * Bb + b;
        __half2 v = ((const __half2*)(g_Oq + ((size_t)i * NQ + lq) * Cc))[c];
        float2 f = __half22float2(v);
        a0 += f.x; a1 += f.y;
    }
    const float inv = 1.f / (float)R_;
    ((__half2*)(g_ctx + (size_t)(Bb * NTOK + j) * Cc))[c] =
        __floats2half2_rn(a0 * inv, a1 * inv);
}

// ---------------- launch ----------------
extern "C" void kernel_launch(void* const* d_in, const int* in_sizes, int n_in,
                              void* d_out, int out_size) {
    const float* x     = (const float*)d_in[0];
    const float* q     = (const float*)d_in[1];
    const float* W_in  = (const float*)d_in[2];
    const float* W_out = (const float*)d_in[3];
    const float* b_out = (const float*)d_in[4];
    const int*   qmask = (const int*)d_in[5];
    float* out = (float*)d_out;

    static bool attr_set = false;
    if (!attr_set) {
        cudaFuncSetAttribute(k_gemm_mma, cudaFuncAttributeMaxDynamicSharedMemorySize,
                             SMEM_GEMM);
        cudaFuncSetAttribute(k_attn_fused, cudaFuncAttributeMaxDynamicSharedMemorySize,
                             SMEM_ATT);
        attr_set = true;
    }

    k_cvt_w<<<(4 * Cc * Cc + 255) / 256, 256>>>(W_in, W_out);
    k_prep<<<(CTXROWS * (Cc / 4) + 255) / 256, 256>>>(x, q);

    dim3 g_qkv(3 * Cc / 128, CTXROWS / 128);
    k_gemm_mma<<<g_qkv, 256, SMEM_GEMM>>>(nullptr, nullptr, CTXROWS, 3 * Cc, 0);

    k_attn_fused<<<BW * NH, 512, SMEM_ATT>>>(qmask);

    k_ctx_q<<<(Bb * NQ * (Cc / 2) + 255) / 256, 256>>>();

    dim3 g_out(Cc / 128, CTXROWS / 128);
    k_gemm_mma<<<g_out, 256, SMEM_GEMM>>>(b_out, out, CTXROWS, Cc, 1);
}

// round 16
// speedup vs baseline: 7.0609x; 1.0113x over previous
#include <cuda_runtime.h>
#include <cuda_fp16.h>
#include <cstdint>

// ---------------- problem constants ----------------
constexpr int Bb   = 4;
constexpr int NTOK = 4096;
constexpr int Cc   = 768;
constexpr int NQ   = 64;
constexpr int HH   = 64, WW = 64;
constexpr int WSZ  = 14;
constexpr int NH   = 12, DH = 64;
constexpr int NWX  = 5;
constexpr int R_   = 25;
constexpr int BW   = Bb * R_;           // 100
constexpr int NWIN = WSZ * WSZ;         // 196
constexpr int LL   = NWIN + NQ;         // 260
constexpr int CTXROWS = Bb * NTOK + Bb * NQ; // 16640
constexpr int PROW = NTOK + NQ;         // 4160 rows per (b,head)

// ---------------- scratch (f16 intermediates) ----------------
__device__ __half g_tok[(size_t)CTXROWS * Cc];
__device__ __half g_Q[(size_t)Bb * NH * PROW * DH];
__device__ __half g_K[(size_t)Bb * NH * PROW * DH];
__device__ __half g_V[(size_t)Bb * NH * PROW * DH];
__device__ __half g_Oq[(size_t)BW * NQ * Cc];
__device__ __half g_ctx[(size_t)CTXROWS * Cc];
__device__ __half g_Wt[(size_t)(3 * Cc) * Cc];
__device__ __half g_Wot[(size_t)Cc * Cc];

// ---------------- helpers ----------------
__device__ __forceinline__ uint32_t smem_u32(const void* p) {
    uint32_t a;
    asm("{ .reg .u64 t; cvta.to.shared.u64 t, %1; cvt.u32.u64 %0, t; }"
        : "=r"(a) : "l"(p));
    return a;
}
__device__ __forceinline__ void cp16(uint32_t s, const void* g) {
    asm volatile("cp.async.cg.shared.global [%0], [%1], 16;" :: "r"(s), "l"(g) : "memory");
}
__device__ __forceinline__ void cp16z(uint32_t s, const void* g, int sz) {
    asm volatile("cp.async.cg.shared.global [%0], [%1], 16, %2;"
                 :: "r"(s), "l"(g), "r"(sz) : "memory");
}
__device__ __forceinline__ void mma_f16(float* c, const uint32_t* a,
                                        uint32_t b0, uint32_t b1) {
    asm volatile("mma.sync.aligned.m16n8k16.row.col.f32.f16.f16.f32 "
                 "{%0,%1,%2,%3}, {%4,%5,%6,%7}, {%8,%9}, {%0,%1,%2,%3};"
                 : "+f"(c[0]), "+f"(c[1]), "+f"(c[2]), "+f"(c[3])
                 : "r"(a[0]), "r"(a[1]), "r"(a[2]), "r"(a[3]), "r"(b0), "r"(b1));
}
__device__ __forceinline__ void mma_f16_k8(float* c, uint32_t a0, uint32_t a1,
                                           uint32_t b0) {
    asm volatile("mma.sync.aligned.m16n8k8.row.col.f32.f16.f16.f32 "
                 "{%0,%1,%2,%3}, {%4,%5}, {%6}, {%0,%1,%2,%3};"
                 : "+f"(c[0]), "+f"(c[1]), "+f"(c[2]), "+f"(c[3])
                 : "r"(a0), "r"(a1), "r"(b0));
}
__device__ __forceinline__ void ldsm_x4(uint32_t* r, uint32_t addr) {
    asm volatile("ldmatrix.sync.aligned.m8n8.x4.shared.b16 {%0,%1,%2,%3}, [%4];"
                 : "=r"(r[0]), "=r"(r[1]), "=r"(r[2]), "=r"(r[3]) : "r"(addr));
}
__device__ __forceinline__ void ldsm_x2(uint32_t* r, uint32_t addr) {
    asm volatile("ldmatrix.sync.aligned.m8n8.x2.shared.b16 {%0,%1}, [%2];"
                 : "=r"(r[0]), "=r"(r[1]) : "r"(addr));
}
__device__ __forceinline__ void ldsm_x4t(uint32_t* r, uint32_t addr) {
    asm volatile("ldmatrix.sync.aligned.m8n8.x4.trans.shared.b16 {%0,%1,%2,%3}, [%4];"
                 : "=r"(r[0]), "=r"(r[1]), "=r"(r[2]), "=r"(r[3]) : "r"(addr));
}
__device__ __forceinline__ void bar_grp(int id) {
    asm volatile("bar.sync %0, 128;" :: "r"(id) : "memory");
}
__device__ __forceinline__ uint32_t ex2_h2(float lo, float hi) {
    __half2 h = __floats2half2_rn(lo, hi);
    uint32_t u = *(uint32_t*)&h, r;
    asm("ex2.approx.f16x2 %0, %1;" : "=r"(r) : "r"(u));
    return r;
}

// ---------------- 0) convert weights to f16 ----------------
__global__ __launch_bounds__(256) void k_cvt_w(const float* __restrict__ Win,
                                               const float* __restrict__ Wout) {
    int idx = blockIdx.x * blockDim.x + threadIdx.x;
    const int N1 = 3 * Cc * Cc;
    const int N2 = Cc * Cc;
    if (idx < N1) g_Wt[idx] = __float2half_rn(Win[idx]);
    else if (idx < N1 + N2) g_Wot[idx - N1] = __float2half_rn(Wout[idx - N1]);
}

// ---------------- 1) unique tokens -> f16 ----------------
__global__ __launch_bounds__(256) void k_prep(const float* __restrict__ x,
                                              const float* __restrict__ q) {
    int idx = blockIdx.x * blockDim.x + threadIdx.x;
    if (idx >= CTXROWS * (Cc / 4)) return;
    int t  = idx / (Cc / 4);
    int c4 = idx % (Cc / 4);
    float4 val;
    if (t < Bb * NTOK) val = ((const float4*)(x + (size_t)t * Cc))[c4];
    else               val = ((const float4*)(q + (size_t)(t - Bb * NTOK) * Cc))[c4];
    __half2* dst = (__half2*)(g_tok + (size_t)t * Cc + c4 * 4);
    dst[0] = __floats2half2_rn(val.x, val.y);
    dst[1] = __floats2half2_rn(val.z, val.w);
}

// ---------------- 2) f16 mma.sync GEMM (NT), 3-stage + ldmatrix -------------
constexpr int RSH    = 72;
constexpr int TILEB  = 128 * RSH * 2;
constexpr int NSTAGE = 3;
constexpr int SMEM_GEMM = 2 * NSTAGE * TILEB;

__global__ __launch_bounds__(256, 2) void k_gemm_mma(const float* __restrict__ bias,
                                                     float* __restrict__ out,
                                                     int M, int Nn, int mode) {
    extern __shared__ char smc[];
    uint32_t sb = smem_u32(smc);
    const __half* A  = (mode == 0) ? g_tok : g_ctx;
    const __half* Bw = (mode == 0) ? g_Wt  : g_Wot;
    int tid = threadIdx.x, wid = tid >> 5, lane = tid & 31;
    int grp = lane >> 2, tig = lane & 3;
    int wm = wid & 3, wn = wid >> 2;
    int mb = blockIdx.y, nb = blockIdx.x;

    int m8 = lane >> 3, r8 = lane & 7;
    uint32_t aoff = (uint32_t)((wm * 32 + (m8 & 1) * 8 + r8) * (RSH * 2) + (m8 >> 1) * 16);
    uint32_t boff = (uint32_t)((wn * 64 + (m8 >> 1) * 8 + r8) * (RSH * 2) + (m8 & 1) * 16);

    float acc[2][8][4];
#pragma unroll
    for (int i = 0; i < 2; i++)
#pragma unroll
        for (int j = 0; j < 8; j++)
#pragma unroll
            for (int k = 0; k < 4; k++) acc[i][j][k] = 0.f;

    auto copy_tile = [&](int kc, int buf) {
        uint32_t sa  = sb + buf * TILEB;
        uint32_t sbm = sb + NSTAGE * TILEB + buf * TILEB;
#pragma unroll
        for (int i = 0; i < 4; i++) {
            int idx = tid * 4 + i;
            int r = idx >> 3, c8 = idx & 7;
            int gm = mb * 128 + r;
            if (gm >= M) gm = M - 1;
            cp16(sa + r * (RSH * 2) + c8 * 16, A + (size_t)gm * Cc + kc + c8 * 8);
            int gn = nb * 128 + r;
            cp16(sbm + r * (RSH * 2) + c8 * 16, Bw + (size_t)gn * Cc + kc + c8 * 8);
        }
        asm volatile("cp.async.commit_group;" ::: "memory");
    };

    const int NCH = Cc / 64;
    copy_tile(0, 0);
    copy_tile(64, 1);

    int buf = 0;
    for (int ci = 0; ci < NCH; ci++) {
        if (ci < NCH - 1)
            asm volatile("cp.async.wait_group 1;" ::: "memory");
        else
            asm volatile("cp.async.wait_group 0;" ::: "memory");
        __syncthreads();
        if (ci + 2 < NCH) {
            int nbuf = buf + 2; if (nbuf >= NSTAGE) nbuf -= NSTAGE;
            copy_tile((ci + 2) * 64, nbuf);
        }

        uint32_t sa  = sb + buf * TILEB + aoff;
        uint32_t sbm = sb + NSTAGE * TILEB + buf * TILEB + boff;
#pragma unroll
        for (int ks = 0; ks < 4; ks++) {
            uint32_t a[2][4];
            ldsm_x4(a[0], sa + ks * 32);
            ldsm_x4(a[1], sa + ks * 32 + 16 * (RSH * 2));
            uint32_t bf[4][4];
#pragma unroll
            for (int p = 0; p < 4; p++)
                ldsm_x4(bf[p], sbm + ks * 32 + p * (16 * (RSH * 2)));
#pragma unroll
            for (int p = 0; p < 4; p++)
#pragma unroll
                for (int j = 0; j < 2; j++) {
                    int nt = p * 2 + j;
                    mma_f16(acc[0][nt], a[0], bf[p][2 * j], bf[p][2 * j + 1]);
                    mma_f16(acc[1][nt], a[1], bf[p][2 * j], bf[p][2 * j + 1]);
                }
        }
        buf++; if (buf >= NSTAGE) buf = 0;
    }

#pragma unroll
    for (int mt = 0; mt < 2; mt++) {
        int m0 = mb * 128 + wm * 32 + mt * 16 + grp;
#pragma unroll
        for (int nt = 0; nt < 8; nt++) {
            int n0 = nb * 128 + wn * 64 + nt * 8 + tig * 2;
#pragma unroll
            for (int h = 0; h < 2; h++) {
                int m = m0 + h * 8;
                if (m >= M) continue;
                float v0 = acc[mt][nt][h * 2 + 0];
                float v1 = acc[mt][nt][h * 2 + 1];
                if (mode == 0) {
                    int b, p;
                    if (m < Bb * NTOK) { b = m >> 12; p = m & (NTOK - 1); }
                    else { int t = m - Bb * NTOK; b = t >> 6; p = NTOK + (t & (NQ - 1)); }
                    int which = n0 / Cc;
                    int hd = (n0 % Cc) / DH;
                    int dd = n0 % DH;
                    __half* dst = (which == 0) ? g_Q : (which == 1) ? g_K : g_V;
                    *(__half2*)(dst + (((size_t)(b * NH + hd)) * PROW + p) * DH + dd) =
                        __floats2half2_rn(v0, v1);
                } else {
                    *(float2*)(out + (size_t)m * Nn + n0) =
                        make_float2(v0 + bias[n0], v1 + bias[n0 + 1]);
                }
            }
        }
    }
}

// ---------------- 3) fused attention: 288-key padding, tail tiles -----------
constexpr int PADL   = 288;       // 4 warps x 72 keys
constexpr int KQ_STR = 72;
constexpr int O_STR  = 68;
constexpr int H_V    = PADL * KQ_STR;             // 20736
constexpr int H_Q    = 2 * PADL * KQ_STR;         // 41472
constexpr int H_END  = H_Q + 4 * 2 * 16 * KQ_STR; // 50688 halves
constexpr int F_OB0  = (H_END * 2) / 4;           // 25344 floats
constexpr int F_OB1  = F_OB0 + 64 * O_STR;
constexpr int F_RMAX = F_OB1 + 64 * O_STR;
constexpr int F_RSUM = F_RMAX + 256;
constexpr int F_MSK  = F_RSUM + 256;
constexpr int SMEM_ATT = (F_MSK + PADL) * 4;      // ~139 KB

// 0.125 * log2(e)
#define SCL2 0.18033688011112042f

__global__ __launch_bounds__(512, 1) void k_attn_fused(const int* __restrict__ q_mask) {
    extern __shared__ char smc[];
    __half* Ks = (__half*)smc;
    __half* Vs = (__half*)smc + H_V;
    float* smf = (float*)smc;
    float* Ob0 = smf + F_OB0;
    float* Ob1 = smf + F_OB1;
    float* rmax = smf + F_RMAX;
    float* rsum = smf + F_RSUM;
    float* msk  = smf + F_MSK;
    uint32_t sbase = smem_u32(smc);

    int z  = blockIdx.x;
    int i  = z / NH;
    int hd = z % NH;
    int bp = i / R_;
    int w  = i % R_;
    int bq = i % Bb;
    int wy = w / NWX, wx = w % NWX;

    const __half* Kpix = g_K + ((size_t)(bp * NH + hd)) * PROW * DH;
    const __half* Kq   = g_K + ((size_t)(bq * NH + hd)) * PROW * DH + (size_t)NTOK * DH;
    const __half* Vpix = g_V + ((size_t)(bp * NH + hd)) * PROW * DH;
    const __half* Vq   = g_V + ((size_t)(bq * NH + hd)) * PROW * DH + (size_t)NTOK * DH;
    const __half* Qpix = g_Q + ((size_t)(bp * NH + hd)) * PROW * DH;
    const __half* Qq   = g_Q + ((size_t)(bq * NH + hd)) * PROW * DH + (size_t)NTOK * DH;

    int tid = threadIdx.x, wid = tid >> 5, lane = tid & 31;
    int grp = lane >> 2, tig = lane & 3;
    int wm = wid & 3, wn = wid >> 2;
    int gth = (wid >> 2) * 32 + lane;
    int lr0 = wm * 16 + grp, lr1 = lr0 + 8;
    int m8 = lane >> 3, r8 = lane & 7;
    int barid = wm + 1;
    const int NT = (wm == 0) ? 5 : 4;

    int qgrp = H_Q + wm * (2 * 16 * KQ_STR);
    uint32_t q_off = sbase + (uint32_t)(qgrp * 2) +
                     (uint32_t)(((m8 & 1) * 8 + r8) * 144 + (m8 >> 1) * 16);
    uint32_t k_off = sbase +
                     (uint32_t)((wn * 72 + (m8 >> 1) * 8 + r8) * 144 + (m8 & 1) * 16);
    // K tail x2: lanes 0-7 -> k-half 0, lanes 8-15 -> k-half 1 (rows 64-71 of slice)
    uint32_t k2_off = sbase +
                      (uint32_t)((wn * 72 + 64 + (lane & 7)) * 144 + ((lane >> 3) & 1) * 16);
    uint32_t v_off = sbase + (uint32_t)(H_V * 2) +
                     (uint32_t)(((m8 & 1) * 8 + r8) * 144 + (m8 >> 1) * 16);
    // V tail x4t: 4 matrices = key rows 64-71 x dh tiles m8 (byte m8*16)
    uint32_t vt_off = sbase + (uint32_t)(H_V * 2) +
                      (uint32_t)((wn * 72 + 64 + r8) * 144 + m8 * 16);

    auto prefetch_q = [&](int qt, int buf) {
        int r = gth >> 3, c = gth & 7;
        int gr = qt * 64 + wm * 16 + r;
        const __half* src = Qpix;
        int sz = 0;
        if (gr < NWIN) {
            int py = wy * WSZ + gr / WSZ, px = wx * WSZ + gr % WSZ;
            if (py < HH && px < WW) { src = Qpix + (size_t)(py * WW + px) * DH + c * 8; sz = 16; }
        } else if (gr < LL) {
            src = Qq + (size_t)(gr - NWIN) * DH + c * 8; sz = 16;
        }
        uint32_t dst = sbase + (uint32_t)((qgrp + buf * (16 * KQ_STR)) * 2) + r * 144 + c * 16;
        cp16z(dst, src, sz);
        asm volatile("cp.async.commit_group;" ::: "memory");
    };

    prefetch_q(0, 0);

    for (int j = tid; j < PADL; j += 512) {
        float m = 0.f;
        if (j >= NWIN)
            m = (j < LL && q_mask[bq * NQ + j - NWIN] != 0) ? 0.f : -1e30f;
        msk[j] = m;
    }
    for (int idx = tid; idx < PADL * 8; idx += 512) {
        int r = idx >> 3, c = idx & 7;
        uint4 kv = make_uint4(0, 0, 0, 0), vv = make_uint4(0, 0, 0, 0);
        if (r < NWIN) {
            int py = wy * WSZ + r / WSZ, px = wx * WSZ + r % WSZ;
            if (py < HH && px < WW) {
                kv = ((const uint4*)(Kpix + (size_t)(py * WW + px) * DH))[c];
                vv = ((const uint4*)(Vpix + (size_t)(py * WW + px) * DH))[c];
            }
        } else if (r < LL) {
            kv = ((const uint4*)(Kq + (size_t)(r - NWIN) * DH))[c];
            vv = ((const uint4*)(Vq + (size_t)(r - NWIN) * DH))[c];
        }
        *(uint4*)(Ks + r * KQ_STR + c * 8) = kv;
        *(uint4*)(Vs + r * KQ_STR + c * 8) = vv;
    }
    __syncthreads();

    for (int qt = 0; qt < NT; qt++) {
        uint32_t qb = q_off + (uint32_t)((qt & 1) * (16 * KQ_STR * 2));
        asm volatile("cp.async.wait_group 0;" ::: "memory");
        bar_grp(barid);

        // ---- S = Q @ K^T : 9 n-tiles (4 x4 pairs + 1 x2 tail) ----
        float sf[9][4];
#pragma unroll
        for (int t = 0; t < 9; t++)
#pragma unroll
            for (int k = 0; k < 4; k++) sf[t][k] = 0.f;
#pragma unroll
        for (int ks = 0; ks < 4; ks++) {
            uint32_t a[4];
            ldsm_x4(a, qb + ks * 32);
#pragma unroll
            for (int tp = 0; tp < 4; tp++) {
                uint32_t bb[4];
                ldsm_x4(bb, k_off + tp * (16 * 144) + ks * 32);
                mma_f16(sf[2 * tp],     a, bb[0], bb[1]);
                mma_f16(sf[2 * tp + 1], a, bb[2], bb[3]);
            }
            uint32_t t2[2];
            ldsm_x2(t2, k2_off + ks * 32);
            mma_f16(sf[8], a, t2[0], t2[1]);
        }

        // ---- scale (log2 domain) + mask + rowmax ----
        float mx0 = -3e38f, mx1 = -3e38f;
#pragma unroll
        for (int t = 0; t < 9; t++) {
            int jb = wn * 72 + t * 8 + 2 * tig;
            float m0 = msk[jb], m1 = msk[jb + 1];
            sf[t][0] = sf[t][0] * SCL2 + m0;
            sf[t][1] = sf[t][1] * SCL2 + m1;
            sf[t][2] = sf[t][2] * SCL2 + m0;
            sf[t][3] = sf[t][3] * SCL2 + m1;
            mx0 = fmaxf(mx0, fmaxf(sf[t][0], sf[t][1]));
            mx1 = fmaxf(mx1, fmaxf(sf[t][2], sf[t][3]));
        }
        mx0 = fmaxf(mx0, __shfl_xor_sync(~0u, mx0, 1));
        mx0 = fmaxf(mx0, __shfl_xor_sync(~0u, mx0, 2));
        mx1 = fmaxf(mx1, __shfl_xor_sync(~0u, mx1, 1));
        mx1 = fmaxf(mx1, __shfl_xor_sync(~0u, mx1, 2));
        if (tig == 0) {
            rmax[lr0 * 4 + wn] = mx0;
            rmax[lr1 * 4 + wn] = mx1;
        }
        bar_grp(barid);
        float4 r40 = *(float4*)(rmax + lr0 * 4);
        float4 r41 = *(float4*)(rmax + lr1 * 4);
        float M0 = fmaxf(fmaxf(r40.x, r40.y), fmaxf(r40.z, r40.w));
        float M1 = fmaxf(fmaxf(r41.x, r41.y), fmaxf(r41.z, r41.w));

        if (qt + 1 < NT) prefetch_q(qt + 1, (qt + 1) & 1);

        // ---- P = 2^(s - M) via f16x2 ex2; row sums from exact P ----
        float s0 = 0.f, s1 = 0.f;
        uint32_t pk[9][2];
#pragma unroll
        for (int t = 0; t < 9; t++) {
            uint32_t p0 = ex2_h2(sf[t][0] - M0, sf[t][1] - M0);
            uint32_t p1 = ex2_h2(sf[t][2] - M1, sf[t][3] - M1);
            pk[t][0] = p0;
            pk[t][1] = p1;
            float2 f0 = __half22float2(*(__half2*)&p0);
            float2 f1 = __half22float2(*(__half2*)&p1);
            s0 += f0.x + f0.y;
            s1 += f1.x + f1.y;
        }
        s0 += __shfl_xor_sync(~0u, s0, 1);
        s0 += __shfl_xor_sync(~0u, s0, 2);
        s1 += __shfl_xor_sync(~0u, s1, 1);
        s1 += __shfl_xor_sync(~0u, s1, 2);
        if (tig == 0) {
            rsum[lr0 * 4 + wn] = s0;
            rsum[lr1 * 4 + wn] = s1;
        }

        // ---- O_partial = P @ V : 4 k16 steps + 1 k8 tail ----
        float of[8][4];
#pragma unroll
        for (int nt = 0; nt < 8; nt++)
#pragma unroll
            for (int k = 0; k < 4; k++) of[nt][k] = 0.f;
#pragma unroll
        for (int kt = 0; kt < 4; kt++) {
            uint32_t a[4];
            a[0] = pk[2 * kt][0];
            a[1] = pk[2 * kt][1];
            a[2] = pk[2 * kt + 1][0];
            a[3] = pk[2 * kt + 1][1];
            uint32_t vb = v_off + (uint32_t)((wn * 72 + kt * 16) * 144);
#pragma unroll
            for (int v = 0; v < 4; v++) {
                uint32_t vf[4];
                ldsm_x4t(vf, vb + v * 32);
                mma_f16(of[2 * v],     a, vf[0], vf[1]);
                mma_f16(of[2 * v + 1], a, vf[2], vf[3]);
            }
        }
        {   // k8 tail: keys 64-71 of slice
            uint32_t vfa[4], vfb[4];
            ldsm_x4t(vfa, vt_off);        // b0 for dh tiles 0-3
            ldsm_x4t(vfb, vt_off + 64);   // b0 for dh tiles 4-7
#pragma unroll
            for (int v = 0; v < 4; v++) {
                mma_f16_k8(of[v],     pk[8][0], pk[8][1], vfa[v]);
                mma_f16_k8(of[v + 4], pk[8][0], pk[8][1], vfb[v]);
            }
        }

        // ---- combine 4 key-slices (group-local) ----
        if (wn < 2) {
            float* Ob = (wn == 0) ? Ob0 : Ob1;
#pragma unroll
            for (int nt = 0; nt < 8; nt++) {
                int c = nt * 8 + 2 * tig;
                *(float2*)(Ob + lr0 * O_STR + c) = make_float2(of[nt][0], of[nt][1]);
                *(float2*)(Ob + lr1 * O_STR + c) = make_float2(of[nt][2], of[nt][3]);
            }
        }
        bar_grp(barid);
        if (wn >= 2) {
            float* Ob = (wn == 2) ? Ob0 : Ob1;
#pragma unroll
            for (int nt = 0; nt < 8; nt++) {
                int c = nt * 8 + 2 * tig;
                float2 p0 = *(float2*)(Ob + lr0 * O_STR + c);
                float2 p1 = *(float2*)(Ob + lr1 * O_STR + c);
                *(float2*)(Ob + lr0 * O_STR + c) =
                    make_float2(p0.x + of[nt][0], p0.y + of[nt][1]);
                *(float2*)(Ob + lr1 * O_STR + c) =
                    make_float2(p1.x + of[nt][2], p1.y + of[nt][3]);
            }
        }
        bar_grp(barid);

        // ---- final merge + normalize + scatter (group-local rows) ----
        {
            int r = wm * 16 + (gth >> 3);
            int c0 = (gth & 7) * 8;
            int grow = qt * 64 + r;
            if (grow < LL) {
                float4 s4 = *(float4*)(rsum + r * 4);
                float inv = 1.f / (s4.x + s4.y + s4.z + s4.w);
                float4 x0 = *(float4*)(Ob0 + r * O_STR + c0);
                float4 x1 = *(float4*)(Ob1 + r * O_STR + c0);
                float4 y0 = *(float4*)(Ob0 + r * O_STR + c0 + 4);
                float4 y1 = *(float4*)(Ob1 + r * O_STR + c0 + 4);
                __half2 h0 = __floats2half2_rn((x0.x + x1.x) * inv, (x0.y + x1.y) * inv);
                __half2 h1 = __floats2half2_rn((x0.z + x1.z) * inv, (x0.w + x1.w) * inv);
                __half2 h2 = __floats2half2_rn((y0.x + y1.x) * inv, (y0.y + y1.y) * inv);
                __half2 h3 = __floats2half2_rn((y0.z + y1.z) * inv, (y0.w + y1.w) * inv);
                __half2* dst = nullptr;
                if (grow < NWIN) {
                    int py = wy * WSZ + grow / WSZ, px = wx * WSZ + grow % WSZ;
                    if (py < HH && px < WW)
                        dst = (__half2*)(g_ctx + ((size_t)bp * NTOK + py * WW + px) * Cc
                                         + hd * DH + c0);
                } else {
                    dst = (__half2*)(g_Oq + ((size_t)i * NQ + (grow - NWIN)) * Cc
                                     + hd * DH + c0);
                }
                if (dst) { dst[0] = h0; dst[1] = h1; dst[2] = h2; dst[3] = h3; }
            }
        }
    }
}

// ---------------- 4) ctx rows for queries: mean over windows ----------------
__global__ __launch_bounds__(256) void k_ctx_q() {
    int idx = blockIdx.x * blockDim.x + threadIdx.x;
    const int SEG = Cc / 2;
    if (idx >= Bb * NQ * SEG) return;
    int j = idx / SEG, c = idx % SEG;
    int b = j / NQ, lq = j % NQ;
    float a0 = 0.f, a1 = 0.f;
#pragma unroll
    for (int w = 0; w < R_; w++) {
        int i = w * Bb + b;
        __half2 v = ((const __half2*)(g_Oq + ((size_t)i * NQ + lq) * Cc))[c];
        float2 f = __half22float2(v);
        a0 += f.x; a1 += f.y;
    }
    const float inv = 1.f / (float)R_;
    ((__half2*)(g_ctx + (size_t)(Bb * NTOK + j) * Cc))[c] =
        __floats2half2_rn(a0 * inv, a1 * inv);
}

// ---------------- launch ----------------
extern "C" void kernel_launch(void* const* d_in, const int* in_sizes, int n_in,
                              void* d_out, int out_size) {
    const float* x     = (const float*)d_in[0];
    const float* q     = (const float*)d_in[1];
    const float* W_in  = (const float*)d_in[2];
    const float* W_out = (const float*)d_in[3];
    const float* b_out = (const float*)d_in[4];
    const int*   qmask = (const int*)d_in[5];
    float* out = (float*)d_out;

    static bool attr_set = false;
    if (!attr_set) {
        cudaFuncSetAttribute(k_gemm_mma, cudaFuncAttributeMaxDynamicSharedMemorySize,
                             SMEM_GEMM);
        cudaFuncSetAttribute(k_attn_fused, cudaFuncAttributeMaxDynamicSharedMemorySize,
                             SMEM_ATT);
        attr_set = true;
    }

    k_cvt_w<<<(4 * Cc * Cc + 255) / 256, 256>>>(W_in, W_out);
    k_prep<<<(CTXROWS * (Cc / 4) + 255) / 256, 256>>>(x, q);

    dim3 g_qkv(3 * Cc / 128, CTXROWS / 128);
    k_gemm_mma<<<g_qkv, 256, SMEM_GEMM>>>(nullptr, nullptr, CTXROWS, 3 * Cc, 0);

    k_attn_fused<<<BW * NH, 512, SMEM_ATT>>>(qmask);

    k_ctx_q<<<(Bb * NQ * (Cc / 2) + 255) / 256, 256>>>();

    dim3 g_out(Cc / 128, CTXROWS / 128);
    k_gemm_mma<<<g_out, 256, SMEM_GEMM>>>(b_out, out, CTXROWS, Cc, 1);
}

// round 17
// speedup vs baseline: 7.1538x; 1.0132x over previous
#include <cuda_runtime.h>
#include <cuda_fp16.h>
#include <cstdint>

// ---------------- problem constants ----------------
constexpr int Bb   = 4;
constexpr int NTOK = 4096;
constexpr int Cc   = 768;
constexpr int NQ   = 64;
constexpr int HH   = 64, WW = 64;
constexpr int WSZ  = 14;
constexpr int NH   = 12, DH = 64;
constexpr int NWX  = 5;
constexpr int R_   = 25;
constexpr int BW   = Bb * R_;           // 100
constexpr int NWIN = WSZ * WSZ;         // 196
constexpr int LL   = NWIN + NQ;         // 260
constexpr int CTXROWS = Bb * NTOK + Bb * NQ; // 16640
constexpr int PROW = NTOK + NQ;         // 4160 rows per (b,head)

// ---------------- scratch (f16 intermediates) ----------------
__device__ __half g_tok[(size_t)CTXROWS * Cc];
__device__ __half g_Q[(size_t)Bb * NH * PROW * DH];
__device__ __half g_K[(size_t)Bb * NH * PROW * DH];
__device__ __half g_V[(size_t)Bb * NH * PROW * DH];
__device__ __half g_Oq[(size_t)BW * NQ * Cc];
__device__ __half g_ctx[(size_t)CTXROWS * Cc];
__device__ __half g_Wt[(size_t)(3 * Cc) * Cc];
__device__ __half g_Wot[(size_t)Cc * Cc];

// ---------------- helpers ----------------
__device__ __forceinline__ uint32_t smem_u32(const void* p) {
    uint32_t a;
    asm("{ .reg .u64 t; cvta.to.shared.u64 t, %1; cvt.u32.u64 %0, t; }"
        : "=r"(a) : "l"(p));
    return a;
}
__device__ __forceinline__ void cp16(uint32_t s, const void* g) {
    asm volatile("cp.async.cg.shared.global [%0], [%1], 16;" :: "r"(s), "l"(g) : "memory");
}
__device__ __forceinline__ void cp16z(uint32_t s, const void* g, int sz) {
    asm volatile("cp.async.cg.shared.global [%0], [%1], 16, %2;"
                 :: "r"(s), "l"(g), "r"(sz) : "memory");
}
__device__ __forceinline__ void mma_f16(float* c, const uint32_t* a,
                                        uint32_t b0, uint32_t b1) {
    asm volatile("mma.sync.aligned.m16n8k16.row.col.f32.f16.f16.f32 "
                 "{%0,%1,%2,%3}, {%4,%5,%6,%7}, {%8,%9}, {%0,%1,%2,%3};"
                 : "+f"(c[0]), "+f"(c[1]), "+f"(c[2]), "+f"(c[3])
                 : "r"(a[0]), "r"(a[1]), "r"(a[2]), "r"(a[3]), "r"(b0), "r"(b1));
}
__device__ __forceinline__ void mma_f16_k8(float* c, uint32_t a0, uint32_t a1,
                                           uint32_t b0) {
    asm volatile("mma.sync.aligned.m16n8k8.row.col.f32.f16.f16.f32 "
                 "{%0,%1,%2,%3}, {%4,%5}, {%6}, {%0,%1,%2,%3};"
                 : "+f"(c[0]), "+f"(c[1]), "+f"(c[2]), "+f"(c[3])
                 : "r"(a0), "r"(a1), "r"(b0));
}
__device__ __forceinline__ void ldsm_x4(uint32_t* r, uint32_t addr) {
    asm volatile("ldmatrix.sync.aligned.m8n8.x4.shared.b16 {%0,%1,%2,%3}, [%4];"
                 : "=r"(r[0]), "=r"(r[1]), "=r"(r[2]), "=r"(r[3]) : "r"(addr));
}
__device__ __forceinline__ void ldsm_x2(uint32_t* r, uint32_t addr) {
    asm volatile("ldmatrix.sync.aligned.m8n8.x2.shared.b16 {%0,%1}, [%2];"
                 : "=r"(r[0]), "=r"(r[1]) : "r"(addr));
}
__device__ __forceinline__ void ldsm_x4t(uint32_t* r, uint32_t addr) {
    asm volatile("ldmatrix.sync.aligned.m8n8.x4.trans.shared.b16 {%0,%1,%2,%3}, [%4];"
                 : "=r"(r[0]), "=r"(r[1]), "=r"(r[2]), "=r"(r[3]) : "r"(addr));
}
__device__ __forceinline__ void bar_grp(int id) {
    asm volatile("bar.sync %0, 128;" :: "r"(id) : "memory");
}
__device__ __forceinline__ uint32_t ex2_h2(float lo, float hi) {
    __half2 h = __floats2half2_rn(lo, hi);
    uint32_t u = *(uint32_t*)&h, r;
    asm("ex2.approx.f16x2 %0, %1;" : "=r"(r) : "r"(u));
    return r;
}

// ---------------- 1) fused prep: tokens + weights -> f16 (vectorized) -------
constexpr int PREP_TOK = CTXROWS * (Cc / 4);           // token float4 items
constexpr int PREP_W1  = (3 * Cc * Cc) / 4;            // W_in float4 items
constexpr int PREP_W2  = (Cc * Cc) / 4;                // W_out float4 items
constexpr int PREP_ALL = PREP_TOK + PREP_W1 + PREP_W2;

__global__ __launch_bounds__(256) void k_prep(const float* __restrict__ x,
                                              const float* __restrict__ q,
                                              const float* __restrict__ Win,
                                              const float* __restrict__ Wout) {
    int idx = blockIdx.x * blockDim.x + threadIdx.x;
    if (idx >= PREP_ALL) return;
    const float* src;
    __half* dst;
    int j;
    if (idx < PREP_TOK) {
        int t  = idx / (Cc / 4);
        int c4 = idx % (Cc / 4);
        if (t < Bb * NTOK) { src = x; j = t * (Cc / 4) + c4; }
        else { src = q; j = (t - Bb * NTOK) * (Cc / 4) + c4; }
        dst = g_tok + (size_t)idx * 4;
    } else if (idx < PREP_TOK + PREP_W1) {
        j = idx - PREP_TOK;
        src = Win;
        dst = g_Wt + (size_t)j * 4;
    } else {
        j = idx - PREP_TOK - PREP_W1;
        src = Wout;
        dst = g_Wot + (size_t)j * 4;
    }
    float4 val = ((const float4*)src)[j];
    ((__half2*)dst)[0] = __floats2half2_rn(val.x, val.y);
    ((__half2*)dst)[1] = __floats2half2_rn(val.z, val.w);
}

// ---------------- 2) f16 mma.sync GEMM (NT), 3-stage + ldmatrix -------------
constexpr int RSH    = 72;
constexpr int TILEB  = 128 * RSH * 2;
constexpr int NSTAGE = 3;
constexpr int SMEM_GEMM = 2 * NSTAGE * TILEB;

__global__ __launch_bounds__(256, 2) void k_gemm_mma(const float* __restrict__ bias,
                                                     float* __restrict__ out,
                                                     int M, int Nn, int mode) {
    extern __shared__ char smc[];
    uint32_t sb = smem_u32(smc);
    const __half* A  = (mode == 0) ? g_tok : g_ctx;
    const __half* Bw = (mode == 0) ? g_Wt  : g_Wot;
    int tid = threadIdx.x, wid = tid >> 5, lane = tid & 31;
    int grp = lane >> 2, tig = lane & 3;
    int wm = wid & 3, wn = wid >> 2;
    int mb = blockIdx.y, nb = blockIdx.x;

    int m8 = lane >> 3, r8 = lane & 7;
    uint32_t aoff = (uint32_t)((wm * 32 + (m8 & 1) * 8 + r8) * (RSH * 2) + (m8 >> 1) * 16);
    uint32_t boff = (uint32_t)((wn * 64 + (m8 >> 1) * 8 + r8) * (RSH * 2) + (m8 & 1) * 16);

    float acc[2][8][4];
#pragma unroll
    for (int i = 0; i < 2; i++)
#pragma unroll
        for (int j = 0; j < 8; j++)
#pragma unroll
            for (int k = 0; k < 4; k++) acc[i][j][k] = 0.f;

    auto copy_tile = [&](int kc, int buf) {
        uint32_t sa  = sb + buf * TILEB;
        uint32_t sbm = sb + NSTAGE * TILEB + buf * TILEB;
#pragma unroll
        for (int i = 0; i < 4; i++) {
            int idx = tid * 4 + i;
            int r = idx >> 3, c8 = idx & 7;
            int gm = mb * 128 + r;
            if (gm >= M) gm = M - 1;
            cp16(sa + r * (RSH * 2) + c8 * 16, A + (size_t)gm * Cc + kc + c8 * 8);
            int gn = nb * 128 + r;
            cp16(sbm + r * (RSH * 2) + c8 * 16, Bw + (size_t)gn * Cc + kc + c8 * 8);
        }
        asm volatile("cp.async.commit_group;" ::: "memory");
    };

    const int NCH = Cc / 64;
    copy_tile(0, 0);
    copy_tile(64, 1);

    int buf = 0;
    for (int ci = 0; ci < NCH; ci++) {
        if (ci < NCH - 1)
            asm volatile("cp.async.wait_group 1;" ::: "memory");
        else
            asm volatile("cp.async.wait_group 0;" ::: "memory");
        __syncthreads();
        if (ci + 2 < NCH) {
            int nbuf = buf + 2; if (nbuf >= NSTAGE) nbuf -= NSTAGE;
            copy_tile((ci + 2) * 64, nbuf);
        }

        uint32_t sa  = sb + buf * TILEB + aoff;
        uint32_t sbm = sb + NSTAGE * TILEB + buf * TILEB + boff;
#pragma unroll
        for (int ks = 0; ks < 4; ks++) {
            uint32_t a[2][4];
            ldsm_x4(a[0], sa + ks * 32);
            ldsm_x4(a[1], sa + ks * 32 + 16 * (RSH * 2));
            uint32_t bf[4][4];
#pragma unroll
            for (int p = 0; p < 4; p++)
                ldsm_x4(bf[p], sbm + ks * 32 + p * (16 * (RSH * 2)));
#pragma unroll
            for (int p = 0; p < 4; p++)
#pragma unroll
                for (int j = 0; j < 2; j++) {
                    int nt = p * 2 + j;
                    mma_f16(acc[0][nt], a[0], bf[p][2 * j], bf[p][2 * j + 1]);
                    mma_f16(acc[1][nt], a[1], bf[p][2 * j], bf[p][2 * j + 1]);
                }
        }
        buf++; if (buf >= NSTAGE) buf = 0;
    }

#pragma unroll
    for (int mt = 0; mt < 2; mt++) {
        int m0 = mb * 128 + wm * 32 + mt * 16 + grp;
#pragma unroll
        for (int nt = 0; nt < 8; nt++) {
            int n0 = nb * 128 + wn * 64 + nt * 8 + tig * 2;
#pragma unroll
            for (int h = 0; h < 2; h++) {
                int m = m0 + h * 8;
                if (m >= M) continue;
                float v0 = acc[mt][nt][h * 2 + 0];
                float v1 = acc[mt][nt][h * 2 + 1];
                if (mode == 0) {
                    int b, p;
                    if (m < Bb * NTOK) { b = m >> 12; p = m & (NTOK - 1); }
                    else { int t = m - Bb * NTOK; b = t >> 6; p = NTOK + (t & (NQ - 1)); }
                    int which = n0 / Cc;
                    int hd = (n0 % Cc) / DH;
                    int dd = n0 % DH;
                    __half* dst = (which == 0) ? g_Q : (which == 1) ? g_K : g_V;
                    *(__half2*)(dst + (((size_t)(b * NH + hd)) * PROW + p) * DH + dd) =
                        __floats2half2_rn(v0, v1);
                } else {
                    *(float2*)(out + (size_t)m * Nn + n0) =
                        make_float2(v0 + bias[n0], v1 + bias[n0 + 1]);
                }
            }
        }
    }
}

// ---------------- 3) fused attention: 1-pass Ob combine ---------------------
constexpr int PADL   = 288;
constexpr int KQ_STR = 72;
constexpr int O_STR  = 68;
constexpr int H_V    = PADL * KQ_STR;             // 20736
constexpr int H_Q    = 2 * PADL * KQ_STR;         // 41472
constexpr int H_END  = H_Q + 4 * 2 * 16 * KQ_STR; // 50688 halves
constexpr int F_OB   = (H_END * 2) / 4;           // 4 buffers of 64*O_STR
constexpr int F_RMAX = F_OB + 4 * 64 * O_STR;
constexpr int F_RSUM = F_RMAX + 256;
constexpr int F_MSK  = F_RSUM + 256;
constexpr int SMEM_ATT = (F_MSK + PADL) * 4;      // ~175 KB

// 0.125 * log2(e)
#define SCL2 0.18033688011112042f

__global__ __launch_bounds__(512, 1) void k_attn_fused(const int* __restrict__ q_mask) {
    extern __shared__ char smc[];
    __half* Ks = (__half*)smc;
    __half* Vs = (__half*)smc + H_V;
    float* smf = (float*)smc;
    float* Obb = smf + F_OB;
    float* rmax = smf + F_RMAX;
    float* rsum = smf + F_RSUM;
    float* msk  = smf + F_MSK;
    uint32_t sbase = smem_u32(smc);

    int z  = blockIdx.x;
    int i  = z / NH;
    int hd = z % NH;
    int bp = i / R_;
    int w  = i % R_;
    int bq = i % Bb;
    int wy = w / NWX, wx = w % NWX;

    const __half* Kpix = g_K + ((size_t)(bp * NH + hd)) * PROW * DH;
    const __half* Kq   = g_K + ((size_t)(bq * NH + hd)) * PROW * DH + (size_t)NTOK * DH;
    const __half* Vpix = g_V + ((size_t)(bp * NH + hd)) * PROW * DH;
    const __half* Vq   = g_V + ((size_t)(bq * NH + hd)) * PROW * DH + (size_t)NTOK * DH;
    const __half* Qpix = g_Q + ((size_t)(bp * NH + hd)) * PROW * DH;
    const __half* Qq   = g_Q + ((size_t)(bq * NH + hd)) * PROW * DH + (size_t)NTOK * DH;

    int tid = threadIdx.x, wid = tid >> 5, lane = tid & 31;
    int grp = lane >> 2, tig = lane & 3;
    int wm = wid & 3, wn = wid >> 2;
    int gth = (wid >> 2) * 32 + lane;
    int lr0 = wm * 16 + grp, lr1 = lr0 + 8;
    int m8 = lane >> 3, r8 = lane & 7;
    int barid = wm + 1;
    const int NT = (wm == 0) ? 5 : 4;
    float* Ob = Obb + wn * (64 * O_STR);   // own buffer per key-slice

    int qgrp = H_Q + wm * (2 * 16 * KQ_STR);
    uint32_t q_off = sbase + (uint32_t)(qgrp * 2) +
                     (uint32_t)(((m8 & 1) * 8 + r8) * 144 + (m8 >> 1) * 16);
    uint32_t k_off = sbase +
                     (uint32_t)((wn * 72 + (m8 >> 1) * 8 + r8) * 144 + (m8 & 1) * 16);
    uint32_t k2_off = sbase +
                      (uint32_t)((wn * 72 + 64 + (lane & 7)) * 144 + ((lane >> 3) & 1) * 16);
    uint32_t v_off = sbase + (uint32_t)(H_V * 2) +
                     (uint32_t)(((m8 & 1) * 8 + r8) * 144 + (m8 >> 1) * 16);
    uint32_t vt_off = sbase + (uint32_t)(H_V * 2) +
                      (uint32_t)((wn * 72 + 64 + r8) * 144 + m8 * 16);

    auto prefetch_q = [&](int qt, int buf) {
        int r = gth >> 3, c = gth & 7;
        int gr = qt * 64 + wm * 16 + r;
        const __half* src = Qpix;
        int sz = 0;
        if (gr < NWIN) {
            int py = wy * WSZ + gr / WSZ, px = wx * WSZ + gr % WSZ;
            if (py < HH && px < WW) { src = Qpix + (size_t)(py * WW + px) * DH + c * 8; sz = 16; }
        } else if (gr < LL) {
            src = Qq + (size_t)(gr - NWIN) * DH + c * 8; sz = 16;
        }
        uint32_t dst = sbase + (uint32_t)((qgrp + buf * (16 * KQ_STR)) * 2) + r * 144 + c * 16;
        cp16z(dst, src, sz);
        asm volatile("cp.async.commit_group;" ::: "memory");
    };

    prefetch_q(0, 0);

    for (int j = tid; j < PADL; j += 512) {
        float m = 0.f;
        if (j >= NWIN)
            m = (j < LL && q_mask[bq * NQ + j - NWIN] != 0) ? 0.f : -1e30f;
        msk[j] = m;
    }
    for (int idx = tid; idx < PADL * 8; idx += 512) {
        int r = idx >> 3, c = idx & 7;
        uint4 kv = make_uint4(0, 0, 0, 0), vv = make_uint4(0, 0, 0, 0);
        if (r < NWIN) {
            int py = wy * WSZ + r / WSZ, px = wx * WSZ + r % WSZ;
            if (py < HH && px < WW) {
                kv = ((const uint4*)(Kpix + (size_t)(py * WW + px) * DH))[c];
                vv = ((const uint4*)(Vpix + (size_t)(py * WW + px) * DH))[c];
            }
        } else if (r < LL) {
            kv = ((const uint4*)(Kq + (size_t)(r - NWIN) * DH))[c];
            vv = ((const uint4*)(Vq + (size_t)(r - NWIN) * DH))[c];
        }
        *(uint4*)(Ks + r * KQ_STR + c * 8) = kv;
        *(uint4*)(Vs + r * KQ_STR + c * 8) = vv;
    }
    __syncthreads();

    for (int qt = 0; qt < NT; qt++) {
        uint32_t qb = q_off + (uint32_t)((qt & 1) * (16 * KQ_STR * 2));
        asm volatile("cp.async.wait_group 0;" ::: "memory");
        bar_grp(barid);

        // ---- S = Q @ K^T : 9 n-tiles (4 x4 pairs + 1 x2 tail) ----
        float sf[9][4];
#pragma unroll
        for (int t = 0; t < 9; t++)
#pragma unroll
            for (int k = 0; k < 4; k++) sf[t][k] = 0.f;
#pragma unroll
        for (int ks = 0; ks < 4; ks++) {
            uint32_t a[4];
            ldsm_x4(a, qb + ks * 32);
#pragma unroll
            for (int tp = 0; tp < 4; tp++) {
                uint32_t bb[4];
                ldsm_x4(bb, k_off + tp * (16 * 144) + ks * 32);
                mma_f16(sf[2 * tp],     a, bb[0], bb[1]);
                mma_f16(sf[2 * tp + 1], a, bb[2], bb[3]);
            }
            uint32_t t2[2];
            ldsm_x2(t2, k2_off + ks * 32);
            mma_f16(sf[8], a, t2[0], t2[1]);
        }

        // ---- scale (log2 domain) + mask + rowmax ----
        float mx0 = -3e38f, mx1 = -3e38f;
#pragma unroll
        for (int t = 0; t < 9; t++) {
            int jb = wn * 72 + t * 8 + 2 * tig;
            float m0 = msk[jb], m1 = msk[jb + 1];
            sf[t][0] = sf[t][0] * SCL2 + m0;
            sf[t][1] = sf[t][1] * SCL2 + m1;
            sf[t][2] = sf[t][2] * SCL2 + m0;
            sf[t][3] = sf[t][3] * SCL2 + m1;
            mx0 = fmaxf(mx0, fmaxf(sf[t][0], sf[t][1]));
            mx1 = fmaxf(mx1, fmaxf(sf[t][2], sf[t][3]));
        }
        mx0 = fmaxf(mx0, __shfl_xor_sync(~0u, mx0, 1));
        mx0 = fmaxf(mx0, __shfl_xor_sync(~0u, mx0, 2));
        mx1 = fmaxf(mx1, __shfl_xor_sync(~0u, mx1, 1));
        mx1 = fmaxf(mx1, __shfl_xor_sync(~0u, mx1, 2));
        if (tig == 0) {
            rmax[lr0 * 4 + wn] = mx0;
            rmax[lr1 * 4 + wn] = mx1;
        }
        bar_grp(barid);
        float4 r40 = *(float4*)(rmax + lr0 * 4);
        float4 r41 = *(float4*)(rmax + lr1 * 4);
        float M0 = fmaxf(fmaxf(r40.x, r40.y), fmaxf(r40.z, r40.w));
        float M1 = fmaxf(fmaxf(r41.x, r41.y), fmaxf(r41.z, r41.w));

        if (qt + 1 < NT) prefetch_q(qt + 1, (qt + 1) & 1);

        // ---- P = 2^(s - M) via f16x2 ex2; row sums from exact P ----
        float s0 = 0.f, s1 = 0.f;
        uint32_t pk[9][2];
#pragma unroll
        for (int t = 0; t < 9; t++) {
            uint32_t p0 = ex2_h2(sf[t][0] - M0, sf[t][1] - M0);
            uint32_t p1 = ex2_h2(sf[t][2] - M1, sf[t][3] - M1);
            pk[t][0] = p0;
            pk[t][1] = p1;
            float2 f0 = __half22float2(*(__half2*)&p0);
            float2 f1 = __half22float2(*(__half2*)&p1);
            s0 += f0.x + f0.y;
            s1 += f1.x + f1.y;
        }
        s0 += __shfl_xor_sync(~0u, s0, 1);
        s0 += __shfl_xor_sync(~0u, s0, 2);
        s1 += __shfl_xor_sync(~0u, s1, 1);
        s1 += __shfl_xor_sync(~0u, s1, 2);
        if (tig == 0) {
            rsum[lr0 * 4 + wn] = s0;
            rsum[lr1 * 4 + wn] = s1;
        }

        // ---- O_partial = P @ V : 4 k16 steps + 1 k8 tail ----
        float of[8][4];
#pragma unroll
        for (int nt = 0; nt < 8; nt++)
#pragma unroll
            for (int k = 0; k < 4; k++) of[nt][k] = 0.f;
#pragma unroll
        for (int kt = 0; kt < 4; kt++) {
            uint32_t a[4];
            a[0] = pk[2 * kt][0];
            a[1] = pk[2 * kt][1];
            a[2] = pk[2 * kt + 1][0];
            a[3] = pk[2 * kt + 1][1];
            uint32_t vb = v_off + (uint32_t)((wn * 72 + kt * 16) * 144);
#pragma unroll
            for (int v = 0; v < 4; v++) {
                uint32_t vf[4];
                ldsm_x4t(vf, vb + v * 32);
                mma_f16(of[2 * v],     a, vf[0], vf[1]);
                mma_f16(of[2 * v + 1], a, vf[2], vf[3]);
            }
        }
        {   // k8 tail: keys 64-71 of slice
            uint32_t vfa[4], vfb[4];
            ldsm_x4t(vfa, vt_off);
            ldsm_x4t(vfb, vt_off + 64);
#pragma unroll
            for (int v = 0; v < 4; v++) {
                mma_f16_k8(of[v],     pk[8][0], pk[8][1], vfa[v]);
                mma_f16_k8(of[v + 4], pk[8][0], pk[8][1], vfb[v]);
            }
        }

        // ---- 1-pass combine: every warp stores to its own Ob buffer ----
#pragma unroll
        for (int nt = 0; nt < 8; nt++) {
            int c = nt * 8 + 2 * tig;
            *(float2*)(Ob + lr0 * O_STR + c) = make_float2(of[nt][0], of[nt][1]);
            *(float2*)(Ob + lr1 * O_STR + c) = make_float2(of[nt][2], of[nt][3]);
        }
        bar_grp(barid);

        // ---- final merge of 4 buffers + normalize + scatter ----
        {
            int r = wm * 16 + (gth >> 3);
            int c0 = (gth & 7) * 8;
            int grow = qt * 64 + r;
            if (grow < LL) {
                float4 s4 = *(float4*)(rsum + r * 4);
                float inv = 1.f / (s4.x + s4.y + s4.z + s4.w);
                float a0 = 0, a1 = 0, a2 = 0, a3 = 0, b0 = 0, b1 = 0, b2 = 0, b3 = 0;
#pragma unroll
                for (int s = 0; s < 4; s++) {
                    const float* Os = Obb + s * (64 * O_STR) + r * O_STR + c0;
                    float4 xx = *(const float4*)Os;
                    float4 yy = *(const float4*)(Os + 4);
                    a0 += xx.x; a1 += xx.y; a2 += xx.z; a3 += xx.w;
                    b0 += yy.x; b1 += yy.y; b2 += yy.z; b3 += yy.w;
                }
                __half2 h0 = __floats2half2_rn(a0 * inv, a1 * inv);
                __half2 h1 = __floats2half2_rn(a2 * inv, a3 * inv);
                __half2 h2 = __floats2half2_rn(b0 * inv, b1 * inv);
                __half2 h3 = __floats2half2_rn(b2 * inv, b3 * inv);
                __half2* dst = nullptr;
                if (grow < NWIN) {
                    int py = wy * WSZ + grow / WSZ, px = wx * WSZ + grow % WSZ;
                    if (py < HH && px < WW)
                        dst = (__half2*)(g_ctx + ((size_t)bp * NTOK + py * WW + px) * Cc
                                         + hd * DH + c0);
                } else {
                    dst = (__half2*)(g_Oq + ((size_t)i * NQ + (grow - NWIN)) * Cc
                                     + hd * DH + c0);
                }
                if (dst) { dst[0] = h0; dst[1] = h1; dst[2] = h2; dst[3] = h3; }
            }
        }
    }
}

// ---------------- 4) ctx rows for queries: mean over windows ----------------
__global__ __launch_bounds__(256) void k_ctx_q() {
    int idx = blockIdx.x * blockDim.x + threadIdx.x;
    const int SEG = Cc / 2;
    if (idx >= Bb * NQ * SEG) return;
    int j = idx / SEG, c = idx % SEG;
    int b = j / NQ, lq = j % NQ;
    float a0 = 0.f, a1 = 0.f;
#pragma unroll
    for (int w = 0; w < R_; w++) {
        int i = w * Bb + b;
        __half2 v = ((const __half2*)(g_Oq + ((size_t)i * NQ + lq) * Cc))[c];
        float2 f = __half22float2(v);
        a0 += f.x; a1 += f.y;
    }
    const float inv = 1.f / (float)R_;
    ((__half2*)(g_ctx + (size_t)(Bb * NTOK + j) * Cc))[c] =
        __floats2half2_rn(a0 * inv, a1 * inv);
}

// ---------------- launch ----------------
extern "C" void kernel_launch(void* const* d_in, const int* in_sizes, int n_in,
                              void* d_out, int out_size) {
    const float* x     = (const float*)d_in[0];
    const float* q     = (const float*)d_in[1];
    const float* W_in  = (const float*)d_in[2];
    const float* W_out = (const float*)d_in[3];
    const float* b_out = (const float*)d_in[4];
    const int*   qmask = (const int*)d_in[5];
    float* out = (float*)d_out;

    static bool attr_set = false;
    if (!attr_set) {
        cudaFuncSetAttribute(k_gemm_mma, cudaFuncAttributeMaxDynamicSharedMemorySize,
                             SMEM_GEMM);
        cudaFuncSetAttribute(k_attn_fused, cudaFuncAttributeMaxDynamicSharedMemorySize,
                             SMEM_ATT);
        attr_set = true;
    }

    k_prep<<<(PREP_ALL + 255) / 256, 256>>>(x, q, W_in, W_out);

    dim3 g_qkv(3 * Cc / 128, CTXROWS / 128);
    k_gemm_mma<<<g_qkv, 256, SMEM_GEMM>>>(nullptr, nullptr, CTXROWS, 3 * Cc, 0);

    k_attn_fused<<<BW * NH, 512, SMEM_ATT>>>(qmask);

    k_ctx_q<<<(Bb * NQ * (Cc / 2) + 255) / 256, 256>>>();

    dim3 g_out(Cc / 128, CTXROWS / 128);
    k_gemm_mma<<<g_out, 256, SMEM_GEMM>>>(b_out, out, CTXROWS, Cc, 1);
}